// round 1
// baseline (speedup 1.0000x reference)
#include <cuda_runtime.h>
#include <cuda_bf16.h>
#include <math.h>

// Problem constants
#define B_ 2
#define S_ 2048
#define D_ 2048
#define H_ 16
#define DK_ 128

// Scratch: 6 buffers of B*S*D floats = 192MB static device memory (allowed).
static const size_t NBSD = (size_t)B_ * S_ * D_;
__device__ float g_scratch[6 * (size_t)B_ * S_ * D_];

// ---------------------------------------------------------------------------
// GEMM: C[M,N] = A[M,K] @ W[N,K]^T + bias[N]   (NT form, all row-major)
// 128x128 tile, BK=8, 256 threads, 8x8 per-thread microtile.
// ---------------------------------------------------------------------------
__global__ __launch_bounds__(256) void sgemm_nt_bias(
    const float* __restrict__ A, const float* __restrict__ W,
    const float* __restrict__ bias, float* __restrict__ C,
    int M, int N, int K)
{
    const int STR = 132;  // 128 + 4 pad: conflict-free transposed stores
    __shared__ __align__(16) float As[8 * 132];
    __shared__ __align__(16) float Ws[8 * 132];

    int tid = threadIdx.x;
    int bx = blockIdx.x, by = blockIdx.y;

    int lr = tid >> 1;            // 0..127 tile row
    int lc = (tid & 1) << 2;      // 0 or 4  (k offset)
    int tx = tid & 15;            // 0..15 -> N microtiles
    int ty = tid >> 4;            // 0..15 -> M microtiles

    const float* Ap = A + (size_t)(by * 128 + lr) * K + lc;
    const float* Wp = W + (size_t)(bx * 128 + lr) * K + lc;

    float acc[8][8];
#pragma unroll
    for (int i = 0; i < 8; i++)
#pragma unroll
        for (int j = 0; j < 8; j++) acc[i][j] = 0.f;

    for (int k0 = 0; k0 < K; k0 += 8) {
        float4 av = *(const float4*)(Ap + k0);
        float4 wv = *(const float4*)(Wp + k0);
        As[(lc + 0) * STR + lr] = av.x;
        As[(lc + 1) * STR + lr] = av.y;
        As[(lc + 2) * STR + lr] = av.z;
        As[(lc + 3) * STR + lr] = av.w;
        Ws[(lc + 0) * STR + lr] = wv.x;
        Ws[(lc + 1) * STR + lr] = wv.y;
        Ws[(lc + 2) * STR + lr] = wv.z;
        Ws[(lc + 3) * STR + lr] = wv.w;
        __syncthreads();

#pragma unroll
        for (int kk = 0; kk < 8; kk++) {
            float4 a0 = *(const float4*)&As[kk * STR + ty * 8];
            float4 a1 = *(const float4*)&As[kk * STR + ty * 8 + 4];
            float4 w0 = *(const float4*)&Ws[kk * STR + tx * 8];
            float4 w1 = *(const float4*)&Ws[kk * STR + tx * 8 + 4];
            float a[8] = {a0.x, a0.y, a0.z, a0.w, a1.x, a1.y, a1.z, a1.w};
            float w[8] = {w0.x, w0.y, w0.z, w0.w, w1.x, w1.y, w1.z, w1.w};
#pragma unroll
            for (int i = 0; i < 8; i++)
#pragma unroll
                for (int j = 0; j < 8; j++)
                    acc[i][j] += a[i] * w[j];
        }
        __syncthreads();
    }

    int row0 = by * 128 + ty * 8;
    int col0 = bx * 128 + tx * 8;
    float4 b0 = *(const float4*)(bias + col0);
    float4 b1 = *(const float4*)(bias + col0 + 4);
    float bb[8] = {b0.x, b0.y, b0.z, b0.w, b1.x, b1.y, b1.z, b1.w};
#pragma unroll
    for (int i = 0; i < 8; i++) {
        float4 o0, o1;
        o0.x = acc[i][0] + bb[0]; o0.y = acc[i][1] + bb[1];
        o0.z = acc[i][2] + bb[2]; o0.w = acc[i][3] + bb[3];
        o1.x = acc[i][4] + bb[4]; o1.y = acc[i][5] + bb[5];
        o1.z = acc[i][6] + bb[6]; o1.w = acc[i][7] + bb[7];
        *(float4*)(C + (size_t)(row0 + i) * N + col0) = o0;
        *(float4*)(C + (size_t)(row0 + i) * N + col0 + 4) = o1;
    }
}

// ---------------------------------------------------------------------------
// RoPE + relayout: [B,S,D] (d = h*128+i) -> [B,H,S,DK], rope applied to Q,K.
// One thread per (b,h,s,i<64): handles both rotated halves.
// ---------------------------------------------------------------------------
__global__ __launch_bounds__(256) void rope_relayout_kernel(
    const float* __restrict__ Qlin, const float* __restrict__ Klin,
    const float* __restrict__ Vlin,
    float* __restrict__ Qh, float* __restrict__ Kh, float* __restrict__ Vh)
{
    int idx = blockIdx.x * 256 + threadIdx.x;          // B*H*S*64 = 4194304
    if (idx >= B_ * H_ * S_ * 64) return;
    int i  = idx & 63;
    int s  = (idx >> 6) & (S_ - 1);
    int hb = idx >> 17;                                 // b*H + h, 0..31
    int h  = hb & (H_ - 1);
    int b  = hb >> 4;

    size_t lin = ((size_t)(b * S_ + s)) * D_ + h * DK_ + i;
    size_t out = ((size_t)hb * S_ + s) * DK_ + i;

    float inv = 1.0f / powf(10000.0f, (float)(2 * i) / 128.0f);
    float ang = (float)s * inv;
    float sn, cs;
    sincosf(ang, &sn, &cs);

    float q0 = Qlin[lin], q1 = Qlin[lin + 64];
    Qh[out]      = q0 * cs - q1 * sn;
    Qh[out + 64] = q1 * cs + q0 * sn;
    float k0 = Klin[lin], k1 = Klin[lin + 64];
    Kh[out]      = k0 * cs - k1 * sn;
    Kh[out + 64] = k1 * cs + k0 * sn;
    Vh[out]      = Vlin[lin];
    Vh[out + 64] = Vlin[lin + 64];
}

// ---------------------------------------------------------------------------
// Flash attention (causal, fp32). BM=BN=64, DK=128, 256 threads.
// Grid: (32 qtiles reversed, H, B). O layout [B,H,S,DK].
// ---------------------------------------------------------------------------
#define QSTR 130
#define SSTR 65
#define ATT_SMEM ((3 * 64 * QSTR + 64 * SSTR + 3 * 64) * 4)

__global__ __launch_bounds__(256) void attn_kernel(
    const float* __restrict__ Q, const float* __restrict__ K,
    const float* __restrict__ V, float* __restrict__ O)
{
    extern __shared__ float sm[];
    float* Qs   = sm;                    // 64 * 130
    float* Ks   = Qs + 64 * QSTR;        // 64 * 130
    float* Vs   = Ks + 64 * QSTR;        // 64 * 130
    float* Ss   = Vs + 64 * QSTR;        // 64 * 65
    float* mrow = Ss + 64 * SSTR;        // 64
    float* lrow = mrow + 64;             // 64
    float* arow = lrow + 64;             // 64

    int qt = (int)gridDim.x - 1 - (int)blockIdx.x;   // heavy tiles first
    int h = blockIdx.y, b = blockIdx.z;
    size_t base = ((size_t)(b * H_ + h)) * S_ * DK_;
    const float* Qb = Q + base + (size_t)qt * 64 * DK_;
    const float* Kb = K + base;
    const float* Vb = V + base;

    int tid = threadIdx.x;
    int tx = tid & 15, ty = tid >> 4;

    // Load Q tile (64 x 128)
    for (int i = tid; i < 64 * 32; i += 256) {
        int r = i >> 5, c = (i & 31) << 2;
        float4 v = *(const float4*)(Qb + r * DK_ + c);
        Qs[r * QSTR + c + 0] = v.x;
        Qs[r * QSTR + c + 1] = v.y;
        Qs[r * QSTR + c + 2] = v.z;
        Qs[r * QSTR + c + 3] = v.w;
    }
    if (tid < 64) { mrow[tid] = -1e30f; lrow[tid] = 0.f; }

    float Oacc[4][8];
#pragma unroll
    for (int i = 0; i < 4; i++)
#pragma unroll
        for (int j = 0; j < 8; j++) Oacc[i][j] = 0.f;

    const float scale = 0.088388347648318440f;   // 1/sqrt(128)
    int nkt = qt + 1;

    for (int kt = 0; kt < nkt; kt++) {
        __syncthreads();   // prev PV done (and Q visible on first iter after next sync)
        for (int i = tid; i < 64 * 32; i += 256) {
            int r = i >> 5, c = (i & 31) << 2;
            float4 kv = *(const float4*)(Kb + (size_t)(kt * 64 + r) * DK_ + c);
            float4 vv = *(const float4*)(Vb + (size_t)(kt * 64 + r) * DK_ + c);
            Ks[r * QSTR + c + 0] = kv.x; Ks[r * QSTR + c + 1] = kv.y;
            Ks[r * QSTR + c + 2] = kv.z; Ks[r * QSTR + c + 3] = kv.w;
            Vs[r * QSTR + c + 0] = vv.x; Vs[r * QSTR + c + 1] = vv.y;
            Vs[r * QSTR + c + 2] = vv.z; Vs[r * QSTR + c + 3] = vv.w;
        }
        __syncthreads();

        // Scores: S = Q @ K^T (64x64x128), 4x4 per thread, float2 k-vectorized
        float acc[4][4];
#pragma unroll
        for (int i = 0; i < 4; i++)
#pragma unroll
            for (int j = 0; j < 4; j++) acc[i][j] = 0.f;

        for (int k = 0; k < 128; k += 2) {
            float2 a[4], w[4];
#pragma unroll
            for (int i = 0; i < 4; i++)
                a[i] = *(const float2*)&Qs[(ty + 16 * i) * QSTR + k];
#pragma unroll
            for (int j = 0; j < 4; j++)
                w[j] = *(const float2*)&Ks[(tx + 16 * j) * QSTR + k];
#pragma unroll
            for (int i = 0; i < 4; i++)
#pragma unroll
                for (int j = 0; j < 4; j++)
                    acc[i][j] += a[i].x * w[j].x + a[i].y * w[j].y;
        }

        bool diag = (kt == qt);
#pragma unroll
        for (int i = 0; i < 4; i++) {
#pragma unroll
            for (int j = 0; j < 4; j++) {
                int r = ty + 16 * i, c = tx + 16 * j;
                float s = acc[i][j] * scale;
                if (diag && c > r) s = -1e30f;
                Ss[r * SSTR + c] = s;
            }
        }
        __syncthreads();

        // Online softmax: 4 threads per row
        {
            int r = tid >> 2, q4 = tid & 3;
            float rm = -1e30f;
            for (int c = q4; c < 64; c += 4) rm = fmaxf(rm, Ss[r * SSTR + c]);
            rm = fmaxf(rm, __shfl_xor_sync(0xffffffffu, rm, 1));
            rm = fmaxf(rm, __shfl_xor_sync(0xffffffffu, rm, 2));
            float mold = mrow[r];
            float mnew = fmaxf(mold, rm);
            float sum = 0.f;
            for (int c = q4; c < 64; c += 4) {
                float p = __expf(Ss[r * SSTR + c] - mnew);
                Ss[r * SSTR + c] = p;
                sum += p;
            }
            sum += __shfl_xor_sync(0xffffffffu, sum, 1);
            sum += __shfl_xor_sync(0xffffffffu, sum, 2);
            if (q4 == 0) {
                float alpha = __expf(mold - mnew);
                arow[r] = alpha;
                mrow[r] = mnew;
                lrow[r] = lrow[r] * alpha + sum;
            }
        }
        __syncthreads();

        // Rescale O and accumulate P @ V (64x128x64)
        float al[4];
#pragma unroll
        for (int i = 0; i < 4; i++) al[i] = arow[ty + 16 * i];
#pragma unroll
        for (int i = 0; i < 4; i++)
#pragma unroll
            for (int j = 0; j < 8; j++) Oacc[i][j] *= al[i];

        for (int k = 0; k < 64; k++) {
            float p[4], v[8];
#pragma unroll
            for (int i = 0; i < 4; i++) p[i] = Ss[(ty + 16 * i) * SSTR + k];
#pragma unroll
            for (int j = 0; j < 8; j++) v[j] = Vs[k * QSTR + tx + 16 * j];
#pragma unroll
            for (int i = 0; i < 4; i++)
#pragma unroll
                for (int j = 0; j < 8; j++)
                    Oacc[i][j] += p[i] * v[j];
        }
    }
    __syncthreads();

    float linv[4];
#pragma unroll
    for (int i = 0; i < 4; i++) linv[i] = 1.0f / lrow[ty + 16 * i];
    float* Ob = O + base + (size_t)qt * 64 * DK_;
#pragma unroll
    for (int i = 0; i < 4; i++)
#pragma unroll
        for (int j = 0; j < 8; j++)
            Ob[(ty + 16 * i) * DK_ + tx + 16 * j] = Oacc[i][j] * linv[i];
}

// ---------------------------------------------------------------------------
// Relayout attention output: [B,H,S,DK] -> [B,S,D]
// ---------------------------------------------------------------------------
__global__ __launch_bounds__(256) void relayout_out_kernel(
    const float* __restrict__ Oh, float* __restrict__ Olin)
{
    int idx = blockIdx.x * 256 + threadIdx.x;   // B*H*S*DK = 8388608
    if (idx >= (int)(B_ * H_ * S_ * DK_)) return;
    int i = idx & 127;
    int s = (idx >> 7) & (S_ - 1);
    int h = (idx >> 18) & (H_ - 1);
    int b = idx >> 22;
    Olin[((size_t)b * S_ + s) * D_ + h * DK_ + i] = Oh[idx];
}

// ---------------------------------------------------------------------------
extern "C" void kernel_launch(void* const* d_in, const int* in_sizes, int n_in,
                              void* d_out, int out_size)
{
    const float* x  = (const float*)d_in[0];
    // d_in[1] = mask (causal tril; handled analytically)
    const float* Wq = (const float*)d_in[2];
    const float* bq = (const float*)d_in[3];
    const float* Wk = (const float*)d_in[4];
    const float* bk = (const float*)d_in[5];
    const float* Wv = (const float*)d_in[6];
    const float* bv = (const float*)d_in[7];
    const float* Wo = (const float*)d_in[8];
    const float* bo = (const float*)d_in[9];
    float* out = (float*)d_out;

    float* base = nullptr;
    cudaGetSymbolAddress((void**)&base, g_scratch);
    float* Qlin = base;
    float* Klin = base + NBSD;
    float* Vlin = base + 2 * NBSD;
    float* Qh   = base + 3 * NBSD;
    float* Kh   = base + 4 * NBSD;
    float* Vh   = base + 5 * NBSD;
    float* Oh   = Qlin;     // lin buffers dead after rope
    float* Olin = Klin;

    const int M = B_ * S_, N = D_, K = D_;
    dim3 gg(N / 128, M / 128);   // (16, 32)

    sgemm_nt_bias<<<gg, 256>>>(x, Wq, bq, Qlin, M, N, K);
    sgemm_nt_bias<<<gg, 256>>>(x, Wk, bk, Klin, M, N, K);
    sgemm_nt_bias<<<gg, 256>>>(x, Wv, bv, Vlin, M, N, K);

    int rope_total = B_ * H_ * S_ * 64;
    rope_relayout_kernel<<<rope_total / 256, 256>>>(Qlin, Klin, Vlin, Qh, Kh, Vh);

    cudaFuncSetAttribute(attn_kernel,
                         cudaFuncAttributeMaxDynamicSharedMemorySize, ATT_SMEM);
    attn_kernel<<<dim3(S_ / 64, H_, B_), 256, ATT_SMEM>>>(Qh, Kh, Vh, Oh);

    int o_total = B_ * H_ * S_ * DK_;
    relayout_out_kernel<<<o_total / 256, 256>>>(Oh, Olin);

    sgemm_nt_bias<<<gg, 256>>>(Olin, Wo, bo, out, M, N, K);
}

// round 3
// speedup vs baseline: 2.0137x; 2.0137x over previous
#include <cuda_runtime.h>
#include <cuda_bf16.h>
#include <math.h>
#include <cstdint>

// Problem constants
#define B_ 2
#define S_ 2048
#define D_ 2048
#define H_ 16
#define DK_ 128

static const size_t NBSD = (size_t)B_ * S_ * D_;
__device__ float g_scratch[6 * (size_t)B_ * S_ * D_];
__device__ float g_xt[(size_t)B_ * S_ * D_];          // tf32-rounded x
__device__ float g_wt[4 * (size_t)D_ * D_];           // tf32-rounded Wq,Wk,Wv,Wo

// ============================================================================
// Helpers (arch-generic PTX only: cp.async + mma.sync, both sm_80+)
// ============================================================================
__device__ __forceinline__ uint32_t smem_to_u32(const void* smem_ptr) {
    uint32_t addr;
    asm("{ .reg .u64 tmp; cvta.to.shared.u64 tmp, %1; cvt.u32.u64 %0, tmp; }"
        : "=r"(addr) : "l"(smem_ptr));
    return addr;
}

__device__ __forceinline__ void cp_async16(uint32_t smem_addr, const void* gptr) {
    asm volatile("cp.async.cg.shared.global [%0], [%1], 16;"
                 :: "r"(smem_addr), "l"(gptr));
}
#define CP_ASYNC_COMMIT() asm volatile("cp.async.commit_group;" ::: "memory")
#define CP_ASYNC_WAIT(n)  asm volatile("cp.async.wait_group %0;" :: "n"(n) : "memory")

__device__ __forceinline__ void mma_tf32_16n8k8(float* d, const uint32_t* a,
                                                const uint32_t* b) {
    asm volatile(
        "mma.sync.aligned.m16n8k8.row.col.f32.tf32.tf32.f32 "
        "{%0,%1,%2,%3}, {%4,%5,%6,%7}, {%8,%9}, {%0,%1,%2,%3};"
        : "+f"(d[0]), "+f"(d[1]), "+f"(d[2]), "+f"(d[3])
        : "r"(a[0]), "r"(a[1]), "r"(a[2]), "r"(a[3]), "r"(b[0]), "r"(b[1]));
}

__device__ __forceinline__ float tf32_round(float x) {
    uint32_t u;
    asm("cvt.rna.tf32.f32 %0, %1;" : "=r"(u) : "f"(x));
    return __uint_as_float(u);
}

// ============================================================================
// tf32 rounding pre-pass (elementwise, float4)
// ============================================================================
__global__ __launch_bounds__(256) void tf32_round_kernel(
    const float* __restrict__ in, float* __restrict__ out, int n4)
{
    int i = blockIdx.x * 256 + threadIdx.x;
    if (i >= n4) return;
    float4 v = ((const float4*)in)[i];
    v.x = tf32_round(v.x); v.y = tf32_round(v.y);
    v.z = tf32_round(v.z); v.w = tf32_round(v.w);
    ((float4*)out)[i] = v;
}

// ============================================================================
// mma.sync tf32 GEMM: C[M,N] = A[M,K] @ W[N,K]^T + bias[N]
// BM=BN=128, BK=32, 8 warps (4 M x 2 N), warp tile 32x64, m16n8k8 atoms.
// 3-stage cp.async pipeline. Smem stride 36 floats (conflict-free frags).
// ============================================================================
#define GSTR 36
#define GEMM_STAGE_FLOATS (2 * 128 * GSTR)          // A tile + B tile
#define GEMM_STAGE_BYTES  (GEMM_STAGE_FLOATS * 4)   // 36864
#define GEMM_SMEM (3 * GEMM_STAGE_BYTES + 16)

__device__ __forceinline__ void gemm_load_stage(
    const float* __restrict__ A, const float* __restrict__ W,
    int row0, int col0, int K, int kc, uint32_t sbase, int tid)
{
#pragma unroll
    for (int i = 0; i < 8; i++) {
        int q = i * 256 + tid;           // 0..2047
        int isB = (i >= 4);
        int r = (q & 1023) >> 3;         // tile row 0..127
        int c = q & 7;                   // 16B chunk 0..7
        const float* g = isB
            ? (W + (size_t)(col0 + r) * K + kc * 32 + c * 4)
            : (A + (size_t)(row0 + r) * K + kc * 32 + c * 4);
        uint32_t soff = (uint32_t)(isB ? (128 * GSTR * 4) : 0) +
                        (uint32_t)(r * GSTR * 4 + c * 16);
        cp_async16(sbase + soff, g);
    }
    CP_ASYNC_COMMIT();
}

__global__ __launch_bounds__(256) void tf32_gemm_nt_bias(
    const float* __restrict__ A, const float* __restrict__ W,
    const float* __restrict__ bias, float* __restrict__ C,
    int M, int N, int K)
{
    extern __shared__ __align__(16) float dsm[];

    int tid = threadIdx.x;
    int wid = tid >> 5;
    int lane = tid & 31;
    int gr = lane >> 2;      // group row 0..7
    int gc = lane & 3;       // group col 0..3
    int wm = wid & 3;        // warp m index 0..3
    int wn = wid >> 2;       // warp n index 0..1

    int bx = blockIdx.x, by = blockIdx.y;
    int row0 = by * 128, col0 = bx * 128;

    uint32_t sb_u32 = smem_to_u32(dsm);

    float acc[2][8][4];
#pragma unroll
    for (int i = 0; i < 2; i++)
#pragma unroll
        for (int j = 0; j < 8; j++)
#pragma unroll
            for (int k = 0; k < 4; k++) acc[i][j][k] = 0.f;

    const int NC = K >> 5;   // 64 stages of K=32

    gemm_load_stage(A, W, row0, col0, K, 0, sb_u32 + 0 * GEMM_STAGE_BYTES, tid);
    gemm_load_stage(A, W, row0, col0, K, 1, sb_u32 + 1 * GEMM_STAGE_BYTES, tid);

    for (int j = 0; j < NC; j++) {
        if (j + 2 < NC) { CP_ASYNC_WAIT(1); } else { CP_ASYNC_WAIT(0); }
        __syncthreads();

        int s = j % 3;
        int jn = j + 2;
        if (jn < NC) {
            gemm_load_stage(A, W, row0, col0, K, jn,
                            sb_u32 + (jn % 3) * GEMM_STAGE_BYTES, tid);
        }

        const float* As = dsm + (size_t)s * GEMM_STAGE_FLOATS;
        const float* Bs = As + 128 * GSTR;

#pragma unroll
        for (int kst = 0; kst < 4; kst++) {
            int k0 = kst * 8;
            uint32_t af[2][4];
#pragma unroll
            for (int ma = 0; ma < 2; ma++) {
                int r = wm * 32 + ma * 16 + gr;
                af[ma][0] = __float_as_uint(As[r * GSTR + k0 + gc]);
                af[ma][1] = __float_as_uint(As[(r + 8) * GSTR + k0 + gc]);
                af[ma][2] = __float_as_uint(As[r * GSTR + k0 + gc + 4]);
                af[ma][3] = __float_as_uint(As[(r + 8) * GSTR + k0 + gc + 4]);
            }
            uint32_t bf[8][2];
#pragma unroll
            for (int na = 0; na < 8; na++) {
                int n = wn * 64 + na * 8 + gr;
                bf[na][0] = __float_as_uint(Bs[n * GSTR + k0 + gc]);
                bf[na][1] = __float_as_uint(Bs[n * GSTR + k0 + gc + 4]);
            }
#pragma unroll
            for (int ma = 0; ma < 2; ma++)
#pragma unroll
                for (int na = 0; na < 8; na++)
                    mma_tf32_16n8k8(acc[ma][na], af[ma], bf[na]);
        }
        __syncthreads();
    }

    // Epilogue: C layout per atom: c0,c1 -> (gr, 2gc..2gc+1); c2,c3 -> (gr+8, ..)
#pragma unroll
    for (int ma = 0; ma < 2; ma++) {
        int row = row0 + wm * 32 + ma * 16 + gr;
#pragma unroll
        for (int na = 0; na < 8; na++) {
            int col = col0 + wn * 64 + na * 8 + gc * 2;
            float2 bb = *(const float2*)(bias + col);
            float2 o0, o1;
            o0.x = acc[ma][na][0] + bb.x;
            o0.y = acc[ma][na][1] + bb.y;
            o1.x = acc[ma][na][2] + bb.x;
            o1.y = acc[ma][na][3] + bb.y;
            *(float2*)(C + (size_t)row * N + col) = o0;
            *(float2*)(C + (size_t)(row + 8) * N + col) = o1;
        }
    }
}

// ---------------------------------------------------------------------------
// RoPE + relayout: [B,S,D] (d = h*128+i) -> [B,H,S,DK], rope applied to Q,K.
// ---------------------------------------------------------------------------
__global__ __launch_bounds__(256) void rope_relayout_kernel(
    const float* __restrict__ Qlin, const float* __restrict__ Klin,
    const float* __restrict__ Vlin,
    float* __restrict__ Qh, float* __restrict__ Kh, float* __restrict__ Vh)
{
    int idx = blockIdx.x * 256 + threadIdx.x;          // B*H*S*64
    if (idx >= B_ * H_ * S_ * 64) return;
    int i  = idx & 63;
    int s  = (idx >> 6) & (S_ - 1);
    int hb = idx >> 17;
    int h  = hb & (H_ - 1);
    int b  = hb >> 4;

    size_t lin = ((size_t)(b * S_ + s)) * D_ + h * DK_ + i;
    size_t out = ((size_t)hb * S_ + s) * DK_ + i;

    float inv = 1.0f / powf(10000.0f, (float)(2 * i) / 128.0f);
    float ang = (float)s * inv;
    float sn, cs;
    sincosf(ang, &sn, &cs);

    float q0 = Qlin[lin], q1 = Qlin[lin + 64];
    Qh[out]      = q0 * cs - q1 * sn;
    Qh[out + 64] = q1 * cs + q0 * sn;
    float k0 = Klin[lin], k1 = Klin[lin + 64];
    Kh[out]      = k0 * cs - k1 * sn;
    Kh[out + 64] = k1 * cs + k0 * sn;
    Vh[out]      = Vlin[lin];
    Vh[out + 64] = Vlin[lin + 64];
}

// ---------------------------------------------------------------------------
// Flash attention (causal, fp32). BM=BN=64, DK=128, 256 threads.
// ---------------------------------------------------------------------------
#define QSTR 130
#define SSTR 65
#define ATT_SMEM ((3 * 64 * QSTR + 64 * SSTR + 3 * 64) * 4)

__global__ __launch_bounds__(256) void attn_kernel(
    const float* __restrict__ Q, const float* __restrict__ K,
    const float* __restrict__ V, float* __restrict__ O)
{
    extern __shared__ float sm[];
    float* Qs   = sm;
    float* Ks   = Qs + 64 * QSTR;
    float* Vs   = Ks + 64 * QSTR;
    float* Ss   = Vs + 64 * QSTR;
    float* mrow = Ss + 64 * SSTR;
    float* lrow = mrow + 64;
    float* arow = lrow + 64;

    int qt = (int)gridDim.x - 1 - (int)blockIdx.x;
    int h = blockIdx.y, b = blockIdx.z;
    size_t base = ((size_t)(b * H_ + h)) * S_ * DK_;
    const float* Qb = Q + base + (size_t)qt * 64 * DK_;
    const float* Kb = K + base;
    const float* Vb = V + base;

    int tid = threadIdx.x;
    int tx = tid & 15, ty = tid >> 4;

    for (int i = tid; i < 64 * 32; i += 256) {
        int r = i >> 5, c = (i & 31) << 2;
        float4 v = *(const float4*)(Qb + r * DK_ + c);
        Qs[r * QSTR + c + 0] = v.x;
        Qs[r * QSTR + c + 1] = v.y;
        Qs[r * QSTR + c + 2] = v.z;
        Qs[r * QSTR + c + 3] = v.w;
    }
    if (tid < 64) { mrow[tid] = -1e30f; lrow[tid] = 0.f; }

    float Oacc[4][8];
#pragma unroll
    for (int i = 0; i < 4; i++)
#pragma unroll
        for (int j = 0; j < 8; j++) Oacc[i][j] = 0.f;

    const float scale = 0.088388347648318440f;
    int nkt = qt + 1;

    for (int kt = 0; kt < nkt; kt++) {
        __syncthreads();
        for (int i = tid; i < 64 * 32; i += 256) {
            int r = i >> 5, c = (i & 31) << 2;
            float4 kv = *(const float4*)(Kb + (size_t)(kt * 64 + r) * DK_ + c);
            float4 vv = *(const float4*)(Vb + (size_t)(kt * 64 + r) * DK_ + c);
            Ks[r * QSTR + c + 0] = kv.x; Ks[r * QSTR + c + 1] = kv.y;
            Ks[r * QSTR + c + 2] = kv.z; Ks[r * QSTR + c + 3] = kv.w;
            Vs[r * QSTR + c + 0] = vv.x; Vs[r * QSTR + c + 1] = vv.y;
            Vs[r * QSTR + c + 2] = vv.z; Vs[r * QSTR + c + 3] = vv.w;
        }
        __syncthreads();

        float acc[4][4];
#pragma unroll
        for (int i = 0; i < 4; i++)
#pragma unroll
            for (int j = 0; j < 4; j++) acc[i][j] = 0.f;

        for (int k = 0; k < 128; k += 2) {
            float2 a[4], w[4];
#pragma unroll
            for (int i = 0; i < 4; i++)
                a[i] = *(const float2*)&Qs[(ty + 16 * i) * QSTR + k];
#pragma unroll
            for (int j = 0; j < 4; j++)
                w[j] = *(const float2*)&Ks[(tx + 16 * j) * QSTR + k];
#pragma unroll
            for (int i = 0; i < 4; i++)
#pragma unroll
                for (int j = 0; j < 4; j++)
                    acc[i][j] += a[i].x * w[j].x + a[i].y * w[j].y;
        }

        bool diag = (kt == qt);
#pragma unroll
        for (int i = 0; i < 4; i++) {
#pragma unroll
            for (int j = 0; j < 4; j++) {
                int r = ty + 16 * i, c = tx + 16 * j;
                float s = acc[i][j] * scale;
                if (diag && c > r) s = -1e30f;
                Ss[r * SSTR + c] = s;
            }
        }
        __syncthreads();

        {
            int r = tid >> 2, q4 = tid & 3;
            float rm = -1e30f;
            for (int c = q4; c < 64; c += 4) rm = fmaxf(rm, Ss[r * SSTR + c]);
            rm = fmaxf(rm, __shfl_xor_sync(0xffffffffu, rm, 1));
            rm = fmaxf(rm, __shfl_xor_sync(0xffffffffu, rm, 2));
            float mold = mrow[r];
            float mnew = fmaxf(mold, rm);
            float sum = 0.f;
            for (int c = q4; c < 64; c += 4) {
                float p = __expf(Ss[r * SSTR + c] - mnew);
                Ss[r * SSTR + c] = p;
                sum += p;
            }
            sum += __shfl_xor_sync(0xffffffffu, sum, 1);
            sum += __shfl_xor_sync(0xffffffffu, sum, 2);
            if (q4 == 0) {
                float alpha = __expf(mold - mnew);
                arow[r] = alpha;
                mrow[r] = mnew;
                lrow[r] = lrow[r] * alpha + sum;
            }
        }
        __syncthreads();

        float al[4];
#pragma unroll
        for (int i = 0; i < 4; i++) al[i] = arow[ty + 16 * i];
#pragma unroll
        for (int i = 0; i < 4; i++)
#pragma unroll
            for (int j = 0; j < 8; j++) Oacc[i][j] *= al[i];

        for (int k = 0; k < 64; k++) {
            float p[4], v[8];
#pragma unroll
            for (int i = 0; i < 4; i++) p[i] = Ss[(ty + 16 * i) * SSTR + k];
#pragma unroll
            for (int j = 0; j < 8; j++) v[j] = Vs[k * QSTR + tx + 16 * j];
#pragma unroll
            for (int i = 0; i < 4; i++)
#pragma unroll
                for (int j = 0; j < 8; j++)
                    Oacc[i][j] += p[i] * v[j];
        }
    }
    __syncthreads();

    float linv[4];
#pragma unroll
    for (int i = 0; i < 4; i++) linv[i] = 1.0f / lrow[ty + 16 * i];
    float* Ob = O + base + (size_t)qt * 64 * DK_;
#pragma unroll
    for (int i = 0; i < 4; i++)
#pragma unroll
        for (int j = 0; j < 8; j++)
            Ob[(ty + 16 * i) * DK_ + tx + 16 * j] = Oacc[i][j] * linv[i];
}

// ---------------------------------------------------------------------------
// Relayout attention output: [B,H,S,DK] -> [B,S,D], tf32-rounded (feeds GEMM A)
// ---------------------------------------------------------------------------
__global__ __launch_bounds__(256) void relayout_out_kernel(
    const float* __restrict__ Oh, float* __restrict__ Olin)
{
    int idx = blockIdx.x * 256 + threadIdx.x;
    if (idx >= (int)(B_ * H_ * S_ * DK_)) return;
    int i = idx & 127;
    int s = (idx >> 7) & (S_ - 1);
    int h = (idx >> 18) & (H_ - 1);
    int b = idx >> 22;
    Olin[((size_t)b * S_ + s) * D_ + h * DK_ + i] = tf32_round(Oh[idx]);
}

// ---------------------------------------------------------------------------
extern "C" void kernel_launch(void* const* d_in, const int* in_sizes, int n_in,
                              void* d_out, int out_size)
{
    const float* x  = (const float*)d_in[0];
    const float* Wq = (const float*)d_in[2];
    const float* bq = (const float*)d_in[3];
    const float* Wk = (const float*)d_in[4];
    const float* bk = (const float*)d_in[5];
    const float* Wv = (const float*)d_in[6];
    const float* bv = (const float*)d_in[7];
    const float* Wo = (const float*)d_in[8];
    const float* bo = (const float*)d_in[9];
    float* out = (float*)d_out;

    float* base = nullptr;
    cudaGetSymbolAddress((void**)&base, g_scratch);
    float* xt = nullptr;
    cudaGetSymbolAddress((void**)&xt, g_xt);
    float* wt = nullptr;
    cudaGetSymbolAddress((void**)&wt, g_wt);

    float* Qlin = base;
    float* Klin = base + NBSD;
    float* Vlin = base + 2 * NBSD;
    float* Qh   = base + 3 * NBSD;
    float* Kh   = base + 4 * NBSD;
    float* Vh   = base + 5 * NBSD;
    float* Oh   = Qlin;
    float* Olin = Klin;
    float* Wqt = wt;
    float* Wkt = wt + (size_t)D_ * D_;
    float* Wvt = wt + 2 * (size_t)D_ * D_;
    float* Wot = wt + 3 * (size_t)D_ * D_;

    const int M = B_ * S_, N = D_, K = D_;

    // tf32 rounding pre-pass
    {
        int nx4 = (int)(NBSD / 4);
        int nw4 = (int)(((size_t)D_ * D_) / 4);
        tf32_round_kernel<<<(nx4 + 255) / 256, 256>>>(x, xt, nx4);
        tf32_round_kernel<<<(nw4 + 255) / 256, 256>>>(Wq, Wqt, nw4);
        tf32_round_kernel<<<(nw4 + 255) / 256, 256>>>(Wk, Wkt, nw4);
        tf32_round_kernel<<<(nw4 + 255) / 256, 256>>>(Wv, Wvt, nw4);
        tf32_round_kernel<<<(nw4 + 255) / 256, 256>>>(Wo, Wot, nw4);
    }

    cudaFuncSetAttribute(tf32_gemm_nt_bias,
                         cudaFuncAttributeMaxDynamicSharedMemorySize, GEMM_SMEM);
    dim3 gg(N / 128, M / 128);   // (16, 32)

    tf32_gemm_nt_bias<<<gg, 256, GEMM_SMEM>>>(xt, Wqt, bq, Qlin, M, N, K);
    tf32_gemm_nt_bias<<<gg, 256, GEMM_SMEM>>>(xt, Wkt, bk, Klin, M, N, K);
    tf32_gemm_nt_bias<<<gg, 256, GEMM_SMEM>>>(xt, Wvt, bv, Vlin, M, N, K);

    int rope_total = B_ * H_ * S_ * 64;
    rope_relayout_kernel<<<rope_total / 256, 256>>>(Qlin, Klin, Vlin, Qh, Kh, Vh);

    cudaFuncSetAttribute(attn_kernel,
                         cudaFuncAttributeMaxDynamicSharedMemorySize, ATT_SMEM);
    attn_kernel<<<dim3(S_ / 64, H_, B_), 256, ATT_SMEM>>>(Qh, Kh, Vh, Oh);

    int o_total = B_ * H_ * S_ * DK_;
    relayout_out_kernel<<<o_total / 256, 256>>>(Oh, Olin);

    tf32_gemm_nt_bias<<<gg, 256, GEMM_SMEM>>>(Olin, Wot, bo, out, M, N, K);
}

// round 4
// speedup vs baseline: 2.7834x; 1.3822x over previous
#include <cuda_runtime.h>
#include <cuda_bf16.h>
#include <math.h>
#include <cstdint>

// Problem constants
#define B_ 2
#define S_ 2048
#define D_ 2048
#define H_ 16
#define DK_ 128

static const size_t NBSD = (size_t)B_ * S_ * D_;
__device__ float g_scratch[6 * (size_t)B_ * S_ * D_];
__device__ float g_xt[(size_t)B_ * S_ * D_];          // tf32-rounded x
__device__ float g_wt[4 * (size_t)D_ * D_];           // tf32-rounded Wq,Wk,Wv,Wo

// ============================================================================
// Helpers (arch-generic PTX only: cp.async + mma.sync, both sm_80+)
// ============================================================================
__device__ __forceinline__ uint32_t smem_to_u32(const void* smem_ptr) {
    uint32_t addr;
    asm("{ .reg .u64 tmp; cvta.to.shared.u64 tmp, %1; cvt.u32.u64 %0, tmp; }"
        : "=r"(addr) : "l"(smem_ptr));
    return addr;
}

__device__ __forceinline__ void cp_async16(uint32_t smem_addr, const void* gptr) {
    asm volatile("cp.async.cg.shared.global [%0], [%1], 16;"
                 :: "r"(smem_addr), "l"(gptr));
}
#define CP_ASYNC_COMMIT() asm volatile("cp.async.commit_group;" ::: "memory")
#define CP_ASYNC_WAIT(n)  asm volatile("cp.async.wait_group %0;" :: "n"(n) : "memory")

__device__ __forceinline__ void mma_tf32_16n8k8(float* d, const uint32_t* a,
                                                const uint32_t* b) {
    asm volatile(
        "mma.sync.aligned.m16n8k8.row.col.f32.tf32.tf32.f32 "
        "{%0,%1,%2,%3}, {%4,%5,%6,%7}, {%8,%9}, {%0,%1,%2,%3};"
        : "+f"(d[0]), "+f"(d[1]), "+f"(d[2]), "+f"(d[3])
        : "r"(a[0]), "r"(a[1]), "r"(a[2]), "r"(a[3]), "r"(b[0]), "r"(b[1]));
}

__device__ __forceinline__ float tf32_round(float x) {
    uint32_t u;
    asm("cvt.rna.tf32.f32 %0, %1;" : "=r"(u) : "f"(x));
    return __uint_as_float(u);
}

// ============================================================================
// tf32 rounding pre-pass (elementwise, float4)
// ============================================================================
__global__ __launch_bounds__(256) void tf32_round_kernel(
    const float* __restrict__ in, float* __restrict__ out, int n4)
{
    int i = blockIdx.x * 256 + threadIdx.x;
    if (i >= n4) return;
    float4 v = ((const float4*)in)[i];
    v.x = tf32_round(v.x); v.y = tf32_round(v.y);
    v.z = tf32_round(v.z); v.w = tf32_round(v.w);
    ((float4*)out)[i] = v;
}

// ============================================================================
// mma.sync tf32 GEMM: C[M,N] = A[M,K] @ W[N,K]^T + bias[N]
// BM=BN=128, BK=32, 8 warps (4 M x 2 N), warp tile 32x64, m16n8k8 atoms.
// 3-stage cp.async pipeline. Smem stride 36 floats (conflict-free frags).
// ============================================================================
#define GSTR 36
#define GEMM_STAGE_FLOATS (2 * 128 * GSTR)          // A tile + B tile
#define GEMM_STAGE_BYTES  (GEMM_STAGE_FLOATS * 4)   // 36864
#define GEMM_SMEM (3 * GEMM_STAGE_BYTES + 16)

__device__ __forceinline__ void gemm_load_stage(
    const float* __restrict__ A, const float* __restrict__ W,
    int row0, int col0, int K, int kc, uint32_t sbase, int tid)
{
#pragma unroll
    for (int i = 0; i < 8; i++) {
        int q = i * 256 + tid;           // 0..2047
        int isB = (i >= 4);
        int r = (q & 1023) >> 3;         // tile row 0..127
        int c = q & 7;                   // 16B chunk 0..7
        const float* g = isB
            ? (W + (size_t)(col0 + r) * K + kc * 32 + c * 4)
            : (A + (size_t)(row0 + r) * K + kc * 32 + c * 4);
        uint32_t soff = (uint32_t)(isB ? (128 * GSTR * 4) : 0) +
                        (uint32_t)(r * GSTR * 4 + c * 16);
        cp_async16(sbase + soff, g);
    }
    CP_ASYNC_COMMIT();
}

__global__ __launch_bounds__(256) void tf32_gemm_nt_bias(
    const float* __restrict__ A, const float* __restrict__ W,
    const float* __restrict__ bias, float* __restrict__ C,
    int M, int N, int K)
{
    extern __shared__ __align__(16) float dsm[];

    int tid = threadIdx.x;
    int wid = tid >> 5;
    int lane = tid & 31;
    int gr = lane >> 2;      // group row 0..7
    int gc = lane & 3;       // group col 0..3
    int wm = wid & 3;        // warp m index 0..3
    int wn = wid >> 2;       // warp n index 0..1

    int bx = blockIdx.x, by = blockIdx.y;
    int row0 = by * 128, col0 = bx * 128;

    uint32_t sb_u32 = smem_to_u32(dsm);

    float acc[2][8][4];
#pragma unroll
    for (int i = 0; i < 2; i++)
#pragma unroll
        for (int j = 0; j < 8; j++)
#pragma unroll
            for (int k = 0; k < 4; k++) acc[i][j][k] = 0.f;

    const int NC = K >> 5;   // 64 stages of K=32

    gemm_load_stage(A, W, row0, col0, K, 0, sb_u32 + 0 * GEMM_STAGE_BYTES, tid);
    gemm_load_stage(A, W, row0, col0, K, 1, sb_u32 + 1 * GEMM_STAGE_BYTES, tid);

    for (int j = 0; j < NC; j++) {
        if (j + 2 < NC) { CP_ASYNC_WAIT(1); } else { CP_ASYNC_WAIT(0); }
        __syncthreads();

        int s = j % 3;
        int jn = j + 2;
        if (jn < NC) {
            gemm_load_stage(A, W, row0, col0, K, jn,
                            sb_u32 + (jn % 3) * GEMM_STAGE_BYTES, tid);
        }

        const float* As = dsm + (size_t)s * GEMM_STAGE_FLOATS;
        const float* Bs = As + 128 * GSTR;

#pragma unroll
        for (int kst = 0; kst < 4; kst++) {
            int k0 = kst * 8;
            uint32_t af[2][4];
#pragma unroll
            for (int ma = 0; ma < 2; ma++) {
                int r = wm * 32 + ma * 16 + gr;
                af[ma][0] = __float_as_uint(As[r * GSTR + k0 + gc]);
                af[ma][1] = __float_as_uint(As[(r + 8) * GSTR + k0 + gc]);
                af[ma][2] = __float_as_uint(As[r * GSTR + k0 + gc + 4]);
                af[ma][3] = __float_as_uint(As[(r + 8) * GSTR + k0 + gc + 4]);
            }
            uint32_t bf[8][2];
#pragma unroll
            for (int na = 0; na < 8; na++) {
                int n = wn * 64 + na * 8 + gr;
                bf[na][0] = __float_as_uint(Bs[n * GSTR + k0 + gc]);
                bf[na][1] = __float_as_uint(Bs[n * GSTR + k0 + gc + 4]);
            }
#pragma unroll
            for (int ma = 0; ma < 2; ma++)
#pragma unroll
                for (int na = 0; na < 8; na++)
                    mma_tf32_16n8k8(acc[ma][na], af[ma], bf[na]);
        }
        __syncthreads();
    }

    // Epilogue
#pragma unroll
    for (int ma = 0; ma < 2; ma++) {
        int row = row0 + wm * 32 + ma * 16 + gr;
#pragma unroll
        for (int na = 0; na < 8; na++) {
            int col = col0 + wn * 64 + na * 8 + gc * 2;
            float2 bb = *(const float2*)(bias + col);
            float2 o0, o1;
            o0.x = acc[ma][na][0] + bb.x;
            o0.y = acc[ma][na][1] + bb.y;
            o1.x = acc[ma][na][2] + bb.x;
            o1.y = acc[ma][na][3] + bb.y;
            *(float2*)(C + (size_t)row * N + col) = o0;
            *(float2*)(C + (size_t)(row + 8) * N + col) = o1;
        }
    }
}

// ---------------------------------------------------------------------------
// RoPE + relayout: [B,S,D] (d = h*128+i) -> [B,H,S,DK], rope applied to Q,K.
// Q,K written fp32 (attn splits hi/lo itself); V written tf32-rounded.
// ---------------------------------------------------------------------------
__global__ __launch_bounds__(256) void rope_relayout_kernel(
    const float* __restrict__ Qlin, const float* __restrict__ Klin,
    const float* __restrict__ Vlin,
    float* __restrict__ Qh, float* __restrict__ Kh, float* __restrict__ Vh)
{
    int idx = blockIdx.x * 256 + threadIdx.x;          // B*H*S*64
    if (idx >= B_ * H_ * S_ * 64) return;
    int i  = idx & 63;
    int s  = (idx >> 6) & (S_ - 1);
    int hb = idx >> 17;
    int h  = hb & (H_ - 1);
    int b  = hb >> 4;

    size_t lin = ((size_t)(b * S_ + s)) * D_ + h * DK_ + i;
    size_t out = ((size_t)hb * S_ + s) * DK_ + i;

    float inv = 1.0f / powf(10000.0f, (float)(2 * i) / 128.0f);
    float ang = (float)s * inv;
    float sn, cs;
    sincosf(ang, &sn, &cs);

    float q0 = Qlin[lin], q1 = Qlin[lin + 64];
    Qh[out]      = q0 * cs - q1 * sn;
    Qh[out + 64] = q1 * cs + q0 * sn;
    float k0 = Klin[lin], k1 = Klin[lin + 64];
    Kh[out]      = k0 * cs - k1 * sn;
    Kh[out + 64] = k1 * cs + k0 * sn;
    Vh[out]      = tf32_round(Vlin[lin]);
    Vh[out + 64] = tf32_round(Vlin[lin + 64]);
}

// ---------------------------------------------------------------------------
// Tensor-core flash attention (causal). BM=BN=64, DK=128, 256 threads (8 warps).
// Scores: 3xTF32 (hi/lo split, fp32-grade). PV: plain tf32.
// Output written directly to [B,S,D] layout, tf32-rounded (feeds final GEMM).
// ---------------------------------------------------------------------------
#define AQSTR 132
#define AVSTR 136
#define ASSTR 68
#define ATT_SMEM ((4 * 64 * AQSTR + 64 * AVSTR + 64 * ASSTR + 192) * 4)

__global__ __launch_bounds__(256) void attn_mma_kernel(
    const float* __restrict__ Q, const float* __restrict__ K,
    const float* __restrict__ V, float* __restrict__ Olin)
{
    extern __shared__ float sm[];
    float* Qhi  = sm;                       // 64 * 132
    float* Qlo  = Qhi + 64 * AQSTR;
    float* Khi  = Qlo + 64 * AQSTR;
    float* Klo  = Khi + 64 * AQSTR;
    float* Vs   = Klo + 64 * AQSTR;         // 64 * 136
    float* Ss   = Vs + 64 * AVSTR;          // 64 * 68
    float* mrow = Ss + 64 * ASSTR;          // 64
    float* lrow = mrow + 64;                // 64
    float* arow = lrow + 64;                // 64

    int qt = (int)gridDim.x - 1 - (int)blockIdx.x;   // heavy tiles first
    int h = blockIdx.y, b = blockIdx.z;
    size_t base = ((size_t)(b * H_ + h)) * S_ * DK_;
    const float* Qb = Q + base + (size_t)qt * 64 * DK_;
    const float* Kb = K + base;
    const float* Vb = V + base;

    int tid = threadIdx.x;
    int wid = tid >> 5;
    int lane = tid & 31;
    int gr = lane >> 2, gc = lane & 3;
    int wm = wid & 3, wn = wid >> 2;

    // Load Q tile, split into tf32 hi/lo
    for (int i = tid; i < 64 * 32; i += 256) {
        int r = i >> 5, c = (i & 31) << 2;
        float4 v = *(const float4*)(Qb + r * DK_ + c);
        float h0 = tf32_round(v.x), h1 = tf32_round(v.y);
        float h2 = tf32_round(v.z), h3 = tf32_round(v.w);
        Qhi[r * AQSTR + c + 0] = h0; Qlo[r * AQSTR + c + 0] = tf32_round(v.x - h0);
        Qhi[r * AQSTR + c + 1] = h1; Qlo[r * AQSTR + c + 1] = tf32_round(v.y - h1);
        Qhi[r * AQSTR + c + 2] = h2; Qlo[r * AQSTR + c + 2] = tf32_round(v.z - h2);
        Qhi[r * AQSTR + c + 3] = h3; Qlo[r * AQSTR + c + 3] = tf32_round(v.w - h3);
    }
    if (tid < 64) { mrow[tid] = -1e30f; lrow[tid] = 0.f; }

    float oacc[8][4];
#pragma unroll
    for (int i = 0; i < 8; i++)
#pragma unroll
        for (int j = 0; j < 4; j++) oacc[i][j] = 0.f;

    const float scale = 0.088388347648318440f;   // 1/sqrt(128)
    int nkt = qt + 1;

    for (int kt = 0; kt < nkt; kt++) {
        __syncthreads();   // protect Ss/Vs/K smem against prior-iter readers

        // Load K (split hi/lo) and V (pre-rounded) tiles
        for (int i = tid; i < 64 * 32; i += 256) {
            int r = i >> 5, c = (i & 31) << 2;
            float4 kv = *(const float4*)(Kb + (size_t)(kt * 64 + r) * DK_ + c);
            float4 vv = *(const float4*)(Vb + (size_t)(kt * 64 + r) * DK_ + c);
            float h0 = tf32_round(kv.x), h1 = tf32_round(kv.y);
            float h2 = tf32_round(kv.z), h3 = tf32_round(kv.w);
            Khi[r * AQSTR + c + 0] = h0; Klo[r * AQSTR + c + 0] = tf32_round(kv.x - h0);
            Khi[r * AQSTR + c + 1] = h1; Klo[r * AQSTR + c + 1] = tf32_round(kv.y - h1);
            Khi[r * AQSTR + c + 2] = h2; Klo[r * AQSTR + c + 2] = tf32_round(kv.z - h2);
            Khi[r * AQSTR + c + 3] = h3; Klo[r * AQSTR + c + 3] = tf32_round(kv.w - h3);
            Vs[r * AVSTR + c + 0] = vv.x; Vs[r * AVSTR + c + 1] = vv.y;
            Vs[r * AVSTR + c + 2] = vv.z; Vs[r * AVSTR + c + 3] = vv.w;
        }
        __syncthreads();

        // Scores: warp tile 16x32 at (wm*16, wn*32); 4 n8 atoms, 3xTF32
        float sacc[4][4];
#pragma unroll
        for (int i = 0; i < 4; i++)
#pragma unroll
            for (int j = 0; j < 4; j++) sacc[i][j] = 0.f;

        int r0 = wm * 16 + gr;
#pragma unroll
        for (int kst = 0; kst < 16; kst++) {
            int k0 = kst * 8;
            uint32_t ah[4], al[4];
            ah[0] = __float_as_uint(Qhi[r0 * AQSTR + k0 + gc]);
            ah[1] = __float_as_uint(Qhi[(r0 + 8) * AQSTR + k0 + gc]);
            ah[2] = __float_as_uint(Qhi[r0 * AQSTR + k0 + gc + 4]);
            ah[3] = __float_as_uint(Qhi[(r0 + 8) * AQSTR + k0 + gc + 4]);
            al[0] = __float_as_uint(Qlo[r0 * AQSTR + k0 + gc]);
            al[1] = __float_as_uint(Qlo[(r0 + 8) * AQSTR + k0 + gc]);
            al[2] = __float_as_uint(Qlo[r0 * AQSTR + k0 + gc + 4]);
            al[3] = __float_as_uint(Qlo[(r0 + 8) * AQSTR + k0 + gc + 4]);
#pragma unroll
            for (int na = 0; na < 4; na++) {
                int n = wn * 32 + na * 8 + gr;
                uint32_t bh[2], bl[2];
                bh[0] = __float_as_uint(Khi[n * AQSTR + k0 + gc]);
                bh[1] = __float_as_uint(Khi[n * AQSTR + k0 + gc + 4]);
                bl[0] = __float_as_uint(Klo[n * AQSTR + k0 + gc]);
                bl[1] = __float_as_uint(Klo[n * AQSTR + k0 + gc + 4]);
                mma_tf32_16n8k8(sacc[na], ah, bl);
                mma_tf32_16n8k8(sacc[na], al, bh);
                mma_tf32_16n8k8(sacc[na], ah, bh);
            }
        }

        // Scale + causal mask + store to Ss
        bool diag = (kt == qt);
#pragma unroll
        for (int na = 0; na < 4; na++) {
            int c = wn * 32 + na * 8 + 2 * gc;
            float s0 = sacc[na][0] * scale;
            float s1 = sacc[na][1] * scale;
            float s2 = sacc[na][2] * scale;
            float s3 = sacc[na][3] * scale;
            if (diag) {
                if (c > r0) s0 = -1e30f;
                if (c + 1 > r0) s1 = -1e30f;
                if (c > r0 + 8) s2 = -1e30f;
                if (c + 1 > r0 + 8) s3 = -1e30f;
            }
            Ss[r0 * ASSTR + c] = s0;
            Ss[r0 * ASSTR + c + 1] = s1;
            Ss[(r0 + 8) * ASSTR + c] = s2;
            Ss[(r0 + 8) * ASSTR + c + 1] = s3;
        }
        __syncthreads();

        // Online softmax: 4 threads per row; P tf32-rounded at store
        {
            int r = tid >> 2, q4 = tid & 3;
            float rm = -1e30f;
#pragma unroll
            for (int c = 0; c < 64; c += 4) rm = fmaxf(rm, Ss[r * ASSTR + c + q4]);
            rm = fmaxf(rm, __shfl_xor_sync(0xffffffffu, rm, 1));
            rm = fmaxf(rm, __shfl_xor_sync(0xffffffffu, rm, 2));
            float mold = mrow[r];
            float mnew = fmaxf(mold, rm);
            float sum = 0.f;
#pragma unroll
            for (int c = 0; c < 64; c += 4) {
                float p = tf32_round(__expf(Ss[r * ASSTR + c + q4] - mnew));
                Ss[r * ASSTR + c + q4] = p;
                sum += p;
            }
            sum += __shfl_xor_sync(0xffffffffu, sum, 1);
            sum += __shfl_xor_sync(0xffffffffu, sum, 2);
            if (q4 == 0) {
                float alpha = __expf(mold - mnew);
                arow[r] = alpha;
                mrow[r] = mnew;
                lrow[r] = lrow[r] * alpha + sum;
            }
        }
        __syncthreads();

        // Rescale O accumulators
        float a0 = arow[r0], a1 = arow[r0 + 8];
#pragma unroll
        for (int na = 0; na < 8; na++) {
            oacc[na][0] *= a0; oacc[na][1] *= a0;
            oacc[na][2] *= a1; oacc[na][3] *= a1;
        }

        // PV: warp tile 16x64 at (wm*16, wn*64); 8 n8 atoms, K=64
#pragma unroll
        for (int kst = 0; kst < 8; kst++) {
            int k0 = kst * 8;
            uint32_t ap[4];
            ap[0] = __float_as_uint(Ss[r0 * ASSTR + k0 + gc]);
            ap[1] = __float_as_uint(Ss[(r0 + 8) * ASSTR + k0 + gc]);
            ap[2] = __float_as_uint(Ss[r0 * ASSTR + k0 + gc + 4]);
            ap[3] = __float_as_uint(Ss[(r0 + 8) * ASSTR + k0 + gc + 4]);
#pragma unroll
            for (int na = 0; na < 8; na++) {
                int n = wn * 64 + na * 8 + gr;
                uint32_t bv[2];
                bv[0] = __float_as_uint(Vs[(k0 + gc) * AVSTR + n]);
                bv[1] = __float_as_uint(Vs[(k0 + gc + 4) * AVSTR + n]);
                mma_tf32_16n8k8(oacc[na], ap, bv);
            }
        }
    }

    // Epilogue: normalize, round, write directly into [B,S,D] layout
    int r0 = wm * 16 + gr;
    float li0 = 1.0f / lrow[r0];
    float li1 = 1.0f / lrow[r0 + 8];
    int srow0 = qt * 64 + r0;
    float* Og0 = Olin + ((size_t)b * S_ + srow0) * D_ + h * DK_;
    float* Og1 = Olin + ((size_t)b * S_ + srow0 + 8) * D_ + h * DK_;
#pragma unroll
    for (int na = 0; na < 8; na++) {
        int col = wn * 64 + na * 8 + 2 * gc;
        float2 o0, o1;
        o0.x = tf32_round(oacc[na][0] * li0);
        o0.y = tf32_round(oacc[na][1] * li0);
        o1.x = tf32_round(oacc[na][2] * li1);
        o1.y = tf32_round(oacc[na][3] * li1);
        *(float2*)(Og0 + col) = o0;
        *(float2*)(Og1 + col) = o1;
    }
}

// ---------------------------------------------------------------------------
extern "C" void kernel_launch(void* const* d_in, const int* in_sizes, int n_in,
                              void* d_out, int out_size)
{
    const float* x  = (const float*)d_in[0];
    const float* Wq = (const float*)d_in[2];
    const float* bq = (const float*)d_in[3];
    const float* Wk = (const float*)d_in[4];
    const float* bk = (const float*)d_in[5];
    const float* Wv = (const float*)d_in[6];
    const float* bv = (const float*)d_in[7];
    const float* Wo = (const float*)d_in[8];
    const float* bo = (const float*)d_in[9];
    float* out = (float*)d_out;

    float* base = nullptr;
    cudaGetSymbolAddress((void**)&base, g_scratch);
    float* xt = nullptr;
    cudaGetSymbolAddress((void**)&xt, g_xt);
    float* wt = nullptr;
    cudaGetSymbolAddress((void**)&wt, g_wt);

    float* Qlin = base;
    float* Klin = base + NBSD;
    float* Vlin = base + 2 * NBSD;
    float* Qh   = base + 3 * NBSD;
    float* Kh   = base + 4 * NBSD;
    float* Vh   = base + 5 * NBSD;
    float* Olin = Klin;    // dead after rope; attn writes rounded [B,S,D] here
    float* Wqt = wt;
    float* Wkt = wt + (size_t)D_ * D_;
    float* Wvt = wt + 2 * (size_t)D_ * D_;
    float* Wot = wt + 3 * (size_t)D_ * D_;

    const int M = B_ * S_, N = D_, K = D_;

    // tf32 rounding pre-pass
    {
        int nx4 = (int)(NBSD / 4);
        int nw4 = (int)(((size_t)D_ * D_) / 4);
        tf32_round_kernel<<<(nx4 + 255) / 256, 256>>>(x, xt, nx4);
        tf32_round_kernel<<<(nw4 + 255) / 256, 256>>>(Wq, Wqt, nw4);
        tf32_round_kernel<<<(nw4 + 255) / 256, 256>>>(Wk, Wkt, nw4);
        tf32_round_kernel<<<(nw4 + 255) / 256, 256>>>(Wv, Wvt, nw4);
        tf32_round_kernel<<<(nw4 + 255) / 256, 256>>>(Wo, Wot, nw4);
    }

    cudaFuncSetAttribute(tf32_gemm_nt_bias,
                         cudaFuncAttributeMaxDynamicSharedMemorySize, GEMM_SMEM);
    dim3 gg(N / 128, M / 128);   // (16, 32)

    tf32_gemm_nt_bias<<<gg, 256, GEMM_SMEM>>>(xt, Wqt, bq, Qlin, M, N, K);
    tf32_gemm_nt_bias<<<gg, 256, GEMM_SMEM>>>(xt, Wkt, bk, Klin, M, N, K);
    tf32_gemm_nt_bias<<<gg, 256, GEMM_SMEM>>>(xt, Wvt, bv, Vlin, M, N, K);

    int rope_total = B_ * H_ * S_ * 64;
    rope_relayout_kernel<<<rope_total / 256, 256>>>(Qlin, Klin, Vlin, Qh, Kh, Vh);

    cudaFuncSetAttribute(attn_mma_kernel,
                         cudaFuncAttributeMaxDynamicSharedMemorySize, ATT_SMEM);
    attn_mma_kernel<<<dim3(S_ / 64, H_, B_), 256, ATT_SMEM>>>(Qh, Kh, Vh, Olin);

    tf32_gemm_nt_bias<<<gg, 256, GEMM_SMEM>>>(Olin, Wot, bo, out, M, N, K);
}

// round 6
// speedup vs baseline: 3.3472x; 1.2026x over previous
#include <cuda_runtime.h>
#include <cuda_bf16.h>
#include <math.h>
#include <cstdint>

// Problem constants
#define B_ 2
#define S_ 2048
#define D_ 2048
#define H_ 16
#define DK_ 128

static const size_t NBSD = (size_t)B_ * S_ * D_;
// 8 planes: Qlin/Olin, Klin, Vlin, Qhi, Qlo, Khi, Klo, Vr
__device__ float g_scratch[8 * (size_t)B_ * S_ * D_];
__device__ float g_xt[(size_t)B_ * S_ * D_];          // tf32-rounded x
__device__ float g_wt[4 * (size_t)D_ * D_];           // tf32-rounded Wq,Wk,Wv,Wo

// ============================================================================
// Helpers (arch-generic PTX only: cp.async + mma.sync, both sm_80+)
// ============================================================================
__device__ __forceinline__ uint32_t smem_to_u32(const void* smem_ptr) {
    uint32_t addr;
    asm("{ .reg .u64 tmp; cvta.to.shared.u64 tmp, %1; cvt.u32.u64 %0, tmp; }"
        : "=r"(addr) : "l"(smem_ptr));
    return addr;
}

__device__ __forceinline__ void cp_async16(uint32_t smem_addr, const void* gptr) {
    asm volatile("cp.async.cg.shared.global [%0], [%1], 16;"
                 :: "r"(smem_addr), "l"(gptr));
}
#define CP_ASYNC_COMMIT() asm volatile("cp.async.commit_group;" ::: "memory")
#define CP_ASYNC_WAIT(n)  asm volatile("cp.async.wait_group %0;" :: "n"(n) : "memory")

__device__ __forceinline__ void mma_tf32_16n8k8(float* d, const uint32_t* a,
                                                const uint32_t* b) {
    asm volatile(
        "mma.sync.aligned.m16n8k8.row.col.f32.tf32.tf32.f32 "
        "{%0,%1,%2,%3}, {%4,%5,%6,%7}, {%8,%9}, {%0,%1,%2,%3};"
        : "+f"(d[0]), "+f"(d[1]), "+f"(d[2]), "+f"(d[3])
        : "r"(a[0]), "r"(a[1]), "r"(a[2]), "r"(a[3]), "r"(b[0]), "r"(b[1]));
}

__device__ __forceinline__ float tf32_round(float x) {
    uint32_t u;
    asm("cvt.rna.tf32.f32 %0, %1;" : "=r"(u) : "f"(x));
    return __uint_as_float(u);
}

// ============================================================================
// tf32 rounding pre-pass (elementwise, float4)
// ============================================================================
__global__ __launch_bounds__(256) void tf32_round_kernel(
    const float* __restrict__ in, float* __restrict__ out, int n4)
{
    int i = blockIdx.x * 256 + threadIdx.x;
    if (i >= n4) return;
    float4 v = ((const float4*)in)[i];
    v.x = tf32_round(v.x); v.y = tf32_round(v.y);
    v.z = tf32_round(v.z); v.w = tf32_round(v.w);
    ((float4*)out)[i] = v;
}

// ============================================================================
// mma.sync tf32 GEMM: C[M,N] = A[M,K] @ W[N,K]^T + bias[N]
// BM=BN=128, BK=32, 8 warps (4 M x 2 N), warp tile 32x64, m16n8k8 atoms.
// 3-stage cp.async pipeline. Smem stride 36 floats (conflict-free frags).
// ============================================================================
#define GSTR 36
#define GEMM_STAGE_FLOATS (2 * 128 * GSTR)          // A tile + B tile
#define GEMM_STAGE_BYTES  (GEMM_STAGE_FLOATS * 4)   // 36864
#define GEMM_SMEM (3 * GEMM_STAGE_BYTES + 16)

__device__ __forceinline__ void gemm_load_stage(
    const float* __restrict__ A, const float* __restrict__ W,
    int row0, int col0, int K, int kc, uint32_t sbase, int tid)
{
#pragma unroll
    for (int i = 0; i < 8; i++) {
        int q = i * 256 + tid;           // 0..2047
        int isB = (i >= 4);
        int r = (q & 1023) >> 3;         // tile row 0..127
        int c = q & 7;                   // 16B chunk 0..7 (BK=32 floats)
        const float* g = isB
            ? (W + (size_t)(col0 + r) * K + kc * 32 + c * 4)
            : (A + (size_t)(row0 + r) * K + kc * 32 + c * 4);
        uint32_t soff = (uint32_t)(isB ? (128 * GSTR * 4) : 0) +
                        (uint32_t)(r * GSTR * 4 + c * 16);
        cp_async16(sbase + soff, g);
    }
    CP_ASYNC_COMMIT();
}

__global__ __launch_bounds__(256) void tf32_gemm_nt_bias(
    const float* __restrict__ A, const float* __restrict__ W,
    const float* __restrict__ bias, float* __restrict__ C,
    int M, int N, int K)
{
    extern __shared__ __align__(16) float dsm[];

    int tid = threadIdx.x;
    int wid = tid >> 5;
    int lane = tid & 31;
    int gr = lane >> 2;
    int gc = lane & 3;
    int wm = wid & 3;
    int wn = wid >> 2;

    int bx = blockIdx.x, by = blockIdx.y;
    int row0 = by * 128, col0 = bx * 128;

    uint32_t sb_u32 = smem_to_u32(dsm);

    float acc[2][8][4];
#pragma unroll
    for (int i = 0; i < 2; i++)
#pragma unroll
        for (int j = 0; j < 8; j++)
#pragma unroll
            for (int k = 0; k < 4; k++) acc[i][j][k] = 0.f;

    const int NC = K >> 5;

    gemm_load_stage(A, W, row0, col0, K, 0, sb_u32 + 0 * GEMM_STAGE_BYTES, tid);
    gemm_load_stage(A, W, row0, col0, K, 1, sb_u32 + 1 * GEMM_STAGE_BYTES, tid);

    for (int j = 0; j < NC; j++) {
        if (j + 2 < NC) { CP_ASYNC_WAIT(1); } else { CP_ASYNC_WAIT(0); }
        __syncthreads();

        int s = j % 3;
        int jn = j + 2;
        if (jn < NC) {
            gemm_load_stage(A, W, row0, col0, K, jn,
                            sb_u32 + (jn % 3) * GEMM_STAGE_BYTES, tid);
        }

        const float* As = dsm + (size_t)s * GEMM_STAGE_FLOATS;
        const float* Bs = As + 128 * GSTR;

#pragma unroll
        for (int kst = 0; kst < 4; kst++) {
            int k0 = kst * 8;
            uint32_t af[2][4];
#pragma unroll
            for (int ma = 0; ma < 2; ma++) {
                int r = wm * 32 + ma * 16 + gr;
                af[ma][0] = __float_as_uint(As[r * GSTR + k0 + gc]);
                af[ma][1] = __float_as_uint(As[(r + 8) * GSTR + k0 + gc]);
                af[ma][2] = __float_as_uint(As[r * GSTR + k0 + gc + 4]);
                af[ma][3] = __float_as_uint(As[(r + 8) * GSTR + k0 + gc + 4]);
            }
            uint32_t bf[8][2];
#pragma unroll
            for (int na = 0; na < 8; na++) {
                int n = wn * 64 + na * 8 + gr;
                bf[na][0] = __float_as_uint(Bs[n * GSTR + k0 + gc]);
                bf[na][1] = __float_as_uint(Bs[n * GSTR + k0 + gc + 4]);
            }
#pragma unroll
            for (int ma = 0; ma < 2; ma++)
#pragma unroll
                for (int na = 0; na < 8; na++)
                    mma_tf32_16n8k8(acc[ma][na], af[ma], bf[na]);
        }
        __syncthreads();
    }

#pragma unroll
    for (int ma = 0; ma < 2; ma++) {
        int row = row0 + wm * 32 + ma * 16 + gr;
#pragma unroll
        for (int na = 0; na < 8; na++) {
            int col = col0 + wn * 64 + na * 8 + gc * 2;
            float2 bb = *(const float2*)(bias + col);
            float2 o0, o1;
            o0.x = acc[ma][na][0] + bb.x;
            o0.y = acc[ma][na][1] + bb.y;
            o1.x = acc[ma][na][2] + bb.x;
            o1.y = acc[ma][na][3] + bb.y;
            *(float2*)(C + (size_t)row * N + col) = o0;
            *(float2*)(C + (size_t)(row + 8) * N + col) = o1;
        }
    }
}

// ---------------------------------------------------------------------------
// RoPE + relayout + tf32 hi/lo pre-split.
// [B,S,D] -> [B,H,S,DK]: Qhi,Qlo,Khi,Klo (3xTF32 operands), Vr (tf32-rounded).
// ---------------------------------------------------------------------------
__global__ __launch_bounds__(256) void rope_relayout_kernel(
    const float* __restrict__ Qlin, const float* __restrict__ Klin,
    const float* __restrict__ Vlin,
    float* __restrict__ Qhi, float* __restrict__ Qlo,
    float* __restrict__ Khi, float* __restrict__ Klo,
    float* __restrict__ Vr)
{
    int idx = blockIdx.x * 256 + threadIdx.x;          // B*H*S*64
    if (idx >= B_ * H_ * S_ * 64) return;
    int i  = idx & 63;
    int s  = (idx >> 6) & (S_ - 1);
    int hb = idx >> 17;
    int h  = hb & (H_ - 1);
    int b  = hb >> 4;

    size_t lin = ((size_t)(b * S_ + s)) * D_ + h * DK_ + i;
    size_t out = ((size_t)hb * S_ + s) * DK_ + i;

    float inv = 1.0f / powf(10000.0f, (float)(2 * i) / 128.0f);
    float ang = (float)s * inv;
    float sn, cs;
    sincosf(ang, &sn, &cs);

    float q0 = Qlin[lin], q1 = Qlin[lin + 64];
    float qr0 = q0 * cs - q1 * sn;
    float qr1 = q1 * cs + q0 * sn;
    float hh;
    hh = tf32_round(qr0); Qhi[out]      = hh; Qlo[out]      = tf32_round(qr0 - hh);
    hh = tf32_round(qr1); Qhi[out + 64] = hh; Qlo[out + 64] = tf32_round(qr1 - hh);

    float k0 = Klin[lin], k1 = Klin[lin + 64];
    float kr0 = k0 * cs - k1 * sn;
    float kr1 = k1 * cs + k0 * sn;
    hh = tf32_round(kr0); Khi[out]      = hh; Klo[out]      = tf32_round(kr0 - hh);
    hh = tf32_round(kr1); Khi[out + 64] = hh; Klo[out + 64] = tf32_round(kr1 - hh);

    Vr[out]      = tf32_round(Vlin[lin]);
    Vr[out + 64] = tf32_round(Vlin[lin + 64]);
}

// ---------------------------------------------------------------------------
// Tensor-core flash attention (causal). BM=BN=64, DK=128, 256 threads (8 warps).
// Scores: 3xTF32 from pre-split Q/K planes. PV: plain tf32.
// cp.async pipelined loads: V double-buffered, K prefetched post-scores.
// Output written directly to [B,S,D] layout, tf32-rounded.
// ---------------------------------------------------------------------------
#define AQSTR 132
#define AVSTR 136
#define ASSTR 68
// float offsets in dynamic smem
#define OQHI 0
#define OQLO (64 * AQSTR)                 // 8448
#define OKHI (2 * 64 * AQSTR)             // 16896
#define OKLO (3 * 64 * AQSTR)             // 25344
#define OV0  (4 * 64 * AQSTR)             // 33792
#define OV1  (OV0 + 64 * AVSTR)           // 42496
#define OSS  (OV1 + 64 * AVSTR)           // 51200
#define OMR  (OSS + 64 * ASSTR)           // 55552
#define OLR  (OMR + 64)
#define OAR  (OLR + 64)
#define ATT_FLOATS (OAR + 64)             // 55744
#define ATT_SMEM (ATT_FLOATS * 4)         // 222976 bytes

__global__ __launch_bounds__(256) void attn_mma_kernel(
    const float* __restrict__ Qhi_g, const float* __restrict__ Qlo_g,
    const float* __restrict__ Khi_g, const float* __restrict__ Klo_g,
    const float* __restrict__ Vg, float* __restrict__ Olin)
{
    extern __shared__ __align__(16) float sm[];
    uint32_t sb = smem_to_u32(sm);

    int qt = (int)gridDim.x - 1 - (int)blockIdx.x;   // heavy tiles first
    int h = blockIdx.y, b = blockIdx.z;
    size_t base = ((size_t)(b * H_ + h)) * S_ * DK_;
    size_t qoff = base + (size_t)qt * 64 * DK_;

    int tid = threadIdx.x;
    int wid = tid >> 5;
    int lane = tid & 31;
    int gr = lane >> 2, gc = lane & 3;
    int wm = wid & 3, wn = wid >> 2;

    // Initial loads: Q hi/lo, K(0) hi/lo, V(0) — cp.async.
    // One 64x128 tile = 2048 x 16B chunks: r = q>>5 (row), c = q&31 (16B chunk).
#pragma unroll
    for (int i = 0; i < 8; i++) {
        int q = i * 256 + tid;           // 0..2047
        int r = q >> 5, c = q & 31;
        size_t g = (size_t)r * DK_ + c * 4;
        uint32_t so132 = (uint32_t)(r * AQSTR + c * 4) * 4;
        uint32_t so136 = (uint32_t)(r * AVSTR + c * 4) * 4;
        cp_async16(sb + OQHI * 4 + so132, Qhi_g + qoff + g);
        cp_async16(sb + OQLO * 4 + so132, Qlo_g + qoff + g);
        cp_async16(sb + OKHI * 4 + so132, Khi_g + base + g);
        cp_async16(sb + OKLO * 4 + so132, Klo_g + base + g);
        cp_async16(sb + OV0 * 4 + so136, Vg + base + g);
    }
    CP_ASYNC_COMMIT();
    CP_ASYNC_WAIT(0);
    if (tid < 64) { sm[OMR + tid] = -1e30f; sm[OLR + tid] = 0.f; }
    __syncthreads();

    const float* Qhi = sm + OQHI;
    const float* Qlo = sm + OQLO;
    const float* Khi = sm + OKHI;
    const float* Klo = sm + OKLO;
    float* Ss = sm + OSS;

    float oacc[8][4];
#pragma unroll
    for (int i = 0; i < 8; i++)
#pragma unroll
        for (int j = 0; j < 4; j++) oacc[i][j] = 0.f;

    const float scale = 0.088388347648318440f;   // 1/sqrt(128)
    int nkt = qt + 1;
    int r0 = wm * 16 + gr;

    for (int kt = 0; kt < nkt; kt++) {
        int vb = kt & 1;
        const float* Vs = sm + (vb ? OV1 : OV0);

        // Prefetch V(kt+1) into alternate buffer (fully overlapped)
        if (kt + 1 < nkt) {
            size_t vt = base + (size_t)(kt + 1) * 64 * DK_;
            uint32_t vdst = sb + (uint32_t)(vb ? OV0 : OV1) * 4;
#pragma unroll
            for (int i = 0; i < 8; i++) {
                int q = i * 256 + tid;
                int r = q >> 5, c = q & 31;
                cp_async16(vdst + (uint32_t)(r * AVSTR + c * 4) * 4,
                           Vg + vt + (size_t)r * DK_ + c * 4);
            }
            CP_ASYNC_COMMIT();
        }

        // Scores: warp tile 16x32 at (wm*16, wn*32); 3xTF32
        float sacc[4][4];
#pragma unroll
        for (int i = 0; i < 4; i++)
#pragma unroll
            for (int j = 0; j < 4; j++) sacc[i][j] = 0.f;

#pragma unroll
        for (int kst = 0; kst < 16; kst++) {
            int k0 = kst * 8;
            uint32_t ah[4], al[4];
            ah[0] = __float_as_uint(Qhi[r0 * AQSTR + k0 + gc]);
            ah[1] = __float_as_uint(Qhi[(r0 + 8) * AQSTR + k0 + gc]);
            ah[2] = __float_as_uint(Qhi[r0 * AQSTR + k0 + gc + 4]);
            ah[3] = __float_as_uint(Qhi[(r0 + 8) * AQSTR + k0 + gc + 4]);
            al[0] = __float_as_uint(Qlo[r0 * AQSTR + k0 + gc]);
            al[1] = __float_as_uint(Qlo[(r0 + 8) * AQSTR + k0 + gc]);
            al[2] = __float_as_uint(Qlo[r0 * AQSTR + k0 + gc + 4]);
            al[3] = __float_as_uint(Qlo[(r0 + 8) * AQSTR + k0 + gc + 4]);
#pragma unroll
            for (int na = 0; na < 4; na++) {
                int n = wn * 32 + na * 8 + gr;
                uint32_t bh[2], bl[2];
                bh[0] = __float_as_uint(Khi[n * AQSTR + k0 + gc]);
                bh[1] = __float_as_uint(Khi[n * AQSTR + k0 + gc + 4]);
                bl[0] = __float_as_uint(Klo[n * AQSTR + k0 + gc]);
                bl[1] = __float_as_uint(Klo[n * AQSTR + k0 + gc + 4]);
                mma_tf32_16n8k8(sacc[na], ah, bl);
                mma_tf32_16n8k8(sacc[na], al, bh);
                mma_tf32_16n8k8(sacc[na], ah, bh);
            }
        }

        // Scale + causal mask + store to Ss
        bool diag = (kt == qt);
#pragma unroll
        for (int na = 0; na < 4; na++) {
            int c = wn * 32 + na * 8 + 2 * gc;
            float s0 = sacc[na][0] * scale;
            float s1 = sacc[na][1] * scale;
            float s2 = sacc[na][2] * scale;
            float s3 = sacc[na][3] * scale;
            if (diag) {
                if (c > r0) s0 = -1e30f;
                if (c + 1 > r0) s1 = -1e30f;
                if (c > r0 + 8) s2 = -1e30f;
                if (c + 1 > r0 + 8) s3 = -1e30f;
            }
            Ss[r0 * ASSTR + c] = s0;
            Ss[r0 * ASSTR + c + 1] = s1;
            Ss[(r0 + 8) * ASSTR + c] = s2;
            Ss[(r0 + 8) * ASSTR + c + 1] = s3;
        }
        __syncthreads();

        // Prefetch K(kt+1) hi/lo — K buffer is dead until next iteration's scores
        if (kt + 1 < nkt) {
            size_t ktb = base + (size_t)(kt + 1) * 64 * DK_;
#pragma unroll
            for (int i = 0; i < 8; i++) {
                int q = i * 256 + tid;
                int r = q >> 5, c = q & 31;
                size_t g = ktb + (size_t)r * DK_ + c * 4;
                uint32_t so = (uint32_t)(r * AQSTR + c * 4) * 4;
                cp_async16(sb + OKHI * 4 + so, Khi_g + g);
                cp_async16(sb + OKLO * 4 + so, Klo_g + g);
            }
            CP_ASYNC_COMMIT();
        }

        // Online softmax: 4 threads per row; P tf32-rounded at store
        {
            int r = tid >> 2, q4 = tid & 3;
            float rm = -1e30f;
#pragma unroll
            for (int c = 0; c < 64; c += 4) rm = fmaxf(rm, Ss[r * ASSTR + c + q4]);
            rm = fmaxf(rm, __shfl_xor_sync(0xffffffffu, rm, 1));
            rm = fmaxf(rm, __shfl_xor_sync(0xffffffffu, rm, 2));
            float mold = sm[OMR + r];
            float mnew = fmaxf(mold, rm);
            float sum = 0.f;
#pragma unroll
            for (int c = 0; c < 64; c += 4) {
                float p = tf32_round(__expf(Ss[r * ASSTR + c + q4] - mnew));
                Ss[r * ASSTR + c + q4] = p;
                sum += p;
            }
            sum += __shfl_xor_sync(0xffffffffu, sum, 1);
            sum += __shfl_xor_sync(0xffffffffu, sum, 2);
            if (q4 == 0) {
                float alpha = __expf(mold - mnew);
                sm[OAR + r] = alpha;
                sm[OMR + r] = mnew;
                sm[OLR + r] = sm[OLR + r] * alpha + sum;
            }
        }
        __syncthreads();

        // Rescale O accumulators
        float a0 = sm[OAR + r0], a1 = sm[OAR + r0 + 8];
#pragma unroll
        for (int na = 0; na < 8; na++) {
            oacc[na][0] *= a0; oacc[na][1] *= a0;
            oacc[na][2] *= a1; oacc[na][3] *= a1;
        }

        // PV: warp tile 16x64 at (wm*16, wn*64); plain tf32, K=64
#pragma unroll
        for (int kst = 0; kst < 8; kst++) {
            int k0 = kst * 8;
            uint32_t ap[4];
            ap[0] = __float_as_uint(Ss[r0 * ASSTR + k0 + gc]);
            ap[1] = __float_as_uint(Ss[(r0 + 8) * ASSTR + k0 + gc]);
            ap[2] = __float_as_uint(Ss[r0 * ASSTR + k0 + gc + 4]);
            ap[3] = __float_as_uint(Ss[(r0 + 8) * ASSTR + k0 + gc + 4]);
#pragma unroll
            for (int na = 0; na < 8; na++) {
                int n = wn * 64 + na * 8 + gr;
                uint32_t bv[2];
                bv[0] = __float_as_uint(Vs[(k0 + gc) * AVSTR + n]);
                bv[1] = __float_as_uint(Vs[(k0 + gc + 4) * AVSTR + n]);
                mma_tf32_16n8k8(oacc[na], ap, bv);
            }
        }

        // All prefetches (V and K hi/lo) must land before next iteration
        CP_ASYNC_WAIT(0);
        __syncthreads();
    }

    // Epilogue: normalize, round, write directly into [B,S,D] layout
    float li0 = 1.0f / sm[OLR + r0];
    float li1 = 1.0f / sm[OLR + r0 + 8];
    int srow0 = qt * 64 + r0;
    float* Og0 = Olin + ((size_t)b * S_ + srow0) * D_ + h * DK_;
    float* Og1 = Olin + ((size_t)b * S_ + srow0 + 8) * D_ + h * DK_;
#pragma unroll
    for (int na = 0; na < 8; na++) {
        int col = wn * 64 + na * 8 + 2 * gc;
        float2 o0, o1;
        o0.x = tf32_round(oacc[na][0] * li0);
        o0.y = tf32_round(oacc[na][1] * li0);
        o1.x = tf32_round(oacc[na][2] * li1);
        o1.y = tf32_round(oacc[na][3] * li1);
        *(float2*)(Og0 + col) = o0;
        *(float2*)(Og1 + col) = o1;
    }
}

// ---------------------------------------------------------------------------
extern "C" void kernel_launch(void* const* d_in, const int* in_sizes, int n_in,
                              void* d_out, int out_size)
{
    const float* x  = (const float*)d_in[0];
    const float* Wq = (const float*)d_in[2];
    const float* bq = (const float*)d_in[3];
    const float* Wk = (const float*)d_in[4];
    const float* bk = (const float*)d_in[5];
    const float* Wv = (const float*)d_in[6];
    const float* bv = (const float*)d_in[7];
    const float* Wo = (const float*)d_in[8];
    const float* bo = (const float*)d_in[9];
    float* out = (float*)d_out;

    float* base = nullptr;
    cudaGetSymbolAddress((void**)&base, g_scratch);
    float* xt = nullptr;
    cudaGetSymbolAddress((void**)&xt, g_xt);
    float* wt = nullptr;
    cudaGetSymbolAddress((void**)&wt, g_wt);

    float* Qlin = base;                 // plane 0 (later Olin)
    float* Klin = base + NBSD;          // plane 1
    float* Vlin = base + 2 * NBSD;      // plane 2
    float* Qhi  = base + 3 * NBSD;      // plane 3
    float* Qlo  = base + 4 * NBSD;      // plane 4
    float* Khi  = base + 5 * NBSD;      // plane 5
    float* Klo  = base + 6 * NBSD;      // plane 6
    float* Vr   = base + 7 * NBSD;      // plane 7
    float* Olin = Qlin;                 // dead after rope
    float* Wqt = wt;
    float* Wkt = wt + (size_t)D_ * D_;
    float* Wvt = wt + 2 * (size_t)D_ * D_;
    float* Wot = wt + 3 * (size_t)D_ * D_;

    const int M = B_ * S_, N = D_, K = D_;

    // tf32 rounding pre-pass
    {
        int nx4 = (int)(NBSD / 4);
        int nw4 = (int)(((size_t)D_ * D_) / 4);
        tf32_round_kernel<<<(nx4 + 255) / 256, 256>>>(x, xt, nx4);
        tf32_round_kernel<<<(nw4 + 255) / 256, 256>>>(Wq, Wqt, nw4);
        tf32_round_kernel<<<(nw4 + 255) / 256, 256>>>(Wk, Wkt, nw4);
        tf32_round_kernel<<<(nw4 + 255) / 256, 256>>>(Wv, Wvt, nw4);
        tf32_round_kernel<<<(nw4 + 255) / 256, 256>>>(Wo, Wot, nw4);
    }

    cudaFuncSetAttribute(tf32_gemm_nt_bias,
                         cudaFuncAttributeMaxDynamicSharedMemorySize, GEMM_SMEM);
    dim3 gg(N / 128, M / 128);   // (16, 32)

    tf32_gemm_nt_bias<<<gg, 256, GEMM_SMEM>>>(xt, Wqt, bq, Qlin, M, N, K);
    tf32_gemm_nt_bias<<<gg, 256, GEMM_SMEM>>>(xt, Wkt, bk, Klin, M, N, K);
    tf32_gemm_nt_bias<<<gg, 256, GEMM_SMEM>>>(xt, Wvt, bv, Vlin, M, N, K);

    int rope_total = B_ * H_ * S_ * 64;
    rope_relayout_kernel<<<rope_total / 256, 256>>>(Qlin, Klin, Vlin,
                                                    Qhi, Qlo, Khi, Klo, Vr);

    cudaFuncSetAttribute(attn_mma_kernel,
                         cudaFuncAttributeMaxDynamicSharedMemorySize, ATT_SMEM);
    attn_mma_kernel<<<dim3(S_ / 64, H_, B_), 256, ATT_SMEM>>>(
        Qhi, Qlo, Khi, Klo, Vr, Olin);

    tf32_gemm_nt_bias<<<gg, 256, GEMM_SMEM>>>(Olin, Wot, bo, out, M, N, K);
}

// round 7
// speedup vs baseline: 3.3919x; 1.0134x over previous
#include <cuda_runtime.h>
#include <cuda_bf16.h>
#include <math.h>
#include <cstdint>

// Problem constants
#define B_ 2
#define S_ 2048
#define D_ 2048
#define H_ 16
#define DK_ 128

static const size_t NBSD = (size_t)B_ * S_ * D_;
// 8 planes: Qlin/Olin, Klin, Vlin, Qhi, Qlo, Khi, Klo, Vr
__device__ float g_scratch[8 * (size_t)B_ * S_ * D_];
__device__ float g_xt[(size_t)B_ * S_ * D_];          // tf32-rounded x
__device__ float g_wt[4 * (size_t)D_ * D_];           // tf32-rounded Wq,Wk,Wv,Wo

// ============================================================================
// Helpers (arch-generic PTX only: cp.async + mma.sync, both sm_80+)
// ============================================================================
__device__ __forceinline__ uint32_t smem_to_u32(const void* smem_ptr) {
    uint32_t addr;
    asm("{ .reg .u64 tmp; cvta.to.shared.u64 tmp, %1; cvt.u32.u64 %0, tmp; }"
        : "=r"(addr) : "l"(smem_ptr));
    return addr;
}

__device__ __forceinline__ void cp_async16(uint32_t smem_addr, const void* gptr) {
    asm volatile("cp.async.cg.shared.global [%0], [%1], 16;"
                 :: "r"(smem_addr), "l"(gptr));
}
#define CP_ASYNC_COMMIT() asm volatile("cp.async.commit_group;" ::: "memory")
#define CP_ASYNC_WAIT(n)  asm volatile("cp.async.wait_group %0;" :: "n"(n) : "memory")

__device__ __forceinline__ void mma_tf32_16n8k8(float* d, const uint32_t* a,
                                                const uint32_t* b) {
    asm volatile(
        "mma.sync.aligned.m16n8k8.row.col.f32.tf32.tf32.f32 "
        "{%0,%1,%2,%3}, {%4,%5,%6,%7}, {%8,%9}, {%0,%1,%2,%3};"
        : "+f"(d[0]), "+f"(d[1]), "+f"(d[2]), "+f"(d[3])
        : "r"(a[0]), "r"(a[1]), "r"(a[2]), "r"(a[3]), "r"(b[0]), "r"(b[1]));
}

__device__ __forceinline__ float tf32_round(float x) {
    uint32_t u;
    asm("cvt.rna.tf32.f32 %0, %1;" : "=r"(u) : "f"(x));
    return __uint_as_float(u);
}

// ============================================================================
// tf32 rounding pre-pass (elementwise, float4)
// ============================================================================
__global__ __launch_bounds__(256) void tf32_round_kernel(
    const float* __restrict__ in, float* __restrict__ out, int n4)
{
    int i = blockIdx.x * 256 + threadIdx.x;
    if (i >= n4) return;
    float4 v = ((const float4*)in)[i];
    v.x = tf32_round(v.x); v.y = tf32_round(v.y);
    v.z = tf32_round(v.z); v.w = tf32_round(v.w);
    ((float4*)out)[i] = v;
}

// ============================================================================
// mma.sync tf32 GEMM: C[M,N] = A[M,K] @ W[N,K]^T + bias[N]
// BM=128, BN=256, BK=32, 8 warps (2 M x 4 N), warp tile 64x64, m16n8k8.
// 3-stage cp.async pipeline. Smem stride 36 floats (conflict-free frags).
// ============================================================================
#define GSTR 36
#define GEMM_STAGE_FLOATS ((128 + 256) * GSTR)      // A tile + B tile = 13824
#define GEMM_STAGE_BYTES  (GEMM_STAGE_FLOATS * 4)   // 55296
#define GEMM_SMEM (3 * GEMM_STAGE_BYTES + 16)       // 165904

__device__ __forceinline__ void gemm_load_stage(
    const float* __restrict__ A, const float* __restrict__ W,
    int row0, int col0, int K, int kc, uint32_t sbase, int tid)
{
    // A tile: 128 rows x 8 chunks = 1024 chunks
#pragma unroll
    for (int i = 0; i < 4; i++) {
        int q = i * 256 + tid;           // 0..1023
        int r = q >> 3;                  // 0..127
        int c = q & 7;                   // 16B chunk
        cp_async16(sbase + (uint32_t)(r * GSTR * 4 + c * 16),
                   A + (size_t)(row0 + r) * K + kc * 32 + c * 4);
    }
    // B tile: 256 rows x 8 chunks = 2048 chunks
#pragma unroll
    for (int i = 0; i < 8; i++) {
        int q = i * 256 + tid;           // 0..2047
        int r = q >> 3;                  // 0..255
        int c = q & 7;
        cp_async16(sbase + (uint32_t)(128 * GSTR * 4) +
                   (uint32_t)(r * GSTR * 4 + c * 16),
                   W + (size_t)(col0 + r) * K + kc * 32 + c * 4);
    }
    CP_ASYNC_COMMIT();
}

__global__ __launch_bounds__(256) void tf32_gemm_nt_bias(
    const float* __restrict__ A, const float* __restrict__ W,
    const float* __restrict__ bias, float* __restrict__ C,
    int M, int N, int K)
{
    extern __shared__ __align__(16) float dsm[];

    int tid = threadIdx.x;
    int wid = tid >> 5;
    int lane = tid & 31;
    int gr = lane >> 2;      // 0..7
    int gc = lane & 3;       // 0..3
    int wm = wid & 1;        // warp m index 0..1 (64 rows each)
    int wn = wid >> 1;       // warp n index 0..3 (64 cols each)

    int bx = blockIdx.x, by = blockIdx.y;
    int row0 = by * 128, col0 = bx * 256;

    uint32_t sb_u32 = smem_to_u32(dsm);

    float acc[4][8][4];
#pragma unroll
    for (int i = 0; i < 4; i++)
#pragma unroll
        for (int j = 0; j < 8; j++)
#pragma unroll
            for (int k = 0; k < 4; k++) acc[i][j][k] = 0.f;

    const int NC = K >> 5;

    gemm_load_stage(A, W, row0, col0, K, 0, sb_u32 + 0 * GEMM_STAGE_BYTES, tid);
    gemm_load_stage(A, W, row0, col0, K, 1, sb_u32 + 1 * GEMM_STAGE_BYTES, tid);

    for (int j = 0; j < NC; j++) {
        if (j + 2 < NC) { CP_ASYNC_WAIT(1); } else { CP_ASYNC_WAIT(0); }
        __syncthreads();

        int s = j % 3;
        int jn = j + 2;
        if (jn < NC) {
            gemm_load_stage(A, W, row0, col0, K, jn,
                            sb_u32 + (jn % 3) * GEMM_STAGE_BYTES, tid);
        }

        const float* As = dsm + (size_t)s * GEMM_STAGE_FLOATS;
        const float* Bs = As + 128 * GSTR;

#pragma unroll
        for (int kst = 0; kst < 4; kst++) {
            int k0 = kst * 8;
            uint32_t af[4][4];
#pragma unroll
            for (int ma = 0; ma < 4; ma++) {
                int r = wm * 64 + ma * 16 + gr;
                af[ma][0] = __float_as_uint(As[r * GSTR + k0 + gc]);
                af[ma][1] = __float_as_uint(As[(r + 8) * GSTR + k0 + gc]);
                af[ma][2] = __float_as_uint(As[r * GSTR + k0 + gc + 4]);
                af[ma][3] = __float_as_uint(As[(r + 8) * GSTR + k0 + gc + 4]);
            }
            uint32_t bf[8][2];
#pragma unroll
            for (int na = 0; na < 8; na++) {
                int n = wn * 64 + na * 8 + gr;
                bf[na][0] = __float_as_uint(Bs[n * GSTR + k0 + gc]);
                bf[na][1] = __float_as_uint(Bs[n * GSTR + k0 + gc + 4]);
            }
#pragma unroll
            for (int ma = 0; ma < 4; ma++)
#pragma unroll
                for (int na = 0; na < 8; na++)
                    mma_tf32_16n8k8(acc[ma][na], af[ma], bf[na]);
        }
        __syncthreads();
    }

#pragma unroll
    for (int ma = 0; ma < 4; ma++) {
        int row = row0 + wm * 64 + ma * 16 + gr;
#pragma unroll
        for (int na = 0; na < 8; na++) {
            int col = col0 + wn * 64 + na * 8 + gc * 2;
            float2 bb = *(const float2*)(bias + col);
            float2 o0, o1;
            o0.x = acc[ma][na][0] + bb.x;
            o0.y = acc[ma][na][1] + bb.y;
            o1.x = acc[ma][na][2] + bb.x;
            o1.y = acc[ma][na][3] + bb.y;
            *(float2*)(C + (size_t)row * N + col) = o0;
            *(float2*)(C + (size_t)(row + 8) * N + col) = o1;
        }
    }
}

// ---------------------------------------------------------------------------
// RoPE + relayout + tf32 hi/lo pre-split.
// [B,S,D] -> [B,H,S,DK]: Qhi,Qlo,Khi,Klo (3xTF32 operands), Vr (tf32-rounded).
// ---------------------------------------------------------------------------
__global__ __launch_bounds__(256) void rope_relayout_kernel(
    const float* __restrict__ Qlin, const float* __restrict__ Klin,
    const float* __restrict__ Vlin,
    float* __restrict__ Qhi, float* __restrict__ Qlo,
    float* __restrict__ Khi, float* __restrict__ Klo,
    float* __restrict__ Vr)
{
    int idx = blockIdx.x * 256 + threadIdx.x;          // B*H*S*64
    if (idx >= B_ * H_ * S_ * 64) return;
    int i  = idx & 63;
    int s  = (idx >> 6) & (S_ - 1);
    int hb = idx >> 17;
    int h  = hb & (H_ - 1);
    int b  = hb >> 4;

    size_t lin = ((size_t)(b * S_ + s)) * D_ + h * DK_ + i;
    size_t out = ((size_t)hb * S_ + s) * DK_ + i;

    float inv = 1.0f / powf(10000.0f, (float)(2 * i) / 128.0f);
    float ang = (float)s * inv;
    float sn, cs;
    sincosf(ang, &sn, &cs);

    float q0 = Qlin[lin], q1 = Qlin[lin + 64];
    float qr0 = q0 * cs - q1 * sn;
    float qr1 = q1 * cs + q0 * sn;
    float hh;
    hh = tf32_round(qr0); Qhi[out]      = hh; Qlo[out]      = tf32_round(qr0 - hh);
    hh = tf32_round(qr1); Qhi[out + 64] = hh; Qlo[out + 64] = tf32_round(qr1 - hh);

    float k0 = Klin[lin], k1 = Klin[lin + 64];
    float kr0 = k0 * cs - k1 * sn;
    float kr1 = k1 * cs + k0 * sn;
    hh = tf32_round(kr0); Khi[out]      = hh; Klo[out]      = tf32_round(kr0 - hh);
    hh = tf32_round(kr1); Khi[out + 64] = hh; Klo[out + 64] = tf32_round(kr1 - hh);

    Vr[out]      = tf32_round(Vlin[lin]);
    Vr[out + 64] = tf32_round(Vlin[lin + 64]);
}

// ---------------------------------------------------------------------------
// Tensor-core flash attention (causal). BM=BN=64, DK=128, 256 threads (8 warps).
// Scores: 3xTF32, Q fragments held in REGISTERS across all kv tiles.
// PV: plain tf32. cp.async pipelined loads (V double-buffered, K prefetched).
// Output written directly to [B,S,D] layout, tf32-rounded.
// ---------------------------------------------------------------------------
#define AQSTR 132
#define AVSTR 136
#define ASSTR 68
// float offsets in dynamic smem
#define OQHI 0
#define OQLO (64 * AQSTR)                 // 8448
#define OKHI (2 * 64 * AQSTR)             // 16896
#define OKLO (3 * 64 * AQSTR)             // 25344
#define OV0  (4 * 64 * AQSTR)             // 33792
#define OV1  (OV0 + 64 * AVSTR)           // 42496
#define OSS  (OV1 + 64 * AVSTR)           // 51200
#define OMR  (OSS + 64 * ASSTR)           // 55552
#define OLR  (OMR + 64)
#define OAR  (OLR + 64)
#define ATT_FLOATS (OAR + 64)             // 55744
#define ATT_SMEM (ATT_FLOATS * 4)         // 222976 bytes

__global__ __launch_bounds__(256, 1) void attn_mma_kernel(
    const float* __restrict__ Qhi_g, const float* __restrict__ Qlo_g,
    const float* __restrict__ Khi_g, const float* __restrict__ Klo_g,
    const float* __restrict__ Vg, float* __restrict__ Olin)
{
    extern __shared__ __align__(16) float sm[];
    uint32_t sb = smem_to_u32(sm);

    int qt = (int)gridDim.x - 1 - (int)blockIdx.x;   // heavy tiles first
    int h = blockIdx.y, b = blockIdx.z;
    size_t base = ((size_t)(b * H_ + h)) * S_ * DK_;
    size_t qoff = base + (size_t)qt * 64 * DK_;

    int tid = threadIdx.x;
    int wid = tid >> 5;
    int lane = tid & 31;
    int gr = lane >> 2, gc = lane & 3;
    int wm = wid & 3, wn = wid >> 2;

    // Initial loads: Q hi/lo, K(0) hi/lo, V(0) — cp.async (2048 chunks/tile)
#pragma unroll
    for (int i = 0; i < 8; i++) {
        int q = i * 256 + tid;           // 0..2047
        int r = q >> 5, c = q & 31;
        size_t g = (size_t)r * DK_ + c * 4;
        uint32_t so132 = (uint32_t)(r * AQSTR + c * 4) * 4;
        uint32_t so136 = (uint32_t)(r * AVSTR + c * 4) * 4;
        cp_async16(sb + OQHI * 4 + so132, Qhi_g + qoff + g);
        cp_async16(sb + OQLO * 4 + so132, Qlo_g + qoff + g);
        cp_async16(sb + OKHI * 4 + so132, Khi_g + base + g);
        cp_async16(sb + OKLO * 4 + so132, Klo_g + base + g);
        cp_async16(sb + OV0 * 4 + so136, Vg + base + g);
    }
    CP_ASYNC_COMMIT();
    CP_ASYNC_WAIT(0);
    if (tid < 64) { sm[OMR + tid] = -1e30f; sm[OLR + tid] = 0.f; }
    __syncthreads();

    const float* Qhi = sm + OQHI;
    const float* Qlo = sm + OQLO;
    const float* Khi = sm + OKHI;
    const float* Klo = sm + OKLO;
    float* Ss = sm + OSS;

    int r0 = wm * 16 + gr;

    // Hoist ALL Q fragments (hi+lo, 16 ksteps) into registers — Q smem
    // traffic per kv-tile drops to zero.
    uint32_t qh[16][4], ql[16][4];
#pragma unroll
    for (int kst = 0; kst < 16; kst++) {
        int k0 = kst * 8;
        qh[kst][0] = __float_as_uint(Qhi[r0 * AQSTR + k0 + gc]);
        qh[kst][1] = __float_as_uint(Qhi[(r0 + 8) * AQSTR + k0 + gc]);
        qh[kst][2] = __float_as_uint(Qhi[r0 * AQSTR + k0 + gc + 4]);
        qh[kst][3] = __float_as_uint(Qhi[(r0 + 8) * AQSTR + k0 + gc + 4]);
        ql[kst][0] = __float_as_uint(Qlo[r0 * AQSTR + k0 + gc]);
        ql[kst][1] = __float_as_uint(Qlo[(r0 + 8) * AQSTR + k0 + gc]);
        ql[kst][2] = __float_as_uint(Qlo[r0 * AQSTR + k0 + gc + 4]);
        ql[kst][3] = __float_as_uint(Qlo[(r0 + 8) * AQSTR + k0 + gc + 4]);
    }

    float oacc[8][4];
#pragma unroll
    for (int i = 0; i < 8; i++)
#pragma unroll
        for (int j = 0; j < 4; j++) oacc[i][j] = 0.f;

    const float scale = 0.088388347648318440f;   // 1/sqrt(128)
    int nkt = qt + 1;

    for (int kt = 0; kt < nkt; kt++) {
        int vb = kt & 1;
        const float* Vs = sm + (vb ? OV1 : OV0);

        // Prefetch V(kt+1) into alternate buffer (fully overlapped)
        if (kt + 1 < nkt) {
            size_t vt = base + (size_t)(kt + 1) * 64 * DK_;
            uint32_t vdst = sb + (uint32_t)(vb ? OV0 : OV1) * 4;
#pragma unroll
            for (int i = 0; i < 8; i++) {
                int q = i * 256 + tid;
                int r = q >> 5, c = q & 31;
                cp_async16(vdst + (uint32_t)(r * AVSTR + c * 4) * 4,
                           Vg + vt + (size_t)r * DK_ + c * 4);
            }
            CP_ASYNC_COMMIT();
        }

        // Scores: warp tile 16x32 at (wm*16, wn*32); 3xTF32, Q from registers
        float sacc[4][4];
#pragma unroll
        for (int i = 0; i < 4; i++)
#pragma unroll
            for (int j = 0; j < 4; j++) sacc[i][j] = 0.f;

#pragma unroll
        for (int kst = 0; kst < 16; kst++) {
            int k0 = kst * 8;
#pragma unroll
            for (int na = 0; na < 4; na++) {
                int n = wn * 32 + na * 8 + gr;
                uint32_t bh[2], bl[2];
                bh[0] = __float_as_uint(Khi[n * AQSTR + k0 + gc]);
                bh[1] = __float_as_uint(Khi[n * AQSTR + k0 + gc + 4]);
                bl[0] = __float_as_uint(Klo[n * AQSTR + k0 + gc]);
                bl[1] = __float_as_uint(Klo[n * AQSTR + k0 + gc + 4]);
                mma_tf32_16n8k8(sacc[na], qh[kst], bl);
                mma_tf32_16n8k8(sacc[na], ql[kst], bh);
                mma_tf32_16n8k8(sacc[na], qh[kst], bh);
            }
        }

        // Scale + causal mask + store to Ss
        bool diag = (kt == qt);
#pragma unroll
        for (int na = 0; na < 4; na++) {
            int c = wn * 32 + na * 8 + 2 * gc;
            float s0 = sacc[na][0] * scale;
            float s1 = sacc[na][1] * scale;
            float s2 = sacc[na][2] * scale;
            float s3 = sacc[na][3] * scale;
            if (diag) {
                if (c > r0) s0 = -1e30f;
                if (c + 1 > r0) s1 = -1e30f;
                if (c > r0 + 8) s2 = -1e30f;
                if (c + 1 > r0 + 8) s3 = -1e30f;
            }
            Ss[r0 * ASSTR + c] = s0;
            Ss[r0 * ASSTR + c + 1] = s1;
            Ss[(r0 + 8) * ASSTR + c] = s2;
            Ss[(r0 + 8) * ASSTR + c + 1] = s3;
        }
        __syncthreads();

        // Prefetch K(kt+1) hi/lo — K smem is dead until next iteration's scores
        if (kt + 1 < nkt) {
            size_t ktb = base + (size_t)(kt + 1) * 64 * DK_;
#pragma unroll
            for (int i = 0; i < 8; i++) {
                int q = i * 256 + tid;
                int r = q >> 5, c = q & 31;
                size_t g = ktb + (size_t)r * DK_ + c * 4;
                uint32_t so = (uint32_t)(r * AQSTR + c * 4) * 4;
                cp_async16(sb + OKHI * 4 + so, Khi_g + g);
                cp_async16(sb + OKLO * 4 + so, Klo_g + g);
            }
            CP_ASYNC_COMMIT();
        }

        // Online softmax: 4 threads per row; P tf32-rounded at store
        {
            int r = tid >> 2, q4 = tid & 3;
            float rm = -1e30f;
#pragma unroll
            for (int c = 0; c < 64; c += 4) rm = fmaxf(rm, Ss[r * ASSTR + c + q4]);
            rm = fmaxf(rm, __shfl_xor_sync(0xffffffffu, rm, 1));
            rm = fmaxf(rm, __shfl_xor_sync(0xffffffffu, rm, 2));
            float mold = sm[OMR + r];
            float mnew = fmaxf(mold, rm);
            float sum = 0.f;
#pragma unroll
            for (int c = 0; c < 64; c += 4) {
                float p = tf32_round(__expf(Ss[r * ASSTR + c + q4] - mnew));
                Ss[r * ASSTR + c + q4] = p;
                sum += p;
            }
            sum += __shfl_xor_sync(0xffffffffu, sum, 1);
            sum += __shfl_xor_sync(0xffffffffu, sum, 2);
            if (q4 == 0) {
                float alpha = __expf(mold - mnew);
                sm[OAR + r] = alpha;
                sm[OMR + r] = mnew;
                sm[OLR + r] = sm[OLR + r] * alpha + sum;
            }
        }
        __syncthreads();

        // Rescale O accumulators
        float a0 = sm[OAR + r0], a1 = sm[OAR + r0 + 8];
#pragma unroll
        for (int na = 0; na < 8; na++) {
            oacc[na][0] *= a0; oacc[na][1] *= a0;
            oacc[na][2] *= a1; oacc[na][3] *= a1;
        }

        // PV: warp tile 16x64 at (wm*16, wn*64); plain tf32, K=64
#pragma unroll
        for (int kst = 0; kst < 8; kst++) {
            int k0 = kst * 8;
            uint32_t ap[4];
            ap[0] = __float_as_uint(Ss[r0 * ASSTR + k0 + gc]);
            ap[1] = __float_as_uint(Ss[(r0 + 8) * ASSTR + k0 + gc]);
            ap[2] = __float_as_uint(Ss[r0 * ASSTR + k0 + gc + 4]);
            ap[3] = __float_as_uint(Ss[(r0 + 8) * ASSTR + k0 + gc + 4]);
#pragma unroll
            for (int na = 0; na < 8; na++) {
                int n = wn * 64 + na * 8 + gr;
                uint32_t bv[2];
                bv[0] = __float_as_uint(Vs[(k0 + gc) * AVSTR + n]);
                bv[1] = __float_as_uint(Vs[(k0 + gc + 4) * AVSTR + n]);
                mma_tf32_16n8k8(oacc[na], ap, bv);
            }
        }

        // All prefetches (V and K hi/lo) must land before next iteration
        CP_ASYNC_WAIT(0);
        __syncthreads();
    }

    // Epilogue: normalize, round, write directly into [B,S,D] layout
    float li0 = 1.0f / sm[OLR + r0];
    float li1 = 1.0f / sm[OLR + r0 + 8];
    int srow0 = qt * 64 + r0;
    float* Og0 = Olin + ((size_t)b * S_ + srow0) * D_ + h * DK_;
    float* Og1 = Olin + ((size_t)b * S_ + srow0 + 8) * D_ + h * DK_;
#pragma unroll
    for (int na = 0; na < 8; na++) {
        int col = wn * 64 + na * 8 + 2 * gc;
        float2 o0, o1;
        o0.x = tf32_round(oacc[na][0] * li0);
        o0.y = tf32_round(oacc[na][1] * li0);
        o1.x = tf32_round(oacc[na][2] * li1);
        o1.y = tf32_round(oacc[na][3] * li1);
        *(float2*)(Og0 + col) = o0;
        *(float2*)(Og1 + col) = o1;
    }
}

// ---------------------------------------------------------------------------
extern "C" void kernel_launch(void* const* d_in, const int* in_sizes, int n_in,
                              void* d_out, int out_size)
{
    const float* x  = (const float*)d_in[0];
    const float* Wq = (const float*)d_in[2];
    const float* bq = (const float*)d_in[3];
    const float* Wk = (const float*)d_in[4];
    const float* bk = (const float*)d_in[5];
    const float* Wv = (const float*)d_in[6];
    const float* bv = (const float*)d_in[7];
    const float* Wo = (const float*)d_in[8];
    const float* bo = (const float*)d_in[9];
    float* out = (float*)d_out;

    float* base = nullptr;
    cudaGetSymbolAddress((void**)&base, g_scratch);
    float* xt = nullptr;
    cudaGetSymbolAddress((void**)&xt, g_xt);
    float* wt = nullptr;
    cudaGetSymbolAddress((void**)&wt, g_wt);

    float* Qlin = base;                 // plane 0 (later Olin)
    float* Klin = base + NBSD;          // plane 1
    float* Vlin = base + 2 * NBSD;      // plane 2
    float* Qhi  = base + 3 * NBSD;      // plane 3
    float* Qlo  = base + 4 * NBSD;      // plane 4
    float* Khi  = base + 5 * NBSD;      // plane 5
    float* Klo  = base + 6 * NBSD;      // plane 6
    float* Vr   = base + 7 * NBSD;      // plane 7
    float* Olin = Qlin;                 // dead after rope
    float* Wqt = wt;
    float* Wkt = wt + (size_t)D_ * D_;
    float* Wvt = wt + 2 * (size_t)D_ * D_;
    float* Wot = wt + 3 * (size_t)D_ * D_;

    const int M = B_ * S_, N = D_, K = D_;

    // tf32 rounding pre-pass
    {
        int nx4 = (int)(NBSD / 4);
        int nw4 = (int)(((size_t)D_ * D_) / 4);
        tf32_round_kernel<<<(nx4 + 255) / 256, 256>>>(x, xt, nx4);
        tf32_round_kernel<<<(nw4 + 255) / 256, 256>>>(Wq, Wqt, nw4);
        tf32_round_kernel<<<(nw4 + 255) / 256, 256>>>(Wk, Wkt, nw4);
        tf32_round_kernel<<<(nw4 + 255) / 256, 256>>>(Wv, Wvt, nw4);
        tf32_round_kernel<<<(nw4 + 255) / 256, 256>>>(Wo, Wot, nw4);
    }

    cudaFuncSetAttribute(tf32_gemm_nt_bias,
                         cudaFuncAttributeMaxDynamicSharedMemorySize, GEMM_SMEM);
    dim3 gg(N / 256, M / 128);   // (8, 32) = 256 CTAs

    tf32_gemm_nt_bias<<<gg, 256, GEMM_SMEM>>>(xt, Wqt, bq, Qlin, M, N, K);
    tf32_gemm_nt_bias<<<gg, 256, GEMM_SMEM>>>(xt, Wkt, bk, Klin, M, N, K);
    tf32_gemm_nt_bias<<<gg, 256, GEMM_SMEM>>>(xt, Wvt, bv, Vlin, M, N, K);

    int rope_total = B_ * H_ * S_ * 64;
    rope_relayout_kernel<<<rope_total / 256, 256>>>(Qlin, Klin, Vlin,
                                                    Qhi, Qlo, Khi, Klo, Vr);

    cudaFuncSetAttribute(attn_mma_kernel,
                         cudaFuncAttributeMaxDynamicSharedMemorySize, ATT_SMEM);
    attn_mma_kernel<<<dim3(S_ / 64, H_, B_), 256, ATT_SMEM>>>(
        Qhi, Qlo, Khi, Klo, Vr, Olin);

    tf32_gemm_nt_bias<<<gg, 256, GEMM_SMEM>>>(Olin, Wot, bo, out, M, N, K);
}

// round 8
// speedup vs baseline: 3.7907x; 1.1176x over previous
#include <cuda_runtime.h>
#include <cuda_fp16.h>
#include <math.h>
#include <cstdint>

// Problem constants
#define B_ 2
#define S_ 2048
#define D_ 2048
#define H_ 16
#define DK_ 128

static const size_t NBSD = (size_t)B_ * S_ * D_;
// fp32 planes: Qlin/Olin, Klin, Vlin, Vr
__device__ float g_scratch[4 * (size_t)B_ * S_ * D_];
// fp16 planes: Qh, Ql, Kh, Kl
__device__ __half g_h16[4 * (size_t)B_ * S_ * D_];
__device__ float g_xt[(size_t)B_ * S_ * D_];          // tf32-rounded x
__device__ float g_wt[4 * (size_t)D_ * D_];           // tf32-rounded Wq,Wk,Wv,Wo

// ============================================================================
// Helpers (arch-generic PTX only: cp.async + mma.sync, both sm_80+)
// ============================================================================
__device__ __forceinline__ uint32_t smem_to_u32(const void* smem_ptr) {
    uint32_t addr;
    asm("{ .reg .u64 tmp; cvta.to.shared.u64 tmp, %1; cvt.u32.u64 %0, tmp; }"
        : "=r"(addr) : "l"(smem_ptr));
    return addr;
}

__device__ __forceinline__ void cp_async16(uint32_t smem_addr, const void* gptr) {
    asm volatile("cp.async.cg.shared.global [%0], [%1], 16;"
                 :: "r"(smem_addr), "l"(gptr));
}
#define CP_ASYNC_COMMIT() asm volatile("cp.async.commit_group;" ::: "memory")
#define CP_ASYNC_WAIT(n)  asm volatile("cp.async.wait_group %0;" :: "n"(n) : "memory")

__device__ __forceinline__ void mma_tf32_16n8k8(float* d, const uint32_t* a,
                                                const uint32_t* b) {
    asm volatile(
        "mma.sync.aligned.m16n8k8.row.col.f32.tf32.tf32.f32 "
        "{%0,%1,%2,%3}, {%4,%5,%6,%7}, {%8,%9}, {%0,%1,%2,%3};"
        : "+f"(d[0]), "+f"(d[1]), "+f"(d[2]), "+f"(d[3])
        : "r"(a[0]), "r"(a[1]), "r"(a[2]), "r"(a[3]), "r"(b[0]), "r"(b[1]));
}

__device__ __forceinline__ void mma_f16_16n8k16(float* d, const uint32_t* a,
                                                const uint32_t* b) {
    asm volatile(
        "mma.sync.aligned.m16n8k16.row.col.f32.f16.f16.f32 "
        "{%0,%1,%2,%3}, {%4,%5,%6,%7}, {%8,%9}, {%0,%1,%2,%3};"
        : "+f"(d[0]), "+f"(d[1]), "+f"(d[2]), "+f"(d[3])
        : "r"(a[0]), "r"(a[1]), "r"(a[2]), "r"(a[3]), "r"(b[0]), "r"(b[1]));
}

__device__ __forceinline__ float tf32_round(float x) {
    uint32_t u;
    asm("cvt.rna.tf32.f32 %0, %1;" : "=r"(u) : "f"(x));
    return __uint_as_float(u);
}

// ============================================================================
// tf32 rounding pre-pass (elementwise, float4)
// ============================================================================
__global__ __launch_bounds__(256) void tf32_round_kernel(
    const float* __restrict__ in, float* __restrict__ out, int n4)
{
    int i = blockIdx.x * 256 + threadIdx.x;
    if (i >= n4) return;
    float4 v = ((const float4*)in)[i];
    v.x = tf32_round(v.x); v.y = tf32_round(v.y);
    v.z = tf32_round(v.z); v.w = tf32_round(v.w);
    ((float4*)out)[i] = v;
}

// ============================================================================
// mma.sync tf32 GEMM: C[M,N] = A[M,K] @ W[N,K]^T + bias[N]
// BM=128, BN=256, BK=32, 8 warps (2 M x 4 N), warp tile 64x64, m16n8k8.
// 3-stage cp.async pipeline. Smem stride 36 floats (conflict-free frags).
// ============================================================================
#define GSTR 36
#define GEMM_STAGE_FLOATS ((128 + 256) * GSTR)      // A tile + B tile = 13824
#define GEMM_STAGE_BYTES  (GEMM_STAGE_FLOATS * 4)   // 55296
#define GEMM_SMEM (3 * GEMM_STAGE_BYTES + 16)       // 165904

__device__ __forceinline__ void gemm_load_stage(
    const float* __restrict__ A, const float* __restrict__ W,
    int row0, int col0, int K, int kc, uint32_t sbase, int tid)
{
#pragma unroll
    for (int i = 0; i < 4; i++) {
        int q = i * 256 + tid;           // 0..1023
        int r = q >> 3;
        int c = q & 7;
        cp_async16(sbase + (uint32_t)(r * GSTR * 4 + c * 16),
                   A + (size_t)(row0 + r) * K + kc * 32 + c * 4);
    }
#pragma unroll
    for (int i = 0; i < 8; i++) {
        int q = i * 256 + tid;           // 0..2047
        int r = q >> 3;
        int c = q & 7;
        cp_async16(sbase + (uint32_t)(128 * GSTR * 4) +
                   (uint32_t)(r * GSTR * 4 + c * 16),
                   W + (size_t)(col0 + r) * K + kc * 32 + c * 4);
    }
    CP_ASYNC_COMMIT();
}

__global__ __launch_bounds__(256) void tf32_gemm_nt_bias(
    const float* __restrict__ A, const float* __restrict__ W,
    const float* __restrict__ bias, float* __restrict__ C,
    int M, int N, int K)
{
    extern __shared__ __align__(16) float dsm[];

    int tid = threadIdx.x;
    int wid = tid >> 5;
    int lane = tid & 31;
    int gr = lane >> 2;
    int gc = lane & 3;
    int wm = wid & 1;
    int wn = wid >> 1;

    int bx = blockIdx.x, by = blockIdx.y;
    int row0 = by * 128, col0 = bx * 256;

    uint32_t sb_u32 = smem_to_u32(dsm);

    float acc[4][8][4];
#pragma unroll
    for (int i = 0; i < 4; i++)
#pragma unroll
        for (int j = 0; j < 8; j++)
#pragma unroll
            for (int k = 0; k < 4; k++) acc[i][j][k] = 0.f;

    const int NC = K >> 5;

    gemm_load_stage(A, W, row0, col0, K, 0, sb_u32 + 0 * GEMM_STAGE_BYTES, tid);
    gemm_load_stage(A, W, row0, col0, K, 1, sb_u32 + 1 * GEMM_STAGE_BYTES, tid);

    for (int j = 0; j < NC; j++) {
        if (j + 2 < NC) { CP_ASYNC_WAIT(1); } else { CP_ASYNC_WAIT(0); }
        __syncthreads();

        int s = j % 3;
        int jn = j + 2;
        if (jn < NC) {
            gemm_load_stage(A, W, row0, col0, K, jn,
                            sb_u32 + (jn % 3) * GEMM_STAGE_BYTES, tid);
        }

        const float* As = dsm + (size_t)s * GEMM_STAGE_FLOATS;
        const float* Bs = As + 128 * GSTR;

#pragma unroll
        for (int kst = 0; kst < 4; kst++) {
            int k0 = kst * 8;
            uint32_t af[4][4];
#pragma unroll
            for (int ma = 0; ma < 4; ma++) {
                int r = wm * 64 + ma * 16 + gr;
                af[ma][0] = __float_as_uint(As[r * GSTR + k0 + gc]);
                af[ma][1] = __float_as_uint(As[(r + 8) * GSTR + k0 + gc]);
                af[ma][2] = __float_as_uint(As[r * GSTR + k0 + gc + 4]);
                af[ma][3] = __float_as_uint(As[(r + 8) * GSTR + k0 + gc + 4]);
            }
            uint32_t bf[8][2];
#pragma unroll
            for (int na = 0; na < 8; na++) {
                int n = wn * 64 + na * 8 + gr;
                bf[na][0] = __float_as_uint(Bs[n * GSTR + k0 + gc]);
                bf[na][1] = __float_as_uint(Bs[n * GSTR + k0 + gc + 4]);
            }
#pragma unroll
            for (int ma = 0; ma < 4; ma++)
#pragma unroll
                for (int na = 0; na < 8; na++)
                    mma_tf32_16n8k8(acc[ma][na], af[ma], bf[na]);
        }
        __syncthreads();
    }

#pragma unroll
    for (int ma = 0; ma < 4; ma++) {
        int row = row0 + wm * 64 + ma * 16 + gr;
#pragma unroll
        for (int na = 0; na < 8; na++) {
            int col = col0 + wn * 64 + na * 8 + gc * 2;
            float2 bb = *(const float2*)(bias + col);
            float2 o0, o1;
            o0.x = acc[ma][na][0] + bb.x;
            o0.y = acc[ma][na][1] + bb.y;
            o1.x = acc[ma][na][2] + bb.x;
            o1.y = acc[ma][na][3] + bb.y;
            *(float2*)(C + (size_t)row * N + col) = o0;
            *(float2*)(C + (size_t)(row + 8) * N + col) = o1;
        }
    }
}

// ---------------------------------------------------------------------------
// RoPE + relayout + fp16 hi/lo pre-split for Q,K; tf32-rounded V.
// [B,S,D] -> [B,H,S,DK] planes: Qh,Ql,Kh,Kl (fp16), Vr (fp32).
// ---------------------------------------------------------------------------
__global__ __launch_bounds__(256) void rope_relayout_kernel(
    const float* __restrict__ Qlin, const float* __restrict__ Klin,
    const float* __restrict__ Vlin,
    __half* __restrict__ Qh, __half* __restrict__ Ql,
    __half* __restrict__ Kh, __half* __restrict__ Kl,
    float* __restrict__ Vr)
{
    int idx = blockIdx.x * 256 + threadIdx.x;          // B*H*S*64
    if (idx >= B_ * H_ * S_ * 64) return;
    int i  = idx & 63;
    int s  = (idx >> 6) & (S_ - 1);
    int hb = idx >> 17;
    int h  = hb & (H_ - 1);
    int b  = hb >> 4;

    size_t lin = ((size_t)(b * S_ + s)) * D_ + h * DK_ + i;
    size_t out = ((size_t)hb * S_ + s) * DK_ + i;

    float inv = 1.0f / powf(10000.0f, (float)(2 * i) / 128.0f);
    float ang = (float)s * inv;
    float sn, cs;
    sincosf(ang, &sn, &cs);

    float q0 = Qlin[lin], q1 = Qlin[lin + 64];
    float qr0 = q0 * cs - q1 * sn;
    float qr1 = q1 * cs + q0 * sn;
    __half hh;
    hh = __float2half_rn(qr0);
    Qh[out] = hh;      Ql[out]      = __float2half_rn(qr0 - __half2float(hh));
    hh = __float2half_rn(qr1);
    Qh[out + 64] = hh; Ql[out + 64] = __float2half_rn(qr1 - __half2float(hh));

    float k0 = Klin[lin], k1 = Klin[lin + 64];
    float kr0 = k0 * cs - k1 * sn;
    float kr1 = k1 * cs + k0 * sn;
    hh = __float2half_rn(kr0);
    Kh[out] = hh;      Kl[out]      = __float2half_rn(kr0 - __half2float(hh));
    hh = __float2half_rn(kr1);
    Kh[out + 64] = hh; Kl[out + 64] = __float2half_rn(kr1 - __half2float(hh));

    Vr[out]      = tf32_round(Vlin[lin]);
    Vr[out + 64] = tf32_round(Vlin[lin + 64]);
}

// ---------------------------------------------------------------------------
// Tensor-core flash attention (causal). BM=BN=64, DK=128, 256 threads (8 warps).
// Scores: fp16 hi/lo 3-pass m16n8k16 (fp32-grade), Q frags in registers.
// PV: plain tf32. cp.async pipelined loads (V double-buffered, K prefetched).
// Output written directly to [B,S,D] layout, tf32-rounded.
// ---------------------------------------------------------------------------
#define AHSTR 136                        // fp16 row stride (halves)
#define AVSTR 136                        // fp32 V row stride (floats)
#define ASSTR 68
// float-granularity offsets in dynamic smem
#define OQH16 0                          // 64*136 halves = 4352 floats
#define OQL16 4352
#define OKH16 8704
#define OKL16 13056
#define OV0   17408                      // fp32, 64*136 = 8704 floats
#define OV1   26112
#define OSS   34816                      // fp32, 64*68 = 4352
#define OMR   39168
#define OLR   39232
#define OAR   39296
#define ATT_FLOATS 39360
#define ATT_SMEM (ATT_FLOATS * 4)        // 157440 bytes

__global__ __launch_bounds__(256, 1) void attn_mma_kernel(
    const __half* __restrict__ Qh_g, const __half* __restrict__ Ql_g,
    const __half* __restrict__ Kh_g, const __half* __restrict__ Kl_g,
    const float* __restrict__ Vg, float* __restrict__ Olin)
{
    extern __shared__ __align__(16) float sm[];
    uint32_t sb = smem_to_u32(sm);

    int qt = (int)gridDim.x - 1 - (int)blockIdx.x;   // heavy tiles first
    int h = blockIdx.y, b = blockIdx.z;
    size_t base = ((size_t)(b * H_ + h)) * S_ * DK_;
    size_t qoff = base + (size_t)qt * 64 * DK_;

    int tid = threadIdx.x;
    int wid = tid >> 5;
    int lane = tid & 31;
    int gr = lane >> 2, gc = lane & 3;
    int wm = wid & 3, wn = wid >> 2;

    // Initial loads: Q hi/lo + K(0) hi/lo (fp16: 1024 x 16B chunks each),
    // V(0) (fp32: 2048 chunks)
#pragma unroll
    for (int i = 0; i < 4; i++) {
        int q = i * 256 + tid;           // 0..1023
        int r = q >> 4, c = q & 15;      // row, 16B chunk (8 halves)
        size_t g = (size_t)r * DK_ + c * 8;
        uint32_t so = (uint32_t)(r * AHSTR * 2 + c * 16);
        cp_async16(sb + OQH16 * 4 + so, Qh_g + qoff + g);
        cp_async16(sb + OQL16 * 4 + so, Ql_g + qoff + g);
        cp_async16(sb + OKH16 * 4 + so, Kh_g + base + g);
        cp_async16(sb + OKL16 * 4 + so, Kl_g + base + g);
    }
#pragma unroll
    for (int i = 0; i < 8; i++) {
        int q = i * 256 + tid;           // 0..2047
        int r = q >> 5, c = q & 31;
        cp_async16(sb + OV0 * 4 + (uint32_t)(r * AVSTR + c * 4) * 4,
                   Vg + base + (size_t)r * DK_ + c * 4);
    }
    CP_ASYNC_COMMIT();
    CP_ASYNC_WAIT(0);
    if (tid < 64) { sm[OMR + tid] = -1e30f; sm[OLR + tid] = 0.f; }
    __syncthreads();

    const __half* Qh = (const __half*)(sm + OQH16);
    const __half* Ql = (const __half*)(sm + OQL16);
    const __half* Kh = (const __half*)(sm + OKH16);
    const __half* Kl = (const __half*)(sm + OKL16);
    float* Ss = sm + OSS;

    int r0 = wm * 16 + gr;

    // Hoist Q fragments (hi+lo) into registers: 8 ksteps x 4 regs x 2 planes.
    // m16n8k16 A-frag: a0={A[gr][2gc],+1} a1={A[gr+8][2gc],+1}
    //                  a2={A[gr][2gc+8],+1} a3={A[gr+8][2gc+8],+1}
    uint32_t qh[8][4], ql[8][4];
#pragma unroll
    for (int kst = 0; kst < 8; kst++) {
        int k0 = kst * 16;
        qh[kst][0] = *(const uint32_t*)&Qh[r0 * AHSTR + k0 + 2 * gc];
        qh[kst][1] = *(const uint32_t*)&Qh[(r0 + 8) * AHSTR + k0 + 2 * gc];
        qh[kst][2] = *(const uint32_t*)&Qh[r0 * AHSTR + k0 + 2 * gc + 8];
        qh[kst][3] = *(const uint32_t*)&Qh[(r0 + 8) * AHSTR + k0 + 2 * gc + 8];
        ql[kst][0] = *(const uint32_t*)&Ql[r0 * AHSTR + k0 + 2 * gc];
        ql[kst][1] = *(const uint32_t*)&Ql[(r0 + 8) * AHSTR + k0 + 2 * gc];
        ql[kst][2] = *(const uint32_t*)&Ql[r0 * AHSTR + k0 + 2 * gc + 8];
        ql[kst][3] = *(const uint32_t*)&Ql[(r0 + 8) * AHSTR + k0 + 2 * gc + 8];
    }

    float oacc[8][4];
#pragma unroll
    for (int i = 0; i < 8; i++)
#pragma unroll
        for (int j = 0; j < 4; j++) oacc[i][j] = 0.f;

    const float scale = 0.088388347648318440f;   // 1/sqrt(128)
    int nkt = qt + 1;

    for (int kt = 0; kt < nkt; kt++) {
        int vb = kt & 1;
        const float* Vs = sm + (vb ? OV1 : OV0);

        // Prefetch V(kt+1) into alternate buffer (fully overlapped)
        if (kt + 1 < nkt) {
            size_t vt = base + (size_t)(kt + 1) * 64 * DK_;
            uint32_t vdst = sb + (uint32_t)(vb ? OV0 : OV1) * 4;
#pragma unroll
            for (int i = 0; i < 8; i++) {
                int q = i * 256 + tid;
                int r = q >> 5, c = q & 31;
                cp_async16(vdst + (uint32_t)(r * AVSTR + c * 4) * 4,
                           Vg + vt + (size_t)r * DK_ + c * 4);
            }
            CP_ASYNC_COMMIT();
        }

        // Scores: warp tile 16x32 at (wm*16, wn*32); fp16 3-pass m16n8k16.
        // B-frag: b0={K[n][k0+2gc],+1}, b1={K[n][k0+2gc+8],+1}
        float sacc[4][4];
#pragma unroll
        for (int i = 0; i < 4; i++)
#pragma unroll
            for (int j = 0; j < 4; j++) sacc[i][j] = 0.f;

#pragma unroll
        for (int kst = 0; kst < 8; kst++) {
            int k0 = kst * 16;
#pragma unroll
            for (int na = 0; na < 4; na++) {
                int n = wn * 32 + na * 8 + gr;
                uint32_t bh[2], bl[2];
                bh[0] = *(const uint32_t*)&Kh[n * AHSTR + k0 + 2 * gc];
                bh[1] = *(const uint32_t*)&Kh[n * AHSTR + k0 + 2 * gc + 8];
                bl[0] = *(const uint32_t*)&Kl[n * AHSTR + k0 + 2 * gc];
                bl[1] = *(const uint32_t*)&Kl[n * AHSTR + k0 + 2 * gc + 8];
                mma_f16_16n8k16(sacc[na], qh[kst], bl);
                mma_f16_16n8k16(sacc[na], ql[kst], bh);
                mma_f16_16n8k16(sacc[na], qh[kst], bh);
            }
        }

        // Scale + causal mask + store to Ss (fp32)
        bool diag = (kt == qt);
#pragma unroll
        for (int na = 0; na < 4; na++) {
            int c = wn * 32 + na * 8 + 2 * gc;
            float s0 = sacc[na][0] * scale;
            float s1 = sacc[na][1] * scale;
            float s2 = sacc[na][2] * scale;
            float s3 = sacc[na][3] * scale;
            if (diag) {
                if (c > r0) s0 = -1e30f;
                if (c + 1 > r0) s1 = -1e30f;
                if (c > r0 + 8) s2 = -1e30f;
                if (c + 1 > r0 + 8) s3 = -1e30f;
            }
            Ss[r0 * ASSTR + c] = s0;
            Ss[r0 * ASSTR + c + 1] = s1;
            Ss[(r0 + 8) * ASSTR + c] = s2;
            Ss[(r0 + 8) * ASSTR + c + 1] = s3;
        }
        __syncthreads();

        // Prefetch K(kt+1) hi/lo — K smem dead until next iteration's scores
        if (kt + 1 < nkt) {
            size_t ktb = base + (size_t)(kt + 1) * 64 * DK_;
#pragma unroll
            for (int i = 0; i < 4; i++) {
                int q = i * 256 + tid;
                int r = q >> 4, c = q & 15;
                size_t g = ktb + (size_t)r * DK_ + c * 8;
                uint32_t so = (uint32_t)(r * AHSTR * 2 + c * 16);
                cp_async16(sb + OKH16 * 4 + so, Kh_g + g);
                cp_async16(sb + OKL16 * 4 + so, Kl_g + g);
            }
            CP_ASYNC_COMMIT();
        }

        // Online softmax: 4 threads per row; P tf32-rounded at store
        {
            int r = tid >> 2, q4 = tid & 3;
            float rm = -1e30f;
#pragma unroll
            for (int c = 0; c < 64; c += 4) rm = fmaxf(rm, Ss[r * ASSTR + c + q4]);
            rm = fmaxf(rm, __shfl_xor_sync(0xffffffffu, rm, 1));
            rm = fmaxf(rm, __shfl_xor_sync(0xffffffffu, rm, 2));
            float mold = sm[OMR + r];
            float mnew = fmaxf(mold, rm);
            float sum = 0.f;
#pragma unroll
            for (int c = 0; c < 64; c += 4) {
                float p = tf32_round(__expf(Ss[r * ASSTR + c + q4] - mnew));
                Ss[r * ASSTR + c + q4] = p;
                sum += p;
            }
            sum += __shfl_xor_sync(0xffffffffu, sum, 1);
            sum += __shfl_xor_sync(0xffffffffu, sum, 2);
            if (q4 == 0) {
                float alpha = __expf(mold - mnew);
                sm[OAR + r] = alpha;
                sm[OMR + r] = mnew;
                sm[OLR + r] = sm[OLR + r] * alpha + sum;
            }
        }
        __syncthreads();

        // Rescale O accumulators
        float a0 = sm[OAR + r0], a1 = sm[OAR + r0 + 8];
#pragma unroll
        for (int na = 0; na < 8; na++) {
            oacc[na][0] *= a0; oacc[na][1] *= a0;
            oacc[na][2] *= a1; oacc[na][3] *= a1;
        }

        // PV: warp tile 16x64 at (wm*16, wn*64); plain tf32 m16n8k8, K=64
#pragma unroll
        for (int kst = 0; kst < 8; kst++) {
            int k0 = kst * 8;
            uint32_t ap[4];
            ap[0] = __float_as_uint(Ss[r0 * ASSTR + k0 + gc]);
            ap[1] = __float_as_uint(Ss[(r0 + 8) * ASSTR + k0 + gc]);
            ap[2] = __float_as_uint(Ss[r0 * ASSTR + k0 + gc + 4]);
            ap[3] = __float_as_uint(Ss[(r0 + 8) * ASSTR + k0 + gc + 4]);
#pragma unroll
            for (int na = 0; na < 8; na++) {
                int n = wn * 64 + na * 8 + gr;
                uint32_t bv[2];
                bv[0] = __float_as_uint(Vs[(k0 + gc) * AVSTR + n]);
                bv[1] = __float_as_uint(Vs[(k0 + gc + 4) * AVSTR + n]);
                mma_tf32_16n8k8(oacc[na], ap, bv);
            }
        }

        // All prefetches (V and K hi/lo) must land before next iteration
        CP_ASYNC_WAIT(0);
        __syncthreads();
    }

    // Epilogue: normalize, round, write directly into [B,S,D] layout
    float li0 = 1.0f / sm[OLR + r0];
    float li1 = 1.0f / sm[OLR + r0 + 8];
    int srow0 = qt * 64 + r0;
    float* Og0 = Olin + ((size_t)b * S_ + srow0) * D_ + h * DK_;
    float* Og1 = Olin + ((size_t)b * S_ + srow0 + 8) * D_ + h * DK_;
#pragma unroll
    for (int na = 0; na < 8; na++) {
        int col = wn * 64 + na * 8 + 2 * gc;
        float2 o0, o1;
        o0.x = tf32_round(oacc[na][0] * li0);
        o0.y = tf32_round(oacc[na][1] * li0);
        o1.x = tf32_round(oacc[na][2] * li1);
        o1.y = tf32_round(oacc[na][3] * li1);
        *(float2*)(Og0 + col) = o0;
        *(float2*)(Og1 + col) = o1;
    }
}

// ---------------------------------------------------------------------------
extern "C" void kernel_launch(void* const* d_in, const int* in_sizes, int n_in,
                              void* d_out, int out_size)
{
    const float* x  = (const float*)d_in[0];
    const float* Wq = (const float*)d_in[2];
    const float* bq = (const float*)d_in[3];
    const float* Wk = (const float*)d_in[4];
    const float* bk = (const float*)d_in[5];
    const float* Wv = (const float*)d_in[6];
    const float* bv = (const float*)d_in[7];
    const float* Wo = (const float*)d_in[8];
    const float* bo = (const float*)d_in[9];
    float* out = (float*)d_out;

    float* base = nullptr;
    cudaGetSymbolAddress((void**)&base, g_scratch);
    __half* hbase = nullptr;
    cudaGetSymbolAddress((void**)&hbase, g_h16);
    float* xt = nullptr;
    cudaGetSymbolAddress((void**)&xt, g_xt);
    float* wt = nullptr;
    cudaGetSymbolAddress((void**)&wt, g_wt);

    float* Qlin = base;                 // plane 0 (later Olin)
    float* Klin = base + NBSD;          // plane 1
    float* Vlin = base + 2 * NBSD;      // plane 2
    float* Vr   = base + 3 * NBSD;      // plane 3
    __half* Qh16 = hbase;
    __half* Ql16 = hbase + NBSD;
    __half* Kh16 = hbase + 2 * NBSD;
    __half* Kl16 = hbase + 3 * NBSD;
    float* Olin = Qlin;                 // dead after rope
    float* Wqt = wt;
    float* Wkt = wt + (size_t)D_ * D_;
    float* Wvt = wt + 2 * (size_t)D_ * D_;
    float* Wot = wt + 3 * (size_t)D_ * D_;

    const int M = B_ * S_, N = D_, K = D_;

    // tf32 rounding pre-pass
    {
        int nx4 = (int)(NBSD / 4);
        int nw4 = (int)(((size_t)D_ * D_) / 4);
        tf32_round_kernel<<<(nx4 + 255) / 256, 256>>>(x, xt, nx4);
        tf32_round_kernel<<<(nw4 + 255) / 256, 256>>>(Wq, Wqt, nw4);
        tf32_round_kernel<<<(nw4 + 255) / 256, 256>>>(Wk, Wkt, nw4);
        tf32_round_kernel<<<(nw4 + 255) / 256, 256>>>(Wv, Wvt, nw4);
        tf32_round_kernel<<<(nw4 + 255) / 256, 256>>>(Wo, Wot, nw4);
    }

    cudaFuncSetAttribute(tf32_gemm_nt_bias,
                         cudaFuncAttributeMaxDynamicSharedMemorySize, GEMM_SMEM);
    dim3 gg(N / 256, M / 128);   // (8, 32) = 256 CTAs

    tf32_gemm_nt_bias<<<gg, 256, GEMM_SMEM>>>(xt, Wqt, bq, Qlin, M, N, K);
    tf32_gemm_nt_bias<<<gg, 256, GEMM_SMEM>>>(xt, Wkt, bk, Klin, M, N, K);
    tf32_gemm_nt_bias<<<gg, 256, GEMM_SMEM>>>(xt, Wvt, bv, Vlin, M, N, K);

    int rope_total = B_ * H_ * S_ * 64;
    rope_relayout_kernel<<<rope_total / 256, 256>>>(Qlin, Klin, Vlin,
                                                    Qh16, Ql16, Kh16, Kl16, Vr);

    cudaFuncSetAttribute(attn_mma_kernel,
                         cudaFuncAttributeMaxDynamicSharedMemorySize, ATT_SMEM);
    attn_mma_kernel<<<dim3(S_ / 64, H_, B_), 256, ATT_SMEM>>>(
        Qh16, Ql16, Kh16, Kl16, Vr, Olin);

    tf32_gemm_nt_bias<<<gg, 256, GEMM_SMEM>>>(Olin, Wot, bo, out, M, N, K);
}

// round 10
// speedup vs baseline: 3.9452x; 1.0408x over previous
#include <cuda_runtime.h>
#include <cuda_fp16.h>
#include <math.h>
#include <cstdint>
#include <cstring>

// Problem constants
#define B_ 2
#define S_ 2048
#define D_ 2048
#define H_ 16
#define DK_ 128

static const size_t NBSD = (size_t)B_ * S_ * D_;
// fp32 planes: Qlin/Olin, Klin, Vlin
__device__ float g_scratch[3 * (size_t)B_ * S_ * D_];
// fp16 planes: Qh, Ql, Kh, Kl
__device__ __half g_h16[4 * (size_t)B_ * S_ * D_];
// packed V: half2(V[2*s2][d], V[2*s2+1][d]) in [B,H,S/2,DK] u32 layout
__device__ uint32_t g_vp[(size_t)B_ * S_ * D_ / 2];
__device__ float g_xt[(size_t)B_ * S_ * D_];          // tf32-rounded x
__device__ float g_wt[4 * (size_t)D_ * D_];           // tf32-rounded Wq,Wk,Wv,Wo

// ============================================================================
// Helpers (arch-generic PTX only: cp.async + mma.sync, both sm_80+)
// ============================================================================
__device__ __forceinline__ uint32_t smem_to_u32(const void* smem_ptr) {
    uint32_t addr;
    asm("{ .reg .u64 tmp; cvta.to.shared.u64 tmp, %1; cvt.u32.u64 %0, tmp; }"
        : "=r"(addr) : "l"(smem_ptr));
    return addr;
}

__device__ __forceinline__ uint32_t h2_as_u32(__half2 h) {
    uint32_t u;
    memcpy(&u, &h, 4);
    return u;
}

__device__ __forceinline__ void cp_async16(uint32_t smem_addr, const void* gptr) {
    asm volatile("cp.async.cg.shared.global [%0], [%1], 16;"
                 :: "r"(smem_addr), "l"(gptr));
}
#define CP_ASYNC_COMMIT() asm volatile("cp.async.commit_group;" ::: "memory")
#define CP_ASYNC_WAIT(n)  asm volatile("cp.async.wait_group %0;" :: "n"(n) : "memory")

__device__ __forceinline__ void mma_tf32_16n8k8(float* d, const uint32_t* a,
                                                const uint32_t* b) {
    asm volatile(
        "mma.sync.aligned.m16n8k8.row.col.f32.tf32.tf32.f32 "
        "{%0,%1,%2,%3}, {%4,%5,%6,%7}, {%8,%9}, {%0,%1,%2,%3};"
        : "+f"(d[0]), "+f"(d[1]), "+f"(d[2]), "+f"(d[3])
        : "r"(a[0]), "r"(a[1]), "r"(a[2]), "r"(a[3]), "r"(b[0]), "r"(b[1]));
}

__device__ __forceinline__ void mma_f16_16n8k16(float* d, const uint32_t* a,
                                                const uint32_t* b) {
    asm volatile(
        "mma.sync.aligned.m16n8k16.row.col.f32.f16.f16.f32 "
        "{%0,%1,%2,%3}, {%4,%5,%6,%7}, {%8,%9}, {%0,%1,%2,%3};"
        : "+f"(d[0]), "+f"(d[1]), "+f"(d[2]), "+f"(d[3])
        : "r"(a[0]), "r"(a[1]), "r"(a[2]), "r"(a[3]), "r"(b[0]), "r"(b[1]));
}

__device__ __forceinline__ float tf32_round(float x) {
    uint32_t u;
    asm("cvt.rna.tf32.f32 %0, %1;" : "=r"(u) : "f"(x));
    return __uint_as_float(u);
}

// ============================================================================
// tf32 rounding pre-pass (elementwise, float4)
// ============================================================================
__global__ __launch_bounds__(256) void tf32_round_kernel(
    const float* __restrict__ in, float* __restrict__ out, int n4)
{
    int i = blockIdx.x * 256 + threadIdx.x;
    if (i >= n4) return;
    float4 v = ((const float4*)in)[i];
    v.x = tf32_round(v.x); v.y = tf32_round(v.y);
    v.z = tf32_round(v.z); v.w = tf32_round(v.w);
    ((float4*)out)[i] = v;
}

// ============================================================================
// mma.sync tf32 GEMM: C[M,N] = A[M,K] @ W[N,K]^T + bias[N]
// BM=128, BN=256, BK=32, 8 warps (2 M x 4 N), warp tile 64x64, m16n8k8.
// 3-stage cp.async pipeline. Smem stride 36 floats (conflict-free frags).
// ============================================================================
#define GSTR 36
#define GEMM_STAGE_FLOATS ((128 + 256) * GSTR)      // 13824
#define GEMM_STAGE_BYTES  (GEMM_STAGE_FLOATS * 4)   // 55296
#define GEMM_SMEM (3 * GEMM_STAGE_BYTES + 16)       // 165904

__device__ __forceinline__ void gemm_load_stage(
    const float* __restrict__ A, const float* __restrict__ W,
    int row0, int col0, int K, int kc, uint32_t sbase, int tid)
{
#pragma unroll
    for (int i = 0; i < 4; i++) {
        int q = i * 256 + tid;           // 0..1023
        int r = q >> 3;
        int c = q & 7;
        cp_async16(sbase + (uint32_t)(r * GSTR * 4 + c * 16),
                   A + (size_t)(row0 + r) * K + kc * 32 + c * 4);
    }
#pragma unroll
    for (int i = 0; i < 8; i++) {
        int q = i * 256 + tid;           // 0..2047
        int r = q >> 3;
        int c = q & 7;
        cp_async16(sbase + (uint32_t)(128 * GSTR * 4) +
                   (uint32_t)(r * GSTR * 4 + c * 16),
                   W + (size_t)(col0 + r) * K + kc * 32 + c * 4);
    }
    CP_ASYNC_COMMIT();
}

__global__ __launch_bounds__(256) void tf32_gemm_nt_bias(
    const float* __restrict__ A, const float* __restrict__ W,
    const float* __restrict__ bias, float* __restrict__ C,
    int M, int N, int K)
{
    extern __shared__ __align__(16) float dsm[];

    int tid = threadIdx.x;
    int wid = tid >> 5;
    int lane = tid & 31;
    int gr = lane >> 2;
    int gc = lane & 3;
    int wm = wid & 1;
    int wn = wid >> 1;

    int bx = blockIdx.x, by = blockIdx.y;
    int row0 = by * 128, col0 = bx * 256;

    uint32_t sb_u32 = smem_to_u32(dsm);

    float acc[4][8][4];
#pragma unroll
    for (int i = 0; i < 4; i++)
#pragma unroll
        for (int j = 0; j < 8; j++)
#pragma unroll
            for (int k = 0; k < 4; k++) acc[i][j][k] = 0.f;

    const int NC = K >> 5;

    gemm_load_stage(A, W, row0, col0, K, 0, sb_u32 + 0 * GEMM_STAGE_BYTES, tid);
    gemm_load_stage(A, W, row0, col0, K, 1, sb_u32 + 1 * GEMM_STAGE_BYTES, tid);

    for (int j = 0; j < NC; j++) {
        if (j + 2 < NC) { CP_ASYNC_WAIT(1); } else { CP_ASYNC_WAIT(0); }
        __syncthreads();

        int s = j % 3;
        int jn = j + 2;
        if (jn < NC) {
            gemm_load_stage(A, W, row0, col0, K, jn,
                            sb_u32 + (jn % 3) * GEMM_STAGE_BYTES, tid);
        }

        const float* As = dsm + (size_t)s * GEMM_STAGE_FLOATS;
        const float* Bs = As + 128 * GSTR;

#pragma unroll
        for (int kst = 0; kst < 4; kst++) {
            int k0 = kst * 8;
            uint32_t af[4][4];
#pragma unroll
            for (int ma = 0; ma < 4; ma++) {
                int r = wm * 64 + ma * 16 + gr;
                af[ma][0] = __float_as_uint(As[r * GSTR + k0 + gc]);
                af[ma][1] = __float_as_uint(As[(r + 8) * GSTR + k0 + gc]);
                af[ma][2] = __float_as_uint(As[r * GSTR + k0 + gc + 4]);
                af[ma][3] = __float_as_uint(As[(r + 8) * GSTR + k0 + gc + 4]);
            }
            uint32_t bf[8][2];
#pragma unroll
            for (int na = 0; na < 8; na++) {
                int n = wn * 64 + na * 8 + gr;
                bf[na][0] = __float_as_uint(Bs[n * GSTR + k0 + gc]);
                bf[na][1] = __float_as_uint(Bs[n * GSTR + k0 + gc + 4]);
            }
#pragma unroll
            for (int ma = 0; ma < 4; ma++)
#pragma unroll
                for (int na = 0; na < 8; na++)
                    mma_tf32_16n8k8(acc[ma][na], af[ma], bf[na]);
        }
        __syncthreads();
    }

#pragma unroll
    for (int ma = 0; ma < 4; ma++) {
        int row = row0 + wm * 64 + ma * 16 + gr;
#pragma unroll
        for (int na = 0; na < 8; na++) {
            int col = col0 + wn * 64 + na * 8 + gc * 2;
            float2 bb = *(const float2*)(bias + col);
            float2 o0, o1;
            o0.x = acc[ma][na][0] + bb.x;
            o0.y = acc[ma][na][1] + bb.y;
            o1.x = acc[ma][na][2] + bb.x;
            o1.y = acc[ma][na][3] + bb.y;
            *(float2*)(C + (size_t)row * N + col) = o0;
            *(float2*)(C + (size_t)(row + 8) * N + col) = o1;
        }
    }
}

// ---------------------------------------------------------------------------
// RoPE + relayout + fp16 hi/lo pre-split for Q,K (no V here).
// ---------------------------------------------------------------------------
__global__ __launch_bounds__(256) void rope_relayout_kernel(
    const float* __restrict__ Qlin, const float* __restrict__ Klin,
    __half* __restrict__ Qh, __half* __restrict__ Ql,
    __half* __restrict__ Kh, __half* __restrict__ Kl)
{
    int idx = blockIdx.x * 256 + threadIdx.x;          // B*H*S*64
    if (idx >= B_ * H_ * S_ * 64) return;
    int i  = idx & 63;
    int s  = (idx >> 6) & (S_ - 1);
    int hb = idx >> 17;
    int h  = hb & (H_ - 1);
    int b  = hb >> 4;

    size_t lin = ((size_t)(b * S_ + s)) * D_ + h * DK_ + i;
    size_t out = ((size_t)hb * S_ + s) * DK_ + i;

    float inv = 1.0f / powf(10000.0f, (float)(2 * i) / 128.0f);
    float ang = (float)s * inv;
    float sn, cs;
    sincosf(ang, &sn, &cs);

    float q0 = Qlin[lin], q1 = Qlin[lin + 64];
    float qr0 = q0 * cs - q1 * sn;
    float qr1 = q1 * cs + q0 * sn;
    __half hh;
    hh = __float2half_rn(qr0);
    Qh[out] = hh;      Ql[out]      = __float2half_rn(qr0 - __half2float(hh));
    hh = __float2half_rn(qr1);
    Qh[out + 64] = hh; Ql[out + 64] = __float2half_rn(qr1 - __half2float(hh));

    float k0 = Klin[lin], k1 = Klin[lin + 64];
    float kr0 = k0 * cs - k1 * sn;
    float kr1 = k1 * cs + k0 * sn;
    hh = __float2half_rn(kr0);
    Kh[out] = hh;      Kl[out]      = __float2half_rn(kr0 - __half2float(hh));
    hh = __float2half_rn(kr1);
    Kh[out + 64] = hh; Kl[out + 64] = __float2half_rn(kr1 - __half2float(hh));
}

// ---------------------------------------------------------------------------
// V pack: [B,S,D] fp32 -> [B,H,S/2,DK] u32 of half2(V[2s2][d], V[2s2+1][d]).
// ---------------------------------------------------------------------------
__global__ __launch_bounds__(256) void v_pack_kernel(
    const float* __restrict__ Vlin, uint32_t* __restrict__ Vp)
{
    int idx = blockIdx.x * 256 + threadIdx.x;   // B*H*(S/2)*(DK/4) = 1048576
    if (idx >= B_ * H_ * (S_ / 2) * (DK_ / 4)) return;
    int d4 = idx & 31;
    int s2 = (idx >> 5) & (S_ / 2 - 1);
    int hb = idx >> 15;
    int h = hb & (H_ - 1);
    int b = hb >> 4;

    const float* src0 = Vlin + ((size_t)(b * S_ + 2 * s2)) * D_ + h * DK_ + d4 * 4;
    float4 a = *(const float4*)src0;
    float4 c = *(const float4*)(src0 + D_);

    uint4 w;
    w.x = h2_as_u32(__floats2half2_rn(a.x, c.x));
    w.y = h2_as_u32(__floats2half2_rn(a.y, c.y));
    w.z = h2_as_u32(__floats2half2_rn(a.z, c.z));
    w.w = h2_as_u32(__floats2half2_rn(a.w, c.w));
    *(uint4*)(Vp + ((size_t)hb * (S_ / 2) + s2) * DK_ + d4 * 4) = w;
}

// ---------------------------------------------------------------------------
// Tensor-core flash attention (causal). BM=BN=64, DK=128, 256 threads.
// Scores: fp16 hi/lo 3-pass m16n8k16 (Q-hi frags in regs, Q-lo in smem).
// PV: fp16 m16n8k16 (P fp16 from softmax, V packed half2).
// 2 CTAs/SM target: smem 114.4KB, <=128 regs.
// ---------------------------------------------------------------------------
#define AHSTR 136                        // fp16 row stride (halves)
#define AVSTR 136                        // packed-V row stride (u32)
#define ASSTR 68                         // fp32 score stride
#define PSTR  72                         // fp16 P stride (halves)
// float-granularity offsets
#define OV0   0                          // V0 buf (4352 u32) — also Q-hi plane
#define OQL16 4352                       // Q-lo fp16 plane (4352 floats)
#define OKH16 8704
#define OKL16 13056
#define OV1   17408                      // V1 buf (4352 u32)
#define OSS   21760                      // fp32 scores 64*68 = 4352
#define OPS   26112                      // fp16 P 64*72 halves = 2304 floats
#define OMR   28416
#define OLR   28480
#define OAR   28544
#define ATT_FLOATS 28608
#define ATT_SMEM (ATT_FLOATS * 4)        // 114432 bytes

__global__ __launch_bounds__(256, 2) void attn_mma_kernel(
    const __half* __restrict__ Qh_g, const __half* __restrict__ Ql_g,
    const __half* __restrict__ Kh_g, const __half* __restrict__ Kl_g,
    const uint32_t* __restrict__ Vp_g, float* __restrict__ Olin)
{
    extern __shared__ __align__(16) float sm[];
    uint32_t sb = smem_to_u32(sm);

    int qt = (int)gridDim.x - 1 - (int)blockIdx.x;   // heavy tiles first
    int h = blockIdx.y, b = blockIdx.z;
    int hb = b * H_ + h;
    size_t base = (size_t)hb * S_ * DK_;
    size_t qoff = base + (size_t)qt * 64 * DK_;
    size_t vbase = (size_t)hb * (S_ / 2) * DK_;      // u32 units

    int tid = threadIdx.x;
    int wid = tid >> 5;
    int lane = tid & 31;
    int gr = lane >> 2, gc = lane & 3;
    int wm = wid & 3, wn = wid >> 2;

    // Load Q hi/lo + K(0) hi/lo (fp16: 1024 x 16B chunks per plane).
    // Q-hi goes into the OV0 region (reused as V buffer after hoist).
#pragma unroll
    for (int i = 0; i < 4; i++) {
        int q = i * 256 + tid;           // 0..1023
        int r = q >> 4, c = q & 15;      // row, 16B chunk (8 halves)
        size_t g = (size_t)r * DK_ + c * 8;
        uint32_t so = (uint32_t)(r * AHSTR * 2 + c * 16);
        cp_async16(sb + OV0 * 4 + so, Qh_g + qoff + g);
        cp_async16(sb + OQL16 * 4 + so, Ql_g + qoff + g);
        cp_async16(sb + OKH16 * 4 + so, Kh_g + base + g);
        cp_async16(sb + OKL16 * 4 + so, Kl_g + base + g);
    }
    CP_ASYNC_COMMIT();
    CP_ASYNC_WAIT(0);
    __syncthreads();

    const __half* Qhp = (const __half*)(sm + OV0);
    const __half* Qlp = (const __half*)(sm + OQL16);
    const __half* Khp = (const __half*)(sm + OKH16);
    const __half* Klp = (const __half*)(sm + OKL16);
    float* Ss = sm + OSS;
    __half* Ps = (__half*)(sm + OPS);

    int r0 = wm * 16 + gr;

    // Hoist Q-hi fragments into registers (32 regs); Q-lo stays in smem.
    uint32_t qh[8][4];
#pragma unroll
    for (int kst = 0; kst < 8; kst++) {
        int k0 = kst * 16;
        qh[kst][0] = *(const uint32_t*)&Qhp[r0 * AHSTR + k0 + 2 * gc];
        qh[kst][1] = *(const uint32_t*)&Qhp[(r0 + 8) * AHSTR + k0 + 2 * gc];
        qh[kst][2] = *(const uint32_t*)&Qhp[r0 * AHSTR + k0 + 2 * gc + 8];
        qh[kst][3] = *(const uint32_t*)&Qhp[(r0 + 8) * AHSTR + k0 + 2 * gc + 8];
    }
    __syncthreads();   // all warps done reading Q-hi; OV0 region now free

    // Load V(0) into OV0 (1024 x 16B chunks of packed u32)
#pragma unroll
    for (int i = 0; i < 4; i++) {
        int q = i * 256 + tid;           // 0..1023
        int r = q >> 5, c = q & 31;      // 32 rows x 32 chunks
        cp_async16(sb + OV0 * 4 + (uint32_t)(r * AVSTR + c * 4) * 4,
                   Vp_g + vbase + (size_t)r * DK_ + c * 4);
    }
    CP_ASYNC_COMMIT();
    CP_ASYNC_WAIT(0);
    if (tid < 64) { sm[OMR + tid] = -1e30f; sm[OLR + tid] = 0.f; }
    __syncthreads();

    float oacc[8][4];
#pragma unroll
    for (int i = 0; i < 8; i++)
#pragma unroll
        for (int j = 0; j < 4; j++) oacc[i][j] = 0.f;

    const float scale = 0.088388347648318440f;   // 1/sqrt(128)
    int nkt = qt + 1;

    for (int kt = 0; kt < nkt; kt++) {
        int vb = kt & 1;
        const uint32_t* Vs = (const uint32_t*)(sm + (vb ? OV1 : OV0));

        // Prefetch V(kt+1) into alternate buffer
        if (kt + 1 < nkt) {
            size_t vt = vbase + (size_t)(kt + 1) * 32 * DK_;
            uint32_t vdst = sb + (uint32_t)(vb ? OV0 : OV1) * 4;
#pragma unroll
            for (int i = 0; i < 4; i++) {
                int q = i * 256 + tid;
                int r = q >> 5, c = q & 31;
                cp_async16(vdst + (uint32_t)(r * AVSTR + c * 4) * 4,
                           Vp_g + vt + (size_t)r * DK_ + c * 4);
            }
            CP_ASYNC_COMMIT();
        }

        // Scores: warp tile 16x32 at (wm*16, wn*32); fp16 3-pass m16n8k16
        float sacc[4][4];
#pragma unroll
        for (int i = 0; i < 4; i++)
#pragma unroll
            for (int j = 0; j < 4; j++) sacc[i][j] = 0.f;

#pragma unroll
        for (int kst = 0; kst < 8; kst++) {
            int k0 = kst * 16;
            uint32_t ql[4];
            ql[0] = *(const uint32_t*)&Qlp[r0 * AHSTR + k0 + 2 * gc];
            ql[1] = *(const uint32_t*)&Qlp[(r0 + 8) * AHSTR + k0 + 2 * gc];
            ql[2] = *(const uint32_t*)&Qlp[r0 * AHSTR + k0 + 2 * gc + 8];
            ql[3] = *(const uint32_t*)&Qlp[(r0 + 8) * AHSTR + k0 + 2 * gc + 8];
#pragma unroll
            for (int na = 0; na < 4; na++) {
                int n = wn * 32 + na * 8 + gr;
                uint32_t bh[2], bl[2];
                bh[0] = *(const uint32_t*)&Khp[n * AHSTR + k0 + 2 * gc];
                bh[1] = *(const uint32_t*)&Khp[n * AHSTR + k0 + 2 * gc + 8];
                bl[0] = *(const uint32_t*)&Klp[n * AHSTR + k0 + 2 * gc];
                bl[1] = *(const uint32_t*)&Klp[n * AHSTR + k0 + 2 * gc + 8];
                mma_f16_16n8k16(sacc[na], qh[kst], bl);
                mma_f16_16n8k16(sacc[na], ql, bh);
                mma_f16_16n8k16(sacc[na], qh[kst], bh);
            }
        }

        // Scale + causal mask + store to Ss (fp32)
        bool diag = (kt == qt);
#pragma unroll
        for (int na = 0; na < 4; na++) {
            int c = wn * 32 + na * 8 + 2 * gc;
            float s0 = sacc[na][0] * scale;
            float s1 = sacc[na][1] * scale;
            float s2 = sacc[na][2] * scale;
            float s3 = sacc[na][3] * scale;
            if (diag) {
                if (c > r0) s0 = -1e30f;
                if (c + 1 > r0) s1 = -1e30f;
                if (c > r0 + 8) s2 = -1e30f;
                if (c + 1 > r0 + 8) s3 = -1e30f;
            }
            Ss[r0 * ASSTR + c] = s0;
            Ss[r0 * ASSTR + c + 1] = s1;
            Ss[(r0 + 8) * ASSTR + c] = s2;
            Ss[(r0 + 8) * ASSTR + c + 1] = s3;
        }
        __syncthreads();

        // Prefetch K(kt+1) hi/lo
        if (kt + 1 < nkt) {
            size_t ktb = base + (size_t)(kt + 1) * 64 * DK_;
#pragma unroll
            for (int i = 0; i < 4; i++) {
                int q = i * 256 + tid;
                int r = q >> 4, c = q & 15;
                size_t g = ktb + (size_t)r * DK_ + c * 8;
                uint32_t so = (uint32_t)(r * AHSTR * 2 + c * 16);
                cp_async16(sb + OKH16 * 4 + so, Kh_g + g);
                cp_async16(sb + OKL16 * 4 + so, Kl_g + g);
            }
            CP_ASYNC_COMMIT();
        }

        // Online softmax: 4 threads per row; P written fp16 to Ps
        {
            int r = tid >> 2, q4 = tid & 3;
            float rm = -1e30f;
#pragma unroll
            for (int c = 0; c < 64; c += 4) rm = fmaxf(rm, Ss[r * ASSTR + c + q4]);
            rm = fmaxf(rm, __shfl_xor_sync(0xffffffffu, rm, 1));
            rm = fmaxf(rm, __shfl_xor_sync(0xffffffffu, rm, 2));
            float mold = sm[OMR + r];
            float mnew = fmaxf(mold, rm);
            float sum = 0.f;
#pragma unroll
            for (int c = 0; c < 64; c += 4) {
                float p = __expf(Ss[r * ASSTR + c + q4] - mnew);
                __half ph = __float2half_rn(p);
                Ps[r * PSTR + c + q4] = ph;
                sum += __half2float(ph);
            }
            sum += __shfl_xor_sync(0xffffffffu, sum, 1);
            sum += __shfl_xor_sync(0xffffffffu, sum, 2);
            if (q4 == 0) {
                float alpha = __expf(mold - mnew);
                sm[OAR + r] = alpha;
                sm[OMR + r] = mnew;
                sm[OLR + r] = sm[OLR + r] * alpha + sum;
            }
        }
        __syncthreads();

        // Rescale O accumulators
        float a0 = sm[OAR + r0], a1 = sm[OAR + r0 + 8];
#pragma unroll
        for (int na = 0; na < 8; na++) {
            oacc[na][0] *= a0; oacc[na][1] *= a0;
            oacc[na][2] *= a1; oacc[na][3] *= a1;
        }

        // PV: warp tile 16x64 at (wm*16, wn*64); fp16 m16n8k16, K=64 (4 ksteps)
#pragma unroll
        for (int kst = 0; kst < 4; kst++) {
            int k0 = kst * 16;
            uint32_t ap[4];
            ap[0] = *(const uint32_t*)&Ps[r0 * PSTR + k0 + 2 * gc];
            ap[1] = *(const uint32_t*)&Ps[(r0 + 8) * PSTR + k0 + 2 * gc];
            ap[2] = *(const uint32_t*)&Ps[r0 * PSTR + k0 + 2 * gc + 8];
            ap[3] = *(const uint32_t*)&Ps[(r0 + 8) * PSTR + k0 + 2 * gc + 8];
#pragma unroll
            for (int na = 0; na < 8; na++) {
                int n = wn * 64 + na * 8 + gr;
                uint32_t bv[2];
                bv[0] = Vs[(kst * 8 + gc) * AVSTR + n];
                bv[1] = Vs[(kst * 8 + gc + 4) * AVSTR + n];
                mma_f16_16n8k16(oacc[na], ap, bv);
            }
        }

        // All prefetches must land before next iteration
        CP_ASYNC_WAIT(0);
        __syncthreads();
    }

    // Epilogue: normalize, round, write directly into [B,S,D] layout
    float li0 = 1.0f / sm[OLR + r0];
    float li1 = 1.0f / sm[OLR + r0 + 8];
    int srow0 = qt * 64 + r0;
    float* Og0 = Olin + ((size_t)b * S_ + srow0) * D_ + h * DK_;
    float* Og1 = Olin + ((size_t)b * S_ + srow0 + 8) * D_ + h * DK_;
#pragma unroll
    for (int na = 0; na < 8; na++) {
        int col = wn * 64 + na * 8 + 2 * gc;
        float2 o0, o1;
        o0.x = tf32_round(oacc[na][0] * li0);
        o0.y = tf32_round(oacc[na][1] * li0);
        o1.x = tf32_round(oacc[na][2] * li1);
        o1.y = tf32_round(oacc[na][3] * li1);
        *(float2*)(Og0 + col) = o0;
        *(float2*)(Og1 + col) = o1;
    }
}

// ---------------------------------------------------------------------------
extern "C" void kernel_launch(void* const* d_in, const int* in_sizes, int n_in,
                              void* d_out, int out_size)
{
    const float* x  = (const float*)d_in[0];
    const float* Wq = (const float*)d_in[2];
    const float* bq = (const float*)d_in[3];
    const float* Wk = (const float*)d_in[4];
    const float* bk = (const float*)d_in[5];
    const float* Wv = (const float*)d_in[6];
    const float* bv = (const float*)d_in[7];
    const float* Wo = (const float*)d_in[8];
    const float* bo = (const float*)d_in[9];
    float* out = (float*)d_out;

    float* base = nullptr;
    cudaGetSymbolAddress((void**)&base, g_scratch);
    __half* hbase = nullptr;
    cudaGetSymbolAddress((void**)&hbase, g_h16);
    uint32_t* vp = nullptr;
    cudaGetSymbolAddress((void**)&vp, g_vp);
    float* xt = nullptr;
    cudaGetSymbolAddress((void**)&xt, g_xt);
    float* wt = nullptr;
    cudaGetSymbolAddress((void**)&wt, g_wt);

    float* Qlin = base;                 // plane 0 (later Olin)
    float* Klin = base + NBSD;          // plane 1
    float* Vlin = base + 2 * NBSD;      // plane 2
    __half* Qh16 = hbase;
    __half* Ql16 = hbase + NBSD;
    __half* Kh16 = hbase + 2 * NBSD;
    __half* Kl16 = hbase + 3 * NBSD;
    float* Olin = Qlin;                 // dead after rope
    float* Wqt = wt;
    float* Wkt = wt + (size_t)D_ * D_;
    float* Wvt = wt + 2 * (size_t)D_ * D_;
    float* Wot = wt + 3 * (size_t)D_ * D_;

    const int M = B_ * S_, N = D_, K = D_;

    // tf32 rounding pre-pass
    {
        int nx4 = (int)(NBSD / 4);
        int nw4 = (int)(((size_t)D_ * D_) / 4);
        tf32_round_kernel<<<(nx4 + 255) / 256, 256>>>(x, xt, nx4);
        tf32_round_kernel<<<(nw4 + 255) / 256, 256>>>(Wq, Wqt, nw4);
        tf32_round_kernel<<<(nw4 + 255) / 256, 256>>>(Wk, Wkt, nw4);
        tf32_round_kernel<<<(nw4 + 255) / 256, 256>>>(Wv, Wvt, nw4);
        tf32_round_kernel<<<(nw4 + 255) / 256, 256>>>(Wo, Wot, nw4);
    }

    cudaFuncSetAttribute(tf32_gemm_nt_bias,
                         cudaFuncAttributeMaxDynamicSharedMemorySize, GEMM_SMEM);
    dim3 gg(N / 256, M / 128);   // (8, 32) = 256 CTAs

    tf32_gemm_nt_bias<<<gg, 256, GEMM_SMEM>>>(xt, Wqt, bq, Qlin, M, N, K);
    tf32_gemm_nt_bias<<<gg, 256, GEMM_SMEM>>>(xt, Wkt, bk, Klin, M, N, K);
    tf32_gemm_nt_bias<<<gg, 256, GEMM_SMEM>>>(xt, Wvt, bv, Vlin, M, N, K);

    int rope_total = B_ * H_ * S_ * 64;
    rope_relayout_kernel<<<rope_total / 256, 256>>>(Qlin, Klin,
                                                    Qh16, Ql16, Kh16, Kl16);
    int vp_total = B_ * H_ * (S_ / 2) * (DK_ / 4);
    v_pack_kernel<<<vp_total / 256, 256>>>(Vlin, vp);

    cudaFuncSetAttribute(attn_mma_kernel,
                         cudaFuncAttributeMaxDynamicSharedMemorySize, ATT_SMEM);
    attn_mma_kernel<<<dim3(S_ / 64, H_, B_), 256, ATT_SMEM>>>(
        Qh16, Ql16, Kh16, Kl16, vp, Olin);

    tf32_gemm_nt_bias<<<gg, 256, GEMM_SMEM>>>(Olin, Wot, bo, out, M, N, K);
}

// round 11
// speedup vs baseline: 4.0950x; 1.0380x over previous
#include <cuda_runtime.h>
#include <cuda_fp16.h>
#include <math.h>
#include <cstdint>
#include <cstring>

// Problem constants
#define B_ 2
#define S_ 2048
#define D_ 2048
#define H_ 16
#define DK_ 128

static const size_t NBSD = (size_t)B_ * S_ * D_;
// fp32 planes: Qlin/Olin, Klin, Vlin
__device__ float g_scratch[3 * (size_t)B_ * S_ * D_];
// fp16 planes: Qh, Ql, Kh, Kl
__device__ __half g_h16[4 * (size_t)B_ * S_ * D_];
// packed V: half2(V[2*s2][d], V[2*s2+1][d]) in [B,H,S/2,DK] u32 layout
__device__ uint32_t g_vp[(size_t)B_ * S_ * D_ / 2];
__device__ float g_xt[(size_t)B_ * S_ * D_];          // tf32-rounded x
__device__ float g_wt[4 * (size_t)D_ * D_];           // tf32-rounded Wq,Wk,Wv,Wo
__device__ float g_bias[3 * D_];                      // concat bq,bk,bv

// ============================================================================
// Helpers (arch-generic PTX only: cp.async + mma.sync, both sm_80+)
// ============================================================================
__device__ __forceinline__ uint32_t smem_to_u32(const void* smem_ptr) {
    uint32_t addr;
    asm("{ .reg .u64 tmp; cvta.to.shared.u64 tmp, %1; cvt.u32.u64 %0, tmp; }"
        : "=r"(addr) : "l"(smem_ptr));
    return addr;
}

__device__ __forceinline__ uint32_t h2_as_u32(__half2 h) {
    uint32_t u;
    memcpy(&u, &h, 4);
    return u;
}

__device__ __forceinline__ void cp_async16(uint32_t smem_addr, const void* gptr) {
    asm volatile("cp.async.cg.shared.global [%0], [%1], 16;"
                 :: "r"(smem_addr), "l"(gptr));
}
#define CP_ASYNC_COMMIT() asm volatile("cp.async.commit_group;" ::: "memory")
#define CP_ASYNC_WAIT(n)  asm volatile("cp.async.wait_group %0;" :: "n"(n) : "memory")

__device__ __forceinline__ void mma_tf32_16n8k8(float* d, const uint32_t* a,
                                                const uint32_t* b) {
    asm volatile(
        "mma.sync.aligned.m16n8k8.row.col.f32.tf32.tf32.f32 "
        "{%0,%1,%2,%3}, {%4,%5,%6,%7}, {%8,%9}, {%0,%1,%2,%3};"
        : "+f"(d[0]), "+f"(d[1]), "+f"(d[2]), "+f"(d[3])
        : "r"(a[0]), "r"(a[1]), "r"(a[2]), "r"(a[3]), "r"(b[0]), "r"(b[1]));
}

__device__ __forceinline__ void mma_f16_16n8k16(float* d, const uint32_t* a,
                                                const uint32_t* b) {
    asm volatile(
        "mma.sync.aligned.m16n8k16.row.col.f32.f16.f16.f32 "
        "{%0,%1,%2,%3}, {%4,%5,%6,%7}, {%8,%9}, {%0,%1,%2,%3};"
        : "+f"(d[0]), "+f"(d[1]), "+f"(d[2]), "+f"(d[3])
        : "r"(a[0]), "r"(a[1]), "r"(a[2]), "r"(a[3]), "r"(b[0]), "r"(b[1]));
}

__device__ __forceinline__ float tf32_round(float x) {
    uint32_t u;
    asm("cvt.rna.tf32.f32 %0, %1;" : "=r"(u) : "f"(x));
    return __uint_as_float(u);
}

// ============================================================================
// tf32 rounding pre-pass (elementwise, float4)
// ============================================================================
__global__ __launch_bounds__(256) void tf32_round_kernel(
    const float* __restrict__ in, float* __restrict__ out, int n4)
{
    int i = blockIdx.x * 256 + threadIdx.x;
    if (i >= n4) return;
    float4 v = ((const float4*)in)[i];
    v.x = tf32_round(v.x); v.y = tf32_round(v.y);
    v.z = tf32_round(v.z); v.w = tf32_round(v.w);
    ((float4*)out)[i] = v;
}

// ============================================================================
// mma.sync tf32 GEMM: C = A @ W^T + bias. BM=128, BN=256, BK=32, 8 warps.
// Output columns routed to planes of stride plane_stride (for fused QKV);
// row stride fixed at D_=2048. plane = col >> 11.
// ============================================================================
#define GSTR 36
#define GEMM_STAGE_FLOATS ((128 + 256) * GSTR)      // 13824
#define GEMM_STAGE_BYTES  (GEMM_STAGE_FLOATS * 4)   // 55296
#define GEMM_SMEM (3 * GEMM_STAGE_BYTES + 16)       // 165904

__device__ __forceinline__ void gemm_load_stage(
    const float* __restrict__ A, const float* __restrict__ W,
    int row0, int col0, int K, int kc, uint32_t sbase, int tid)
{
#pragma unroll
    for (int i = 0; i < 4; i++) {
        int q = i * 256 + tid;           // 0..1023
        int r = q >> 3;
        int c = q & 7;
        cp_async16(sbase + (uint32_t)(r * GSTR * 4 + c * 16),
                   A + (size_t)(row0 + r) * K + kc * 32 + c * 4);
    }
#pragma unroll
    for (int i = 0; i < 8; i++) {
        int q = i * 256 + tid;           // 0..2047
        int r = q >> 3;
        int c = q & 7;
        cp_async16(sbase + (uint32_t)(128 * GSTR * 4) +
                   (uint32_t)(r * GSTR * 4 + c * 16),
                   W + (size_t)(col0 + r) * K + kc * 32 + c * 4);
    }
    CP_ASYNC_COMMIT();
}

__global__ __launch_bounds__(256) void tf32_gemm_nt_bias(
    const float* __restrict__ A, const float* __restrict__ W,
    const float* __restrict__ bias, float* __restrict__ C,
    int M, int K, size_t plane_stride)
{
    extern __shared__ __align__(16) float dsm[];

    int tid = threadIdx.x;
    int wid = tid >> 5;
    int lane = tid & 31;
    int gr = lane >> 2;
    int gc = lane & 3;
    int wm = wid & 1;
    int wn = wid >> 1;

    int bx = blockIdx.x, by = blockIdx.y;
    int row0 = by * 128, col0 = bx * 256;

    uint32_t sb_u32 = smem_to_u32(dsm);

    float acc[4][8][4];
#pragma unroll
    for (int i = 0; i < 4; i++)
#pragma unroll
        for (int j = 0; j < 8; j++)
#pragma unroll
            for (int k = 0; k < 4; k++) acc[i][j][k] = 0.f;

    const int NC = K >> 5;

    gemm_load_stage(A, W, row0, col0, K, 0, sb_u32 + 0 * GEMM_STAGE_BYTES, tid);
    gemm_load_stage(A, W, row0, col0, K, 1, sb_u32 + 1 * GEMM_STAGE_BYTES, tid);

    for (int j = 0; j < NC; j++) {
        if (j + 2 < NC) { CP_ASYNC_WAIT(1); } else { CP_ASYNC_WAIT(0); }
        __syncthreads();

        int s = j % 3;
        int jn = j + 2;
        if (jn < NC) {
            gemm_load_stage(A, W, row0, col0, K, jn,
                            sb_u32 + (jn % 3) * GEMM_STAGE_BYTES, tid);
        }

        const float* As = dsm + (size_t)s * GEMM_STAGE_FLOATS;
        const float* Bs = As + 128 * GSTR;

#pragma unroll
        for (int kst = 0; kst < 4; kst++) {
            int k0 = kst * 8;
            uint32_t af[4][4];
#pragma unroll
            for (int ma = 0; ma < 4; ma++) {
                int r = wm * 64 + ma * 16 + gr;
                af[ma][0] = __float_as_uint(As[r * GSTR + k0 + gc]);
                af[ma][1] = __float_as_uint(As[(r + 8) * GSTR + k0 + gc]);
                af[ma][2] = __float_as_uint(As[r * GSTR + k0 + gc + 4]);
                af[ma][3] = __float_as_uint(As[(r + 8) * GSTR + k0 + gc + 4]);
            }
            uint32_t bf[8][2];
#pragma unroll
            for (int na = 0; na < 8; na++) {
                int n = wn * 64 + na * 8 + gr;
                bf[na][0] = __float_as_uint(Bs[n * GSTR + k0 + gc]);
                bf[na][1] = __float_as_uint(Bs[n * GSTR + k0 + gc + 4]);
            }
#pragma unroll
            for (int ma = 0; ma < 4; ma++)
#pragma unroll
                for (int na = 0; na < 8; na++)
                    mma_tf32_16n8k8(acc[ma][na], af[ma], bf[na]);
        }
        __syncthreads();
    }

    // Epilogue: plane routing (col>>11), row stride 2048
    float* Cp = C + (size_t)(col0 >> 11) * plane_stride;
    int colp0 = col0 & 2047;
#pragma unroll
    for (int ma = 0; ma < 4; ma++) {
        int row = row0 + wm * 64 + ma * 16 + gr;
#pragma unroll
        for (int na = 0; na < 8; na++) {
            int colf = col0 + wn * 64 + na * 8 + gc * 2;   // bias index
            int colp = colp0 + wn * 64 + na * 8 + gc * 2;  // in-plane col
            float2 bb = *(const float2*)(bias + colf);
            float2 o0, o1;
            o0.x = acc[ma][na][0] + bb.x;
            o0.y = acc[ma][na][1] + bb.y;
            o1.x = acc[ma][na][2] + bb.x;
            o1.y = acc[ma][na][3] + bb.y;
            *(float2*)(Cp + (size_t)row * D_ + colp) = o0;
            *(float2*)(Cp + (size_t)(row + 8) * D_ + colp) = o1;
        }
    }
}

// ---------------------------------------------------------------------------
// RoPE + relayout + fp16 hi/lo pre-split for Q,K.
// ---------------------------------------------------------------------------
__global__ __launch_bounds__(256) void rope_relayout_kernel(
    const float* __restrict__ Qlin, const float* __restrict__ Klin,
    __half* __restrict__ Qh, __half* __restrict__ Ql,
    __half* __restrict__ Kh, __half* __restrict__ Kl)
{
    int idx = blockIdx.x * 256 + threadIdx.x;          // B*H*S*64
    if (idx >= B_ * H_ * S_ * 64) return;
    int i  = idx & 63;
    int s  = (idx >> 6) & (S_ - 1);
    int hb = idx >> 17;
    int h  = hb & (H_ - 1);
    int b  = hb >> 4;

    size_t lin = ((size_t)(b * S_ + s)) * D_ + h * DK_ + i;
    size_t out = ((size_t)hb * S_ + s) * DK_ + i;

    float inv = 1.0f / powf(10000.0f, (float)(2 * i) / 128.0f);
    float ang = (float)s * inv;
    float sn, cs;
    sincosf(ang, &sn, &cs);

    float q0 = Qlin[lin], q1 = Qlin[lin + 64];
    float qr0 = q0 * cs - q1 * sn;
    float qr1 = q1 * cs + q0 * sn;
    __half hh;
    hh = __float2half_rn(qr0);
    Qh[out] = hh;      Ql[out]      = __float2half_rn(qr0 - __half2float(hh));
    hh = __float2half_rn(qr1);
    Qh[out + 64] = hh; Ql[out + 64] = __float2half_rn(qr1 - __half2float(hh));

    float k0 = Klin[lin], k1 = Klin[lin + 64];
    float kr0 = k0 * cs - k1 * sn;
    float kr1 = k1 * cs + k0 * sn;
    hh = __float2half_rn(kr0);
    Kh[out] = hh;      Kl[out]      = __float2half_rn(kr0 - __half2float(hh));
    hh = __float2half_rn(kr1);
    Kh[out + 64] = hh; Kl[out + 64] = __float2half_rn(kr1 - __half2float(hh));
}

// ---------------------------------------------------------------------------
// V pack: [B,S,D] fp32 -> [B,H,S/2,DK] u32 of half2(V[2s2][d], V[2s2+1][d]).
// ---------------------------------------------------------------------------
__global__ __launch_bounds__(256) void v_pack_kernel(
    const float* __restrict__ Vlin, uint32_t* __restrict__ Vp)
{
    int idx = blockIdx.x * 256 + threadIdx.x;
    if (idx >= B_ * H_ * (S_ / 2) * (DK_ / 4)) return;
    int d4 = idx & 31;
    int s2 = (idx >> 5) & (S_ / 2 - 1);
    int hb = idx >> 15;
    int h = hb & (H_ - 1);
    int b = hb >> 4;

    const float* src0 = Vlin + ((size_t)(b * S_ + 2 * s2)) * D_ + h * DK_ + d4 * 4;
    float4 a = *(const float4*)src0;
    float4 c = *(const float4*)(src0 + D_);

    uint4 w;
    w.x = h2_as_u32(__floats2half2_rn(a.x, c.x));
    w.y = h2_as_u32(__floats2half2_rn(a.y, c.y));
    w.z = h2_as_u32(__floats2half2_rn(a.z, c.z));
    w.w = h2_as_u32(__floats2half2_rn(a.w, c.w));
    *(uint4*)(Vp + ((size_t)hb * (S_ / 2) + s2) * DK_ + d4 * 4) = w;
}

// ---------------------------------------------------------------------------
// Tensor-core flash attention (causal), warp-autonomous softmax (FA2 style).
// BM=128, BN=64, 8 warps; each warp owns 16 q-rows (full kv width).
// Scores: fp16 hi/lo 3-pass m16n8k16 (Q-hi in regs, Q-lo in smem).
// Softmax fully in registers (shuffle over quad lanes); P packed in-register
// to fp16 A-frags (no smem S/P round trip). PV: fp16 m16n8k16.
// 3-stage cp.async K/V ring, ONE block barrier per kv-tile.
// ---------------------------------------------------------------------------
#define AHSTR 136                        // fp16 K/Q row stride (halves)
#define AVSTR 136                        // packed-V row stride (u32)
#define STG_F 13056                      // stage: KH 4352 + KL 4352 + V 4352 floats
#define OQL   (3 * STG_F)                // Q-lo plane: 128*136 halves = 8704 floats
#define ATT_FLOATS (OQL + 8704)          // 47872
#define ATT_SMEM (ATT_FLOATS * 4)        // 191488 bytes

__global__ __launch_bounds__(256, 1) void attn_mma_kernel(
    const __half* __restrict__ Qh_g, const __half* __restrict__ Ql_g,
    const __half* __restrict__ Kh_g, const __half* __restrict__ Kl_g,
    const uint32_t* __restrict__ Vp_g, float* __restrict__ Olin)
{
    extern __shared__ __align__(16) float sm[];
    uint32_t sb = smem_to_u32(sm);

    int qt = (int)gridDim.x - 1 - (int)blockIdx.x;   // heavy tiles first
    int h = blockIdx.y, b = blockIdx.z;
    int hb = b * H_ + h;
    size_t base = (size_t)hb * S_ * DK_;
    size_t qoff = base + (size_t)qt * 128 * DK_;
    size_t vbase = (size_t)hb * (S_ / 2) * DK_;      // u32 units

    int tid = threadIdx.x;
    int wid = tid >> 5;
    int lane = tid & 31;
    int gr = lane >> 2, gc = lane & 3;

    int r0 = wid * 16 + gr;          // local q-row (0..127)
    int rbase = qt * 128;

    // ---- Stage Q-hi (into stage-0 area) + Q-lo (OQL): 128 rows x 128 halves
#pragma unroll
    for (int i = 0; i < 8; i++) {
        int q = i * 256 + tid;       // 0..2047
        int r = q >> 4, c = q & 15;
        size_t g = (size_t)r * DK_ + c * 8;
        uint32_t so = (uint32_t)(r * AHSTR * 2 + c * 16);
        cp_async16(sb + so, Qh_g + qoff + g);
        cp_async16(sb + OQL * 4 + so, Ql_g + qoff + g);
    }
    CP_ASYNC_COMMIT();
    CP_ASYNC_WAIT(0);
    __syncthreads();

    uint32_t qh[8][4];
    {
        const __half* Qhp = (const __half*)sm;
#pragma unroll
        for (int kst = 0; kst < 8; kst++) {
            int k0 = kst * 16;
            qh[kst][0] = *(const uint32_t*)&Qhp[r0 * AHSTR + k0 + 2 * gc];
            qh[kst][1] = *(const uint32_t*)&Qhp[(r0 + 8) * AHSTR + k0 + 2 * gc];
            qh[kst][2] = *(const uint32_t*)&Qhp[r0 * AHSTR + k0 + 2 * gc + 8];
            qh[kst][3] = *(const uint32_t*)&Qhp[(r0 + 8) * AHSTR + k0 + 2 * gc + 8];
        }
    }
    __syncthreads();   // stage-0 area free for K/V ring

    const __half* Qlp = (const __half*)(sm + OQL);

    int nkt = 2 * qt + 2;

    // ---- K/V group loader: K(hi,lo) 64 rows + V 32 packed rows into stage s
    auto load_group = [&](int j, int s) {
        size_t kb = base + (size_t)j * 64 * DK_;
        size_t vt = vbase + (size_t)j * 32 * DK_;
        uint32_t kh_dst = sb + (uint32_t)(s * STG_F) * 4;
        uint32_t kl_dst = kh_dst + 4352 * 4;
        uint32_t v_dst  = kh_dst + 8704 * 4;
#pragma unroll
        for (int i = 0; i < 4; i++) {
            int q = i * 256 + tid;   // 0..1023
            int r = q >> 4, c = q & 15;
            size_t g = kb + (size_t)r * DK_ + c * 8;
            uint32_t so = (uint32_t)(r * AHSTR * 2 + c * 16);
            cp_async16(kh_dst + so, Kh_g + g);
            cp_async16(kl_dst + so, Kl_g + g);
        }
#pragma unroll
        for (int i = 0; i < 4; i++) {
            int q = i * 256 + tid;   // 0..1023
            int r = q >> 5, c = q & 31;
            cp_async16(v_dst + (uint32_t)(r * AVSTR + c * 4) * 4,
                       Vp_g + vt + (size_t)r * DK_ + c * 4);
        }
        CP_ASYNC_COMMIT();
    };

    load_group(0, 0);
    if (nkt > 1) load_group(1, 1);

    float oacc[16][4];
#pragma unroll
    for (int i = 0; i < 16; i++)
#pragma unroll
        for (int j = 0; j < 4; j++) oacc[i][j] = 0.f;

    float m0 = -1e30f, m1 = -1e30f, l0 = 0.f, l1 = 0.f;
    const float scale = 0.088388347648318440f;   // 1/sqrt(128)

    for (int j = 0; j < nkt; j++) {
        if (j + 1 < nkt) { CP_ASYNC_WAIT(1); } else { CP_ASYNC_WAIT(0); }
        __syncthreads();   // group j visible; all warps done with stage (j+2)%3

        if (j + 2 < nkt) load_group(j + 2, (j + 2) % 3);

        int s = j % 3;
        const __half* Khp = (const __half*)(sm + s * STG_F);
        const __half* Klp = Khp + 4352 * 2;
        const uint32_t* Vs = (const uint32_t*)(sm + s * STG_F + 8704);

        // Scores: warp tile 16x64, 8 n-atoms, fp16 3-pass
        float sacc[8][4];
#pragma unroll
        for (int i = 0; i < 8; i++)
#pragma unroll
            for (int k = 0; k < 4; k++) sacc[i][k] = 0.f;

#pragma unroll
        for (int kst = 0; kst < 8; kst++) {
            int k0 = kst * 16;
            uint32_t ql[4];
            ql[0] = *(const uint32_t*)&Qlp[r0 * AHSTR + k0 + 2 * gc];
            ql[1] = *(const uint32_t*)&Qlp[(r0 + 8) * AHSTR + k0 + 2 * gc];
            ql[2] = *(const uint32_t*)&Qlp[r0 * AHSTR + k0 + 2 * gc + 8];
            ql[3] = *(const uint32_t*)&Qlp[(r0 + 8) * AHSTR + k0 + 2 * gc + 8];
#pragma unroll
            for (int na = 0; na < 8; na++) {
                int n = na * 8 + gr;
                uint32_t bh[2], bl[2];
                bh[0] = *(const uint32_t*)&Khp[n * AHSTR + k0 + 2 * gc];
                bh[1] = *(const uint32_t*)&Khp[n * AHSTR + k0 + 2 * gc + 8];
                bl[0] = *(const uint32_t*)&Klp[n * AHSTR + k0 + 2 * gc];
                bl[1] = *(const uint32_t*)&Klp[n * AHSTR + k0 + 2 * gc + 8];
                mma_f16_16n8k16(sacc[na], qh[kst], bl);
                mma_f16_16n8k16(sacc[na], ql, bh);
                mma_f16_16n8k16(sacc[na], qh[kst], bh);
            }
        }

        // Scale + causal mask (registers only)
        bool diag = (j >= 2 * qt);
        int rg0 = rbase + r0, rg1 = rg0 + 8;
#pragma unroll
        for (int na = 0; na < 8; na++) {
            float s0 = sacc[na][0] * scale;
            float s1 = sacc[na][1] * scale;
            float s2 = sacc[na][2] * scale;
            float s3 = sacc[na][3] * scale;
            if (diag) {
                int cg = j * 64 + na * 8 + 2 * gc;
                if (cg > rg0) s0 = -1e30f;
                if (cg + 1 > rg0) s1 = -1e30f;
                if (cg > rg1) s2 = -1e30f;
                if (cg + 1 > rg1) s3 = -1e30f;
            }
            sacc[na][0] = s0; sacc[na][1] = s1;
            sacc[na][2] = s2; sacc[na][3] = s3;
        }

        // Warp-local online softmax (reduce over quad lanes gc=0..3)
        float rm0 = -1e30f, rm1 = -1e30f;
#pragma unroll
        for (int na = 0; na < 8; na++) {
            rm0 = fmaxf(rm0, fmaxf(sacc[na][0], sacc[na][1]));
            rm1 = fmaxf(rm1, fmaxf(sacc[na][2], sacc[na][3]));
        }
        rm0 = fmaxf(rm0, __shfl_xor_sync(0xffffffffu, rm0, 1));
        rm0 = fmaxf(rm0, __shfl_xor_sync(0xffffffffu, rm0, 2));
        rm1 = fmaxf(rm1, __shfl_xor_sync(0xffffffffu, rm1, 1));
        rm1 = fmaxf(rm1, __shfl_xor_sync(0xffffffffu, rm1, 2));

        float mn0 = fmaxf(m0, rm0), mn1 = fmaxf(m1, rm1);
        float a0 = __expf(m0 - mn0), a1 = __expf(m1 - mn1);
        m0 = mn0; m1 = mn1;

        uint32_t ap[4][4];
        float sum0 = 0.f, sum1 = 0.f;
#pragma unroll
        for (int kst = 0; kst < 4; kst++) {
            int e = 2 * kst, o = 2 * kst + 1;
            __half2 h00 = __floats2half2_rn(__expf(sacc[e][0] - mn0),
                                            __expf(sacc[e][1] - mn0));
            __half2 h01 = __floats2half2_rn(__expf(sacc[e][2] - mn1),
                                            __expf(sacc[e][3] - mn1));
            __half2 h10 = __floats2half2_rn(__expf(sacc[o][0] - mn0),
                                            __expf(sacc[o][1] - mn0));
            __half2 h11 = __floats2half2_rn(__expf(sacc[o][2] - mn1),
                                            __expf(sacc[o][3] - mn1));
            ap[kst][0] = h2_as_u32(h00);
            ap[kst][1] = h2_as_u32(h01);
            ap[kst][2] = h2_as_u32(h10);
            ap[kst][3] = h2_as_u32(h11);
            float2 f;
            f = __half22float2(h00); sum0 += f.x + f.y;
            f = __half22float2(h10); sum0 += f.x + f.y;
            f = __half22float2(h01); sum1 += f.x + f.y;
            f = __half22float2(h11); sum1 += f.x + f.y;
        }
        sum0 += __shfl_xor_sync(0xffffffffu, sum0, 1);
        sum0 += __shfl_xor_sync(0xffffffffu, sum0, 2);
        sum1 += __shfl_xor_sync(0xffffffffu, sum1, 1);
        sum1 += __shfl_xor_sync(0xffffffffu, sum1, 2);
        l0 = l0 * a0 + sum0;
        l1 = l1 * a1 + sum1;

        // Rescale O accumulators
#pragma unroll
        for (int na = 0; na < 16; na++) {
            oacc[na][0] *= a0; oacc[na][1] *= a0;
            oacc[na][2] *= a1; oacc[na][3] *= a1;
        }

        // PV: warp tile 16x128, fp16 m16n8k16, K=64 (4 ksteps), 16 n-atoms
#pragma unroll
        for (int kst = 0; kst < 4; kst++) {
#pragma unroll
            for (int na = 0; na < 16; na++) {
                int n = na * 8 + gr;
                uint32_t bv[2];
                bv[0] = Vs[(kst * 8 + gc) * AVSTR + n];
                bv[1] = Vs[(kst * 8 + gc + 4) * AVSTR + n];
                mma_f16_16n8k16(oacc[na], ap[kst], bv);
            }
        }
    }

    // Epilogue: normalize, round, write directly into [B,S,D] layout
    float li0 = 1.0f / l0;
    float li1 = 1.0f / l1;
    int srow0 = rbase + r0;
    float* Og0 = Olin + ((size_t)b * S_ + srow0) * D_ + h * DK_;
    float* Og1 = Olin + ((size_t)b * S_ + srow0 + 8) * D_ + h * DK_;
#pragma unroll
    for (int na = 0; na < 16; na++) {
        int col = na * 8 + 2 * gc;
        float2 o0, o1;
        o0.x = tf32_round(oacc[na][0] * li0);
        o0.y = tf32_round(oacc[na][1] * li0);
        o1.x = tf32_round(oacc[na][2] * li1);
        o1.y = tf32_round(oacc[na][3] * li1);
        *(float2*)(Og0 + col) = o0;
        *(float2*)(Og1 + col) = o1;
    }
}

// ---------------------------------------------------------------------------
extern "C" void kernel_launch(void* const* d_in, const int* in_sizes, int n_in,
                              void* d_out, int out_size)
{
    const float* x  = (const float*)d_in[0];
    const float* Wq = (const float*)d_in[2];
    const float* bq = (const float*)d_in[3];
    const float* Wk = (const float*)d_in[4];
    const float* bk = (const float*)d_in[5];
    const float* Wv = (const float*)d_in[6];
    const float* bv = (const float*)d_in[7];
    const float* Wo = (const float*)d_in[8];
    const float* bo = (const float*)d_in[9];
    float* out = (float*)d_out;

    float* base = nullptr;
    cudaGetSymbolAddress((void**)&base, g_scratch);
    __half* hbase = nullptr;
    cudaGetSymbolAddress((void**)&hbase, g_h16);
    uint32_t* vp = nullptr;
    cudaGetSymbolAddress((void**)&vp, g_vp);
    float* xt = nullptr;
    cudaGetSymbolAddress((void**)&xt, g_xt);
    float* wt = nullptr;
    cudaGetSymbolAddress((void**)&wt, g_wt);
    float* biasqkv = nullptr;
    cudaGetSymbolAddress((void**)&biasqkv, g_bias);

    float* Qlin = base;                 // plane 0 (later Olin)
    float* Klin = base + NBSD;          // plane 1
    float* Vlin = base + 2 * NBSD;      // plane 2
    __half* Qh16 = hbase;
    __half* Ql16 = hbase + NBSD;
    __half* Kh16 = hbase + 2 * NBSD;
    __half* Kl16 = hbase + 3 * NBSD;
    float* Olin = Qlin;                 // dead after rope
    float* Wot = wt + 3 * (size_t)D_ * D_;

    const int M = B_ * S_, K = D_;

    // Concatenate QKV biases (async D2D, graph-capturable)
    cudaMemcpyAsync(biasqkv,            bq, D_ * 4, cudaMemcpyDeviceToDevice);
    cudaMemcpyAsync(biasqkv + D_,       bk, D_ * 4, cudaMemcpyDeviceToDevice);
    cudaMemcpyAsync(biasqkv + 2 * D_,   bv, D_ * 4, cudaMemcpyDeviceToDevice);

    // tf32 rounding pre-pass (wt holds Wq,Wk,Wv,Wo contiguously)
    {
        int nx4 = (int)(NBSD / 4);
        int nw4 = (int)(((size_t)D_ * D_) / 4);
        tf32_round_kernel<<<(nx4 + 255) / 256, 256>>>(x, xt, nx4);
        tf32_round_kernel<<<(nw4 + 255) / 256, 256>>>(Wq, wt, nw4);
        tf32_round_kernel<<<(nw4 + 255) / 256, 256>>>(Wk, wt + (size_t)D_ * D_, nw4);
        tf32_round_kernel<<<(nw4 + 255) / 256, 256>>>(Wv, wt + 2 * (size_t)D_ * D_, nw4);
        tf32_round_kernel<<<(nw4 + 255) / 256, 256>>>(Wo, Wot, nw4);
    }

    cudaFuncSetAttribute(tf32_gemm_nt_bias,
                         cudaFuncAttributeMaxDynamicSharedMemorySize, GEMM_SMEM);

    // Fused QKV projection: N=6144, columns routed to Qlin/Klin/Vlin planes
    tf32_gemm_nt_bias<<<dim3(3 * D_ / 256, M / 128), 256, GEMM_SMEM>>>(
        xt, wt, biasqkv, Qlin, M, K, NBSD);

    int rope_total = B_ * H_ * S_ * 64;
    rope_relayout_kernel<<<rope_total / 256, 256>>>(Qlin, Klin,
                                                    Qh16, Ql16, Kh16, Kl16);
    int vp_total = B_ * H_ * (S_ / 2) * (DK_ / 4);
    v_pack_kernel<<<vp_total / 256, 256>>>(Vlin, vp);

    cudaFuncSetAttribute(attn_mma_kernel,
                         cudaFuncAttributeMaxDynamicSharedMemorySize, ATT_SMEM);
    attn_mma_kernel<<<dim3(S_ / 128, H_, B_), 256, ATT_SMEM>>>(
        Qh16, Ql16, Kh16, Kl16, vp, Olin);

    // Output projection: N=2048, plane_stride unused (cols < 2048)
    tf32_gemm_nt_bias<<<dim3(D_ / 256, M / 128), 256, GEMM_SMEM>>>(
        Olin, Wot, bo, out, M, K, 0);
}

// round 12
// speedup vs baseline: 4.0980x; 1.0007x over previous
#include <cuda_runtime.h>
#include <cuda_fp16.h>
#include <math.h>
#include <cstdint>
#include <cstring>

// Problem constants
#define B_ 2
#define S_ 2048
#define D_ 2048
#define H_ 16
#define DK_ 128

static const size_t NBSD = (size_t)B_ * S_ * D_;
// fp32 planes: Qlin/Olin, Klin, Vlin
__device__ float g_scratch[3 * (size_t)B_ * S_ * D_];
// fp16 planes: Qh, Ql, Kh, Kl
__device__ __half g_h16[4 * (size_t)B_ * S_ * D_];
// packed+transposed V: u32 half2(V[2s2][d],V[2s2+1][d]) at [b,h][d][s2]
__device__ uint32_t g_vp[(size_t)B_ * S_ * D_ / 2];
__device__ float g_xt[(size_t)B_ * S_ * D_];          // tf32-rounded x
__device__ float g_wt[4 * (size_t)D_ * D_];           // tf32-rounded Wq,Wk,Wv,Wo
__device__ float g_bias[3 * D_];                      // concat bq,bk,bv

// ============================================================================
// Helpers (arch-generic PTX: cp.async sm_80+, mma.sync sm_80+, ldmatrix sm_75+)
// ============================================================================
__device__ __forceinline__ uint32_t smem_to_u32(const void* smem_ptr) {
    uint32_t addr;
    asm("{ .reg .u64 tmp; cvta.to.shared.u64 tmp, %1; cvt.u32.u64 %0, tmp; }"
        : "=r"(addr) : "l"(smem_ptr));
    return addr;
}

__device__ __forceinline__ uint32_t h2_as_u32(__half2 h) {
    uint32_t u;
    memcpy(&u, &h, 4);
    return u;
}

__device__ __forceinline__ void cp_async16(uint32_t smem_addr, const void* gptr) {
    asm volatile("cp.async.cg.shared.global [%0], [%1], 16;"
                 :: "r"(smem_addr), "l"(gptr));
}
#define CP_ASYNC_COMMIT() asm volatile("cp.async.commit_group;" ::: "memory")
#define CP_ASYNC_WAIT(n)  asm volatile("cp.async.wait_group %0;" :: "n"(n) : "memory")

__device__ __forceinline__ void ldsm_x4(uint32_t* r, uint32_t addr) {
    asm volatile("ldmatrix.sync.aligned.m8n8.x4.shared.b16 {%0,%1,%2,%3}, [%4];"
                 : "=r"(r[0]), "=r"(r[1]), "=r"(r[2]), "=r"(r[3]) : "r"(addr));
}

__device__ __forceinline__ void mma_tf32_16n8k8(float* d, const uint32_t* a,
                                                const uint32_t* b) {
    asm volatile(
        "mma.sync.aligned.m16n8k8.row.col.f32.tf32.tf32.f32 "
        "{%0,%1,%2,%3}, {%4,%5,%6,%7}, {%8,%9}, {%0,%1,%2,%3};"
        : "+f"(d[0]), "+f"(d[1]), "+f"(d[2]), "+f"(d[3])
        : "r"(a[0]), "r"(a[1]), "r"(a[2]), "r"(a[3]), "r"(b[0]), "r"(b[1]));
}

__device__ __forceinline__ void mma_f16_16n8k16(float* d, const uint32_t* a,
                                                const uint32_t* b) {
    asm volatile(
        "mma.sync.aligned.m16n8k16.row.col.f32.f16.f16.f32 "
        "{%0,%1,%2,%3}, {%4,%5,%6,%7}, {%8,%9}, {%0,%1,%2,%3};"
        : "+f"(d[0]), "+f"(d[1]), "+f"(d[2]), "+f"(d[3])
        : "r"(a[0]), "r"(a[1]), "r"(a[2]), "r"(a[3]), "r"(b[0]), "r"(b[1]));
}

__device__ __forceinline__ float tf32_round(float x) {
    uint32_t u;
    asm("cvt.rna.tf32.f32 %0, %1;" : "=r"(u) : "f"(x));
    return __uint_as_float(u);
}

// ============================================================================
// tf32 rounding pre-pass (elementwise, float4)
// ============================================================================
__global__ __launch_bounds__(256) void tf32_round_kernel(
    const float* __restrict__ in, float* __restrict__ out, int n4)
{
    int i = blockIdx.x * 256 + threadIdx.x;
    if (i >= n4) return;
    float4 v = ((const float4*)in)[i];
    v.x = tf32_round(v.x); v.y = tf32_round(v.y);
    v.z = tf32_round(v.z); v.w = tf32_round(v.w);
    ((float4*)out)[i] = v;
}

// ============================================================================
// mma.sync tf32 GEMM: C = A @ W^T + bias. BM=128, BN=256, BK=32, 8 warps.
// Output columns routed to planes of stride plane_stride (fused QKV).
// ============================================================================
#define GSTR 36
#define GEMM_STAGE_FLOATS ((128 + 256) * GSTR)      // 13824
#define GEMM_STAGE_BYTES  (GEMM_STAGE_FLOATS * 4)   // 55296
#define GEMM_SMEM (3 * GEMM_STAGE_BYTES + 16)       // 165904

__device__ __forceinline__ void gemm_load_stage(
    const float* __restrict__ A, const float* __restrict__ W,
    int row0, int col0, int K, int kc, uint32_t sbase, int tid)
{
#pragma unroll
    for (int i = 0; i < 4; i++) {
        int q = i * 256 + tid;           // 0..1023
        int r = q >> 3;
        int c = q & 7;
        cp_async16(sbase + (uint32_t)(r * GSTR * 4 + c * 16),
                   A + (size_t)(row0 + r) * K + kc * 32 + c * 4);
    }
#pragma unroll
    for (int i = 0; i < 8; i++) {
        int q = i * 256 + tid;           // 0..2047
        int r = q >> 3;
        int c = q & 7;
        cp_async16(sbase + (uint32_t)(128 * GSTR * 4) +
                   (uint32_t)(r * GSTR * 4 + c * 16),
                   W + (size_t)(col0 + r) * K + kc * 32 + c * 4);
    }
    CP_ASYNC_COMMIT();
}

__global__ __launch_bounds__(256) void tf32_gemm_nt_bias(
    const float* __restrict__ A, const float* __restrict__ W,
    const float* __restrict__ bias, float* __restrict__ C,
    int M, int K, size_t plane_stride)
{
    extern __shared__ __align__(16) float dsm[];

    int tid = threadIdx.x;
    int wid = tid >> 5;
    int lane = tid & 31;
    int gr = lane >> 2;
    int gc = lane & 3;
    int wm = wid & 1;
    int wn = wid >> 1;

    int bx = blockIdx.x, by = blockIdx.y;
    int row0 = by * 128, col0 = bx * 256;

    uint32_t sb_u32 = smem_to_u32(dsm);

    float acc[4][8][4];
#pragma unroll
    for (int i = 0; i < 4; i++)
#pragma unroll
        for (int j = 0; j < 8; j++)
#pragma unroll
            for (int k = 0; k < 4; k++) acc[i][j][k] = 0.f;

    const int NC = K >> 5;

    gemm_load_stage(A, W, row0, col0, K, 0, sb_u32 + 0 * GEMM_STAGE_BYTES, tid);
    gemm_load_stage(A, W, row0, col0, K, 1, sb_u32 + 1 * GEMM_STAGE_BYTES, tid);

    for (int j = 0; j < NC; j++) {
        if (j + 2 < NC) { CP_ASYNC_WAIT(1); } else { CP_ASYNC_WAIT(0); }
        __syncthreads();

        int s = j % 3;
        int jn = j + 2;
        if (jn < NC) {
            gemm_load_stage(A, W, row0, col0, K, jn,
                            sb_u32 + (jn % 3) * GEMM_STAGE_BYTES, tid);
        }

        const float* As = dsm + (size_t)s * GEMM_STAGE_FLOATS;
        const float* Bs = As + 128 * GSTR;

#pragma unroll
        for (int kst = 0; kst < 4; kst++) {
            int k0 = kst * 8;
            uint32_t af[4][4];
#pragma unroll
            for (int ma = 0; ma < 4; ma++) {
                int r = wm * 64 + ma * 16 + gr;
                af[ma][0] = __float_as_uint(As[r * GSTR + k0 + gc]);
                af[ma][1] = __float_as_uint(As[(r + 8) * GSTR + k0 + gc]);
                af[ma][2] = __float_as_uint(As[r * GSTR + k0 + gc + 4]);
                af[ma][3] = __float_as_uint(As[(r + 8) * GSTR + k0 + gc + 4]);
            }
            uint32_t bf[8][2];
#pragma unroll
            for (int na = 0; na < 8; na++) {
                int n = wn * 64 + na * 8 + gr;
                bf[na][0] = __float_as_uint(Bs[n * GSTR + k0 + gc]);
                bf[na][1] = __float_as_uint(Bs[n * GSTR + k0 + gc + 4]);
            }
#pragma unroll
            for (int ma = 0; ma < 4; ma++)
#pragma unroll
                for (int na = 0; na < 8; na++)
                    mma_tf32_16n8k8(acc[ma][na], af[ma], bf[na]);
        }
        __syncthreads();
    }

    // Epilogue: plane routing (col>>11), row stride 2048
    float* Cp = C + (size_t)(col0 >> 11) * plane_stride;
    int colp0 = col0 & 2047;
#pragma unroll
    for (int ma = 0; ma < 4; ma++) {
        int row = row0 + wm * 64 + ma * 16 + gr;
#pragma unroll
        for (int na = 0; na < 8; na++) {
            int colf = col0 + wn * 64 + na * 8 + gc * 2;
            int colp = colp0 + wn * 64 + na * 8 + gc * 2;
            float2 bb = *(const float2*)(bias + colf);
            float2 o0, o1;
            o0.x = acc[ma][na][0] + bb.x;
            o0.y = acc[ma][na][1] + bb.y;
            o1.x = acc[ma][na][2] + bb.x;
            o1.y = acc[ma][na][3] + bb.y;
            *(float2*)(Cp + (size_t)row * D_ + colp) = o0;
            *(float2*)(Cp + (size_t)(row + 8) * D_ + colp) = o1;
        }
    }
}

// ---------------------------------------------------------------------------
// RoPE + relayout + fp16 hi/lo pre-split for Q,K.
// ---------------------------------------------------------------------------
__global__ __launch_bounds__(256) void rope_relayout_kernel(
    const float* __restrict__ Qlin, const float* __restrict__ Klin,
    __half* __restrict__ Qh, __half* __restrict__ Ql,
    __half* __restrict__ Kh, __half* __restrict__ Kl)
{
    int idx = blockIdx.x * 256 + threadIdx.x;          // B*H*S*64
    if (idx >= B_ * H_ * S_ * 64) return;
    int i  = idx & 63;
    int s  = (idx >> 6) & (S_ - 1);
    int hb = idx >> 17;
    int h  = hb & (H_ - 1);
    int b  = hb >> 4;

    size_t lin = ((size_t)(b * S_ + s)) * D_ + h * DK_ + i;
    size_t out = ((size_t)hb * S_ + s) * DK_ + i;

    float inv = 1.0f / powf(10000.0f, (float)(2 * i) / 128.0f);
    float ang = (float)s * inv;
    float sn, cs;
    sincosf(ang, &sn, &cs);

    float q0 = Qlin[lin], q1 = Qlin[lin + 64];
    float qr0 = q0 * cs - q1 * sn;
    float qr1 = q1 * cs + q0 * sn;
    __half hh;
    hh = __float2half_rn(qr0);
    Qh[out] = hh;      Ql[out]      = __float2half_rn(qr0 - __half2float(hh));
    hh = __float2half_rn(qr1);
    Qh[out + 64] = hh; Ql[out + 64] = __float2half_rn(qr1 - __half2float(hh));

    float k0 = Klin[lin], k1 = Klin[lin + 64];
    float kr0 = k0 * cs - k1 * sn;
    float kr1 = k1 * cs + k0 * sn;
    hh = __float2half_rn(kr0);
    Kh[out] = hh;      Kl[out]      = __float2half_rn(kr0 - __half2float(hh));
    hh = __float2half_rn(kr1);
    Kh[out + 64] = hh; Kl[out + 64] = __float2half_rn(kr1 - __half2float(hh));
}

// ---------------------------------------------------------------------------
// V pack + transpose: [B,S,D] fp32 -> Vt[b,h][d][s2] u32 half2 pairs.
// Smem-tiled 32x32 transpose, coalesced reads and writes.
// ---------------------------------------------------------------------------
__global__ __launch_bounds__(256) void v_pack_kernel(
    const float* __restrict__ Vlin, uint32_t* __restrict__ Vp)
{
    __shared__ uint32_t tile[32][33];
    int blk = blockIdx.x;                // B*H * 4 * 32 = 4096
    int s2b = (blk & 31) * 32;
    int db  = ((blk >> 5) & 3) * 32;
    int hb  = blk >> 7;
    int h = hb & (H_ - 1), b = hb >> 4;
    int t = threadIdx.x;

#pragma unroll
    for (int it = 0; it < 4; it++) {
        int idx = it * 256 + t;          // 0..1023
        int s2l = idx >> 5, dl = idx & 31;
        const float* src = Vlin +
            ((size_t)(b * S_ + 2 * (s2b + s2l))) * D_ + h * DK_ + db + dl;
        tile[s2l][dl] = h2_as_u32(__floats2half2_rn(src[0], src[D_]));
    }
    __syncthreads();
#pragma unroll
    for (int it = 0; it < 4; it++) {
        int idx = it * 256 + t;
        int dl = idx >> 5, s2l = idx & 31;
        Vp[((size_t)hb * DK_ + db + dl) * (S_ / 2) + s2b + s2l] = tile[s2l][dl];
    }
}

// ---------------------------------------------------------------------------
// Tensor-core flash attention (causal), FA2 warp-autonomous softmax + LDSM.
// BM=128, BN=64, 8 warps; warp owns 16 q-rows. All fragment loads via
// ldmatrix.x4 (K hi/lo fused per call, Q-lo a-frags, V b-frags from Vt).
// ---------------------------------------------------------------------------
#define AHSTR 136                        // fp16 K/Q row stride (halves)
#define VTSTR 36                         // Vt row stride (u32)
#define KL_OFF (4352 * 4)                // bytes: KL plane within stage
#define VT_OFF (8704 * 4)                // bytes: Vt tile within stage
#define STG_F 13312                      // stage floats: 4352+4352+4608
#define OQL   (3 * STG_F)                // Q-lo plane offset (floats)
#define ATT_FLOATS (OQL + 8704)          // 48640
#define ATT_SMEM (ATT_FLOATS * 4)        // 194560 bytes

__global__ __launch_bounds__(256, 1) void attn_mma_kernel(
    const __half* __restrict__ Qh_g, const __half* __restrict__ Ql_g,
    const __half* __restrict__ Kh_g, const __half* __restrict__ Kl_g,
    const uint32_t* __restrict__ Vp_g, float* __restrict__ Olin)
{
    extern __shared__ __align__(16) float sm[];
    uint32_t sb = smem_to_u32(sm);

    int qt = (int)gridDim.x - 1 - (int)blockIdx.x;   // heavy tiles first
    int h = blockIdx.y, b = blockIdx.z;
    int hb = b * H_ + h;
    size_t base = (size_t)hb * S_ * DK_;
    size_t qoff = base + (size_t)qt * 128 * DK_;
    size_t vbase = (size_t)hb * DK_ * (S_ / 2);      // u32 units (Vt rows = d)

    int tid = threadIdx.x;
    int wid = tid >> 5;
    int lane = tid & 31;
    int gr = lane >> 2, gc = lane & 3;

    int r0 = wid * 16 + gr;
    int rbase = qt * 128;

    // ---- Stage Q-hi (stage-0 area) + Q-lo (OQL)
#pragma unroll
    for (int i = 0; i < 8; i++) {
        int q = i * 256 + tid;       // 0..2047
        int r = q >> 4, c = q & 15;
        size_t g = (size_t)r * DK_ + c * 8;
        uint32_t so = (uint32_t)(r * AHSTR * 2 + c * 16);
        cp_async16(sb + so, Qh_g + qoff + g);
        cp_async16(sb + OQL * 4 + so, Ql_g + qoff + g);
    }
    CP_ASYNC_COMMIT();
    CP_ASYNC_WAIT(0);
    __syncthreads();

    uint32_t qh[8][4];
    {
        const __half* Qhp = (const __half*)sm;
#pragma unroll
        for (int kst = 0; kst < 8; kst++) {
            int k0 = kst * 16;
            qh[kst][0] = *(const uint32_t*)&Qhp[r0 * AHSTR + k0 + 2 * gc];
            qh[kst][1] = *(const uint32_t*)&Qhp[(r0 + 8) * AHSTR + k0 + 2 * gc];
            qh[kst][2] = *(const uint32_t*)&Qhp[r0 * AHSTR + k0 + 2 * gc + 8];
            qh[kst][3] = *(const uint32_t*)&Qhp[(r0 + 8) * AHSTR + k0 + 2 * gc + 8];
        }
    }
    __syncthreads();   // stage-0 area free for K/V ring

    // ---- Per-lane LDSM base offsets (bytes)
    int lrow = lane & 7, lsel = lane >> 3;
    // K frag x4: m0=Kh(k0), m1=Kh(k0+8h), m2=Kl(k0), m3=Kl(k0+8h)
    uint32_t kfb = (lsel >= 2 ? (uint32_t)KL_OFF : 0u) +
                   (uint32_t)lrow * (AHSTR * 2) + (uint32_t)(lsel & 1) * 16u;
    // Q-lo a-frag x4: m0=(r,k0) m1=(r+8,k0) m2=(r,k0+8h) m3=(r+8,k0+8h)
    uint32_t qlb = sb + (uint32_t)OQL * 4 +
                   (uint32_t)((wid * 16 + (lsel & 1) * 8 + lrow) * (AHSTR * 2)) +
                   (uint32_t)(lsel >> 1) * 16u;
    // V frag x4: m0=(n0,c0) m1=(n0,c0+8h) m2=(n0+8,c0) m3=(n0+8,c0+8h)
    uint32_t vfb = (uint32_t)VT_OFF +
                   (uint32_t)(((lsel >> 1) * 8 + lrow) * (VTSTR * 4)) +
                   (uint32_t)(lsel & 1) * 16u;

    int nkt = 2 * qt + 2;

    // ---- K/V group loader: K(hi,lo) 64 rows + Vt 128 d-rows x 32 s2
    auto load_group = [&](int j, int s) {
        size_t kb = base + (size_t)j * 64 * DK_;
        size_t vt = vbase + (size_t)j * 32;          // s2 offset
        uint32_t st = sb + (uint32_t)(s * STG_F) * 4;
#pragma unroll
        for (int i = 0; i < 4; i++) {
            int q = i * 256 + tid;   // 0..1023
            int r = q >> 4, c = q & 15;
            size_t g = kb + (size_t)r * DK_ + c * 8;
            uint32_t so = (uint32_t)(r * AHSTR * 2 + c * 16);
            cp_async16(st + so, Kh_g + g);
            cp_async16(st + KL_OFF + so, Kl_g + g);
        }
#pragma unroll
        for (int i = 0; i < 4; i++) {
            int q = i * 256 + tid;   // 0..1023 (128 d-rows x 8 chunks)
            int r = q >> 3, c = q & 7;
            cp_async16(st + VT_OFF + (uint32_t)(r * VTSTR * 4 + c * 16),
                       Vp_g + vt + (size_t)r * (S_ / 2) + c * 4);
        }
        CP_ASYNC_COMMIT();
    };

    load_group(0, 0);
    if (nkt > 1) load_group(1, 1);

    float oacc[16][4];
#pragma unroll
    for (int i = 0; i < 16; i++)
#pragma unroll
        for (int j = 0; j < 4; j++) oacc[i][j] = 0.f;

    float m0 = -1e30f, m1 = -1e30f, l0 = 0.f, l1 = 0.f;
    const float scale = 0.088388347648318440f;   // 1/sqrt(128)

    for (int j = 0; j < nkt; j++) {
        if (j + 1 < nkt) { CP_ASYNC_WAIT(1); } else { CP_ASYNC_WAIT(0); }
        __syncthreads();

        if (j + 2 < nkt) load_group(j + 2, (j + 2) % 3);

        uint32_t stage_b = sb + (uint32_t)((j % 3) * STG_F) * 4;

        // Scores: warp tile 16x64, fp16 3-pass, fragments via LDSM
        float sacc[8][4];
#pragma unroll
        for (int i = 0; i < 8; i++)
#pragma unroll
            for (int k = 0; k < 4; k++) sacc[i][k] = 0.f;

#pragma unroll
        for (int kst = 0; kst < 8; kst++) {
            uint32_t ql[4];
            ldsm_x4(ql, qlb + kst * 32);
#pragma unroll
            for (int na = 0; na < 8; na++) {
                uint32_t kf[4];
                ldsm_x4(kf, stage_b + kfb +
                        (uint32_t)(na * 8 * AHSTR * 2) + kst * 32);
                mma_f16_16n8k16(sacc[na], qh[kst], kf + 2);  // qh x Klo
                mma_f16_16n8k16(sacc[na], ql, kf);           // qlo x Khi
                mma_f16_16n8k16(sacc[na], qh[kst], kf);      // qh x Khi
            }
        }

        // Scale + causal mask (registers only)
        bool diag = (j >= 2 * qt);
        int rg0 = rbase + r0, rg1 = rg0 + 8;
#pragma unroll
        for (int na = 0; na < 8; na++) {
            float s0 = sacc[na][0] * scale;
            float s1 = sacc[na][1] * scale;
            float s2 = sacc[na][2] * scale;
            float s3 = sacc[na][3] * scale;
            if (diag) {
                int cg = j * 64 + na * 8 + 2 * gc;
                if (cg > rg0) s0 = -1e30f;
                if (cg + 1 > rg0) s1 = -1e30f;
                if (cg > rg1) s2 = -1e30f;
                if (cg + 1 > rg1) s3 = -1e30f;
            }
            sacc[na][0] = s0; sacc[na][1] = s1;
            sacc[na][2] = s2; sacc[na][3] = s3;
        }

        // Warp-local online softmax
        float rm0 = -1e30f, rm1 = -1e30f;
#pragma unroll
        for (int na = 0; na < 8; na++) {
            rm0 = fmaxf(rm0, fmaxf(sacc[na][0], sacc[na][1]));
            rm1 = fmaxf(rm1, fmaxf(sacc[na][2], sacc[na][3]));
        }
        rm0 = fmaxf(rm0, __shfl_xor_sync(0xffffffffu, rm0, 1));
        rm0 = fmaxf(rm0, __shfl_xor_sync(0xffffffffu, rm0, 2));
        rm1 = fmaxf(rm1, __shfl_xor_sync(0xffffffffu, rm1, 1));
        rm1 = fmaxf(rm1, __shfl_xor_sync(0xffffffffu, rm1, 2));

        float mn0 = fmaxf(m0, rm0), mn1 = fmaxf(m1, rm1);
        float a0 = __expf(m0 - mn0), a1 = __expf(m1 - mn1);
        m0 = mn0; m1 = mn1;

        uint32_t ap[4][4];
        float sum0 = 0.f, sum1 = 0.f;
#pragma unroll
        for (int kst = 0; kst < 4; kst++) {
            int e = 2 * kst, o = 2 * kst + 1;
            __half2 h00 = __floats2half2_rn(__expf(sacc[e][0] - mn0),
                                            __expf(sacc[e][1] - mn0));
            __half2 h01 = __floats2half2_rn(__expf(sacc[e][2] - mn1),
                                            __expf(sacc[e][3] - mn1));
            __half2 h10 = __floats2half2_rn(__expf(sacc[o][0] - mn0),
                                            __expf(sacc[o][1] - mn0));
            __half2 h11 = __floats2half2_rn(__expf(sacc[o][2] - mn1),
                                            __expf(sacc[o][3] - mn1));
            ap[kst][0] = h2_as_u32(h00);
            ap[kst][1] = h2_as_u32(h01);
            ap[kst][2] = h2_as_u32(h10);
            ap[kst][3] = h2_as_u32(h11);
            float2 f;
            f = __half22float2(h00); sum0 += f.x + f.y;
            f = __half22float2(h10); sum0 += f.x + f.y;
            f = __half22float2(h01); sum1 += f.x + f.y;
            f = __half22float2(h11); sum1 += f.x + f.y;
        }
        sum0 += __shfl_xor_sync(0xffffffffu, sum0, 1);
        sum0 += __shfl_xor_sync(0xffffffffu, sum0, 2);
        sum1 += __shfl_xor_sync(0xffffffffu, sum1, 1);
        sum1 += __shfl_xor_sync(0xffffffffu, sum1, 2);
        l0 = l0 * a0 + sum0;
        l1 = l1 * a1 + sum1;

        // Rescale O accumulators
#pragma unroll
        for (int na = 0; na < 16; na++) {
            oacc[na][0] *= a0; oacc[na][1] *= a0;
            oacc[na][2] *= a1; oacc[na][3] *= a1;
        }

        // PV: warp tile 16x128, V fragments via LDSM (2 n-atoms per call)
#pragma unroll
        for (int kst = 0; kst < 4; kst++) {
#pragma unroll
            for (int np = 0; np < 8; np++) {
                uint32_t vf[4];
                ldsm_x4(vf, stage_b + vfb +
                        (uint32_t)(np * 16 * VTSTR * 4) + kst * 32);
                mma_f16_16n8k16(oacc[2 * np], ap[kst], vf);
                mma_f16_16n8k16(oacc[2 * np + 1], ap[kst], vf + 2);
            }
        }
    }

    // Epilogue: normalize, round, write directly into [B,S,D] layout
    float li0 = 1.0f / l0;
    float li1 = 1.0f / l1;
    int srow0 = rbase + r0;
    float* Og0 = Olin + ((size_t)b * S_ + srow0) * D_ + h * DK_;
    float* Og1 = Olin + ((size_t)b * S_ + srow0 + 8) * D_ + h * DK_;
#pragma unroll
    for (int na = 0; na < 16; na++) {
        int col = na * 8 + 2 * gc;
        float2 o0, o1;
        o0.x = tf32_round(oacc[na][0] * li0);
        o0.y = tf32_round(oacc[na][1] * li0);
        o1.x = tf32_round(oacc[na][2] * li1);
        o1.y = tf32_round(oacc[na][3] * li1);
        *(float2*)(Og0 + col) = o0;
        *(float2*)(Og1 + col) = o1;
    }
}

// ---------------------------------------------------------------------------
extern "C" void kernel_launch(void* const* d_in, const int* in_sizes, int n_in,
                              void* d_out, int out_size)
{
    const float* x  = (const float*)d_in[0];
    const float* Wq = (const float*)d_in[2];
    const float* bq = (const float*)d_in[3];
    const float* Wk = (const float*)d_in[4];
    const float* bk = (const float*)d_in[5];
    const float* Wv = (const float*)d_in[6];
    const float* bv = (const float*)d_in[7];
    const float* Wo = (const float*)d_in[8];
    const float* bo = (const float*)d_in[9];
    float* out = (float*)d_out;

    float* base = nullptr;
    cudaGetSymbolAddress((void**)&base, g_scratch);
    __half* hbase = nullptr;
    cudaGetSymbolAddress((void**)&hbase, g_h16);
    uint32_t* vp = nullptr;
    cudaGetSymbolAddress((void**)&vp, g_vp);
    float* xt = nullptr;
    cudaGetSymbolAddress((void**)&xt, g_xt);
    float* wt = nullptr;
    cudaGetSymbolAddress((void**)&wt, g_wt);
    float* biasqkv = nullptr;
    cudaGetSymbolAddress((void**)&biasqkv, g_bias);

    float* Qlin = base;
    float* Klin = base + NBSD;
    float* Vlin = base + 2 * NBSD;
    __half* Qh16 = hbase;
    __half* Ql16 = hbase + NBSD;
    __half* Kh16 = hbase + 2 * NBSD;
    __half* Kl16 = hbase + 3 * NBSD;
    float* Olin = Qlin;
    float* Wot = wt + 3 * (size_t)D_ * D_;

    const int M = B_ * S_, K = D_;

    cudaMemcpyAsync(biasqkv,          bq, D_ * 4, cudaMemcpyDeviceToDevice);
    cudaMemcpyAsync(biasqkv + D_,     bk, D_ * 4, cudaMemcpyDeviceToDevice);
    cudaMemcpyAsync(biasqkv + 2 * D_, bv, D_ * 4, cudaMemcpyDeviceToDevice);

    {
        int nx4 = (int)(NBSD / 4);
        int nw4 = (int)(((size_t)D_ * D_) / 4);
        tf32_round_kernel<<<(nx4 + 255) / 256, 256>>>(x, xt, nx4);
        tf32_round_kernel<<<(nw4 + 255) / 256, 256>>>(Wq, wt, nw4);
        tf32_round_kernel<<<(nw4 + 255) / 256, 256>>>(Wk, wt + (size_t)D_ * D_, nw4);
        tf32_round_kernel<<<(nw4 + 255) / 256, 256>>>(Wv, wt + 2 * (size_t)D_ * D_, nw4);
        tf32_round_kernel<<<(nw4 + 255) / 256, 256>>>(Wo, Wot, nw4);
    }

    cudaFuncSetAttribute(tf32_gemm_nt_bias,
                         cudaFuncAttributeMaxDynamicSharedMemorySize, GEMM_SMEM);

    tf32_gemm_nt_bias<<<dim3(3 * D_ / 256, M / 128), 256, GEMM_SMEM>>>(
        xt, wt, biasqkv, Qlin, M, K, NBSD);

    int rope_total = B_ * H_ * S_ * 64;
    rope_relayout_kernel<<<rope_total / 256, 256>>>(Qlin, Klin,
                                                    Qh16, Ql16, Kh16, Kl16);
    v_pack_kernel<<<B_ * H_ * 4 * 32, 256>>>(Vlin, vp);

    cudaFuncSetAttribute(attn_mma_kernel,
                         cudaFuncAttributeMaxDynamicSharedMemorySize, ATT_SMEM);
    attn_mma_kernel<<<dim3(S_ / 128, H_, B_), 256, ATT_SMEM>>>(
        Qh16, Ql16, Kh16, Kl16, vp, Olin);

    tf32_gemm_nt_bias<<<dim3(D_ / 256, M / 128), 256, GEMM_SMEM>>>(
        Olin, Wot, bo, out, M, K, 0);
}

// round 13
// speedup vs baseline: 4.2676x; 1.0414x over previous
#include <cuda_runtime.h>
#include <cuda_fp16.h>
#include <math.h>
#include <cstdint>
#include <cstring>

// Problem constants
#define B_ 2
#define S_ 2048
#define D_ 2048
#define H_ 16
#define DK_ 128

static const size_t NBSD = (size_t)B_ * S_ * D_;
// fp32 planes: Qlin/Olin, Klin, Vlin
__device__ float g_scratch[3 * (size_t)B_ * S_ * D_];
// fp16 planes: Qh, Kh, Kl
__device__ __half g_h16[3 * (size_t)B_ * S_ * D_];
// packed+transposed V: u32 half2(V[2s2][d],V[2s2+1][d]) at [b,h][d][s2]
__device__ uint32_t g_vp[(size_t)B_ * S_ * D_ / 2];
__device__ float g_xt[(size_t)B_ * S_ * D_];          // tf32-rounded x
__device__ float g_wt[4 * (size_t)D_ * D_];           // tf32-rounded Wq,Wk,Wv,Wo
__device__ float g_bias[3 * D_];                      // concat bq,bk,bv

// ============================================================================
// Helpers (arch-generic PTX: cp.async sm_80+, mma.sync sm_80+, ldmatrix sm_75+)
// ============================================================================
__device__ __forceinline__ uint32_t smem_to_u32(const void* smem_ptr) {
    uint32_t addr;
    asm("{ .reg .u64 tmp; cvta.to.shared.u64 tmp, %1; cvt.u32.u64 %0, tmp; }"
        : "=r"(addr) : "l"(smem_ptr));
    return addr;
}

__device__ __forceinline__ uint32_t h2_as_u32(__half2 h) {
    uint32_t u;
    memcpy(&u, &h, 4);
    return u;
}

__device__ __forceinline__ void cp_async16(uint32_t smem_addr, const void* gptr) {
    asm volatile("cp.async.cg.shared.global [%0], [%1], 16;"
                 :: "r"(smem_addr), "l"(gptr));
}
#define CP_ASYNC_COMMIT() asm volatile("cp.async.commit_group;" ::: "memory")
#define CP_ASYNC_WAIT(n)  asm volatile("cp.async.wait_group %0;" :: "n"(n) : "memory")

__device__ __forceinline__ void ldsm_x4(uint32_t* r, uint32_t addr) {
    asm volatile("ldmatrix.sync.aligned.m8n8.x4.shared.b16 {%0,%1,%2,%3}, [%4];"
                 : "=r"(r[0]), "=r"(r[1]), "=r"(r[2]), "=r"(r[3]) : "r"(addr));
}

__device__ __forceinline__ void mma_tf32_16n8k8(float* d, const uint32_t* a,
                                                const uint32_t* b) {
    asm volatile(
        "mma.sync.aligned.m16n8k8.row.col.f32.tf32.tf32.f32 "
        "{%0,%1,%2,%3}, {%4,%5,%6,%7}, {%8,%9}, {%0,%1,%2,%3};"
        : "+f"(d[0]), "+f"(d[1]), "+f"(d[2]), "+f"(d[3])
        : "r"(a[0]), "r"(a[1]), "r"(a[2]), "r"(a[3]), "r"(b[0]), "r"(b[1]));
}

__device__ __forceinline__ void mma_f16_16n8k16(float* d, const uint32_t* a,
                                                const uint32_t* b) {
    asm volatile(
        "mma.sync.aligned.m16n8k16.row.col.f32.f16.f16.f32 "
        "{%0,%1,%2,%3}, {%4,%5,%6,%7}, {%8,%9}, {%0,%1,%2,%3};"
        : "+f"(d[0]), "+f"(d[1]), "+f"(d[2]), "+f"(d[3])
        : "r"(a[0]), "r"(a[1]), "r"(a[2]), "r"(a[3]), "r"(b[0]), "r"(b[1]));
}

__device__ __forceinline__ float tf32_round(float x) {
    uint32_t u;
    asm("cvt.rna.tf32.f32 %0, %1;" : "=r"(u) : "f"(x));
    return __uint_as_float(u);
}

// ============================================================================
// tf32 rounding pre-passes
// ============================================================================
__global__ __launch_bounds__(256) void tf32_round_kernel(
    const float* __restrict__ in, float* __restrict__ out, int n4)
{
    int i = blockIdx.x * 256 + threadIdx.x;
    if (i >= n4) return;
    float4 v = ((const float4*)in)[i];
    v.x = tf32_round(v.x); v.y = tf32_round(v.y);
    v.z = tf32_round(v.z); v.w = tf32_round(v.w);
    ((float4*)out)[i] = v;
}

// All 4 weight matrices in one launch (sources non-contiguous, dest contiguous)
__global__ __launch_bounds__(256) void w4_round_kernel(
    const float* __restrict__ W0, const float* __restrict__ W1,
    const float* __restrict__ W2, const float* __restrict__ W3,
    float* __restrict__ out)
{
    int i = blockIdx.x * 256 + threadIdx.x;     // 0 .. 4*2^20-1
    const int per = (D_ * D_) / 4;              // 2^20 float4 per plane
    int p = i >> 20, j = i & (per - 1);
    const float* W = (p == 0) ? W0 : (p == 1) ? W1 : (p == 2) ? W2 : W3;
    float4 v = ((const float4*)W)[j];
    v.x = tf32_round(v.x); v.y = tf32_round(v.y);
    v.z = tf32_round(v.z); v.w = tf32_round(v.w);
    ((float4*)out)[i] = v;
}

// ============================================================================
// mma.sync tf32 GEMM: C = A @ W^T + bias. BM=128, BN=256, BK=32, 8 warps.
// Output columns routed to planes of stride plane_stride (fused QKV).
// ============================================================================
#define GSTR 36
#define GEMM_STAGE_FLOATS ((128 + 256) * GSTR)      // 13824
#define GEMM_STAGE_BYTES  (GEMM_STAGE_FLOATS * 4)   // 55296
#define GEMM_SMEM (3 * GEMM_STAGE_BYTES + 16)       // 165904

__device__ __forceinline__ void gemm_load_stage(
    const float* __restrict__ A, const float* __restrict__ W,
    int row0, int col0, int K, int kc, uint32_t sbase, int tid)
{
#pragma unroll
    for (int i = 0; i < 4; i++) {
        int q = i * 256 + tid;
        int r = q >> 3;
        int c = q & 7;
        cp_async16(sbase + (uint32_t)(r * GSTR * 4 + c * 16),
                   A + (size_t)(row0 + r) * K + kc * 32 + c * 4);
    }
#pragma unroll
    for (int i = 0; i < 8; i++) {
        int q = i * 256 + tid;
        int r = q >> 3;
        int c = q & 7;
        cp_async16(sbase + (uint32_t)(128 * GSTR * 4) +
                   (uint32_t)(r * GSTR * 4 + c * 16),
                   W + (size_t)(col0 + r) * K + kc * 32 + c * 4);
    }
    CP_ASYNC_COMMIT();
}

__global__ __launch_bounds__(256) void tf32_gemm_nt_bias(
    const float* __restrict__ A, const float* __restrict__ W,
    const float* __restrict__ bias, float* __restrict__ C,
    int M, int K, size_t plane_stride)
{
    extern __shared__ __align__(16) float dsm[];

    int tid = threadIdx.x;
    int wid = tid >> 5;
    int lane = tid & 31;
    int gr = lane >> 2;
    int gc = lane & 3;
    int wm = wid & 1;
    int wn = wid >> 1;

    int bx = blockIdx.x, by = blockIdx.y;
    int row0 = by * 128, col0 = bx * 256;

    uint32_t sb_u32 = smem_to_u32(dsm);

    float acc[4][8][4];
#pragma unroll
    for (int i = 0; i < 4; i++)
#pragma unroll
        for (int j = 0; j < 8; j++)
#pragma unroll
            for (int k = 0; k < 4; k++) acc[i][j][k] = 0.f;

    const int NC = K >> 5;

    gemm_load_stage(A, W, row0, col0, K, 0, sb_u32 + 0 * GEMM_STAGE_BYTES, tid);
    gemm_load_stage(A, W, row0, col0, K, 1, sb_u32 + 1 * GEMM_STAGE_BYTES, tid);

    for (int j = 0; j < NC; j++) {
        if (j + 2 < NC) { CP_ASYNC_WAIT(1); } else { CP_ASYNC_WAIT(0); }
        __syncthreads();

        int s = j % 3;
        int jn = j + 2;
        if (jn < NC) {
            gemm_load_stage(A, W, row0, col0, K, jn,
                            sb_u32 + (jn % 3) * GEMM_STAGE_BYTES, tid);
        }

        const float* As = dsm + (size_t)s * GEMM_STAGE_FLOATS;
        const float* Bs = As + 128 * GSTR;

#pragma unroll
        for (int kst = 0; kst < 4; kst++) {
            int k0 = kst * 8;
            uint32_t af[4][4];
#pragma unroll
            for (int ma = 0; ma < 4; ma++) {
                int r = wm * 64 + ma * 16 + gr;
                af[ma][0] = __float_as_uint(As[r * GSTR + k0 + gc]);
                af[ma][1] = __float_as_uint(As[(r + 8) * GSTR + k0 + gc]);
                af[ma][2] = __float_as_uint(As[r * GSTR + k0 + gc + 4]);
                af[ma][3] = __float_as_uint(As[(r + 8) * GSTR + k0 + gc + 4]);
            }
            uint32_t bf[8][2];
#pragma unroll
            for (int na = 0; na < 8; na++) {
                int n = wn * 64 + na * 8 + gr;
                bf[na][0] = __float_as_uint(Bs[n * GSTR + k0 + gc]);
                bf[na][1] = __float_as_uint(Bs[n * GSTR + k0 + gc + 4]);
            }
#pragma unroll
            for (int ma = 0; ma < 4; ma++)
#pragma unroll
                for (int na = 0; na < 8; na++)
                    mma_tf32_16n8k8(acc[ma][na], af[ma], bf[na]);
        }
        __syncthreads();
    }

    float* Cp = C + (size_t)(col0 >> 11) * plane_stride;
    int colp0 = col0 & 2047;
#pragma unroll
    for (int ma = 0; ma < 4; ma++) {
        int row = row0 + wm * 64 + ma * 16 + gr;
#pragma unroll
        for (int na = 0; na < 8; na++) {
            int colf = col0 + wn * 64 + na * 8 + gc * 2;
            int colp = colp0 + wn * 64 + na * 8 + gc * 2;
            float2 bb = *(const float2*)(bias + colf);
            float2 o0, o1;
            o0.x = acc[ma][na][0] + bb.x;
            o0.y = acc[ma][na][1] + bb.y;
            o1.x = acc[ma][na][2] + bb.x;
            o1.y = acc[ma][na][3] + bb.y;
            *(float2*)(Cp + (size_t)row * D_ + colp) = o0;
            *(float2*)(Cp + (size_t)(row + 8) * D_ + colp) = o1;
        }
    }
}

// ---------------------------------------------------------------------------
// RoPE + relayout. Q: fp16 hi only (residual dropped — see error analysis).
// K: fp16 hi/lo split.
// ---------------------------------------------------------------------------
__global__ __launch_bounds__(256) void rope_relayout_kernel(
    const float* __restrict__ Qlin, const float* __restrict__ Klin,
    __half* __restrict__ Qh,
    __half* __restrict__ Kh, __half* __restrict__ Kl)
{
    int idx = blockIdx.x * 256 + threadIdx.x;          // B*H*S*64
    if (idx >= B_ * H_ * S_ * 64) return;
    int i  = idx & 63;
    int s  = (idx >> 6) & (S_ - 1);
    int hb = idx >> 17;
    int h  = hb & (H_ - 1);
    int b  = hb >> 4;

    size_t lin = ((size_t)(b * S_ + s)) * D_ + h * DK_ + i;
    size_t out = ((size_t)hb * S_ + s) * DK_ + i;

    float inv = 1.0f / powf(10000.0f, (float)(2 * i) / 128.0f);
    float ang = (float)s * inv;
    float sn, cs;
    sincosf(ang, &sn, &cs);

    float q0 = Qlin[lin], q1 = Qlin[lin + 64];
    Qh[out]      = __float2half_rn(q0 * cs - q1 * sn);
    Qh[out + 64] = __float2half_rn(q1 * cs + q0 * sn);

    float k0 = Klin[lin], k1 = Klin[lin + 64];
    float kr0 = k0 * cs - k1 * sn;
    float kr1 = k1 * cs + k0 * sn;
    __half hh;
    hh = __float2half_rn(kr0);
    Kh[out] = hh;      Kl[out]      = __float2half_rn(kr0 - __half2float(hh));
    hh = __float2half_rn(kr1);
    Kh[out + 64] = hh; Kl[out + 64] = __float2half_rn(kr1 - __half2float(hh));
}

// ---------------------------------------------------------------------------
// V pack + transpose: [B,S,D] fp32 -> Vt[b,h][d][s2] u32 half2 pairs.
// ---------------------------------------------------------------------------
__global__ __launch_bounds__(256) void v_pack_kernel(
    const float* __restrict__ Vlin, uint32_t* __restrict__ Vp)
{
    __shared__ uint32_t tile[32][33];
    int blk = blockIdx.x;                // B*H * 4 * 32 = 4096
    int s2b = (blk & 31) * 32;
    int db  = ((blk >> 5) & 3) * 32;
    int hb  = blk >> 7;
    int h = hb & (H_ - 1), b = hb >> 4;
    int t = threadIdx.x;

#pragma unroll
    for (int it = 0; it < 4; it++) {
        int idx = it * 256 + t;
        int s2l = idx >> 5, dl = idx & 31;
        const float* src = Vlin +
            ((size_t)(b * S_ + 2 * (s2b + s2l))) * D_ + h * DK_ + db + dl;
        tile[s2l][dl] = h2_as_u32(__floats2half2_rn(src[0], src[D_]));
    }
    __syncthreads();
#pragma unroll
    for (int it = 0; it < 4; it++) {
        int idx = it * 256 + t;
        int dl = idx >> 5, s2l = idx & 31;
        Vp[((size_t)hb * DK_ + db + dl) * (S_ / 2) + s2b + s2l] = tile[s2l][dl];
    }
}

// ---------------------------------------------------------------------------
// Tensor-core flash attention (causal), FA2 + LDSM, 2-pass fp16 scores:
// S = Qh x Khi + Qh x Klo  (Q residual dropped; K residual kept).
// BM=128, BN=64, 8 warps. PV fp16 via transposed V. One barrier per kv-tile.
// ---------------------------------------------------------------------------
#define AHSTR 136                        // fp16 K/Q row stride (halves)
#define VTSTR 36                         // Vt row stride (u32)
#define KL_OFF (4352 * 4)                // bytes: KL plane within stage
#define VT_OFF (8704 * 4)                // bytes: Vt tile within stage
#define STG_F 13312                      // stage floats: 4352+4352+4608
#define ATT_FLOATS (3 * STG_F)           // 39936
#define ATT_SMEM (ATT_FLOATS * 4)        // 159744 bytes

__global__ __launch_bounds__(256, 1) void attn_mma_kernel(
    const __half* __restrict__ Qh_g,
    const __half* __restrict__ Kh_g, const __half* __restrict__ Kl_g,
    const uint32_t* __restrict__ Vp_g, float* __restrict__ Olin)
{
    extern __shared__ __align__(16) float sm[];
    uint32_t sb = smem_to_u32(sm);

    int qt = (int)gridDim.x - 1 - (int)blockIdx.x;   // heavy tiles first
    int h = blockIdx.y, b = blockIdx.z;
    int hb = b * H_ + h;
    size_t base = (size_t)hb * S_ * DK_;
    size_t qoff = base + (size_t)qt * 128 * DK_;
    size_t vbase = (size_t)hb * DK_ * (S_ / 2);      // u32 units

    int tid = threadIdx.x;
    int wid = tid >> 5;
    int lane = tid & 31;
    int gr = lane >> 2, gc = lane & 3;

    int r0 = wid * 16 + gr;
    int rbase = qt * 128;

    // ---- Stage Q-hi into stage-0 area (128 rows x 16 chunks = 2048)
#pragma unroll
    for (int i = 0; i < 8; i++) {
        int q = i * 256 + tid;
        int r = q >> 4, c = q & 15;
        cp_async16(sb + (uint32_t)(r * AHSTR * 2 + c * 16),
                   Qh_g + qoff + (size_t)r * DK_ + c * 8);
    }
    CP_ASYNC_COMMIT();
    CP_ASYNC_WAIT(0);
    __syncthreads();

    uint32_t qh[8][4];
    {
        const __half* Qhp = (const __half*)sm;
#pragma unroll
        for (int kst = 0; kst < 8; kst++) {
            int k0 = kst * 16;
            qh[kst][0] = *(const uint32_t*)&Qhp[r0 * AHSTR + k0 + 2 * gc];
            qh[kst][1] = *(const uint32_t*)&Qhp[(r0 + 8) * AHSTR + k0 + 2 * gc];
            qh[kst][2] = *(const uint32_t*)&Qhp[r0 * AHSTR + k0 + 2 * gc + 8];
            qh[kst][3] = *(const uint32_t*)&Qhp[(r0 + 8) * AHSTR + k0 + 2 * gc + 8];
        }
    }
    __syncthreads();   // stage-0 area free for K/V ring

    // ---- Per-lane LDSM base offsets (bytes)
    int lrow = lane & 7, lsel = lane >> 3;
    // K frag x4: m0=Kh(k0), m1=Kh(k0+8h), m2=Kl(k0), m3=Kl(k0+8h)
    uint32_t kfb = (lsel >= 2 ? (uint32_t)KL_OFF : 0u) +
                   (uint32_t)lrow * (AHSTR * 2) + (uint32_t)(lsel & 1) * 16u;
    // V frag x4: m0=(n0,c0) m1=(n0,c0+8h) m2=(n0+8,c0) m3=(n0+8,c0+8h)
    uint32_t vfb = (uint32_t)VT_OFF +
                   (uint32_t)(((lsel >> 1) * 8 + lrow) * (VTSTR * 4)) +
                   (uint32_t)(lsel & 1) * 16u;

    int nkt = 2 * qt + 2;

    auto load_group = [&](int j, int s) {
        size_t kb = base + (size_t)j * 64 * DK_;
        size_t vt = vbase + (size_t)j * 32;
        uint32_t st = sb + (uint32_t)(s * STG_F) * 4;
#pragma unroll
        for (int i = 0; i < 4; i++) {
            int q = i * 256 + tid;
            int r = q >> 4, c = q & 15;
            size_t g = kb + (size_t)r * DK_ + c * 8;
            uint32_t so = (uint32_t)(r * AHSTR * 2 + c * 16);
            cp_async16(st + so, Kh_g + g);
            cp_async16(st + KL_OFF + so, Kl_g + g);
        }
#pragma unroll
        for (int i = 0; i < 4; i++) {
            int q = i * 256 + tid;
            int r = q >> 3, c = q & 7;
            cp_async16(st + VT_OFF + (uint32_t)(r * VTSTR * 4 + c * 16),
                       Vp_g + vt + (size_t)r * (S_ / 2) + c * 4);
        }
        CP_ASYNC_COMMIT();
    };

    load_group(0, 0);
    if (nkt > 1) load_group(1, 1);

    float oacc[16][4];
#pragma unroll
    for (int i = 0; i < 16; i++)
#pragma unroll
        for (int j = 0; j < 4; j++) oacc[i][j] = 0.f;

    float m0 = -1e30f, m1 = -1e30f, l0 = 0.f, l1 = 0.f;
    const float scale = 0.088388347648318440f;   // 1/sqrt(128)

    for (int j = 0; j < nkt; j++) {
        if (j + 1 < nkt) { CP_ASYNC_WAIT(1); } else { CP_ASYNC_WAIT(0); }
        __syncthreads();

        if (j + 2 < nkt) load_group(j + 2, (j + 2) % 3);

        uint32_t stage_b = sb + (uint32_t)((j % 3) * STG_F) * 4;

        // Scores: warp tile 16x64, fp16 2-pass (Qh x Khi + Qh x Klo)
        float sacc[8][4];
#pragma unroll
        for (int i = 0; i < 8; i++)
#pragma unroll
            for (int k = 0; k < 4; k++) sacc[i][k] = 0.f;

#pragma unroll
        for (int kst = 0; kst < 8; kst++) {
#pragma unroll
            for (int na = 0; na < 8; na++) {
                uint32_t kf[4];
                ldsm_x4(kf, stage_b + kfb +
                        (uint32_t)(na * 8 * AHSTR * 2) + kst * 32);
                mma_f16_16n8k16(sacc[na], qh[kst], kf + 2);  // qh x Klo
                mma_f16_16n8k16(sacc[na], qh[kst], kf);      // qh x Khi
            }
        }

        // Scale + causal mask (registers only)
        bool diag = (j >= 2 * qt);
        int rg0 = rbase + r0, rg1 = rg0 + 8;
#pragma unroll
        for (int na = 0; na < 8; na++) {
            float s0 = sacc[na][0] * scale;
            float s1 = sacc[na][1] * scale;
            float s2 = sacc[na][2] * scale;
            float s3 = sacc[na][3] * scale;
            if (diag) {
                int cg = j * 64 + na * 8 + 2 * gc;
                if (cg > rg0) s0 = -1e30f;
                if (cg + 1 > rg0) s1 = -1e30f;
                if (cg > rg1) s2 = -1e30f;
                if (cg + 1 > rg1) s3 = -1e30f;
            }
            sacc[na][0] = s0; sacc[na][1] = s1;
            sacc[na][2] = s2; sacc[na][3] = s3;
        }

        // Warp-local online softmax
        float rm0 = -1e30f, rm1 = -1e30f;
#pragma unroll
        for (int na = 0; na < 8; na++) {
            rm0 = fmaxf(rm0, fmaxf(sacc[na][0], sacc[na][1]));
            rm1 = fmaxf(rm1, fmaxf(sacc[na][2], sacc[na][3]));
        }
        rm0 = fmaxf(rm0, __shfl_xor_sync(0xffffffffu, rm0, 1));
        rm0 = fmaxf(rm0, __shfl_xor_sync(0xffffffffu, rm0, 2));
        rm1 = fmaxf(rm1, __shfl_xor_sync(0xffffffffu, rm1, 1));
        rm1 = fmaxf(rm1, __shfl_xor_sync(0xffffffffu, rm1, 2));

        float mn0 = fmaxf(m0, rm0), mn1 = fmaxf(m1, rm1);
        float a0 = __expf(m0 - mn0), a1 = __expf(m1 - mn1);
        m0 = mn0; m1 = mn1;

        uint32_t ap[4][4];
        float sum0 = 0.f, sum1 = 0.f;
#pragma unroll
        for (int kst = 0; kst < 4; kst++) {
            int e = 2 * kst, o = 2 * kst + 1;
            __half2 h00 = __floats2half2_rn(__expf(sacc[e][0] - mn0),
                                            __expf(sacc[e][1] - mn0));
            __half2 h01 = __floats2half2_rn(__expf(sacc[e][2] - mn1),
                                            __expf(sacc[e][3] - mn1));
            __half2 h10 = __floats2half2_rn(__expf(sacc[o][0] - mn0),
                                            __expf(sacc[o][1] - mn0));
            __half2 h11 = __floats2half2_rn(__expf(sacc[o][2] - mn1),
                                            __expf(sacc[o][3] - mn1));
            ap[kst][0] = h2_as_u32(h00);
            ap[kst][1] = h2_as_u32(h01);
            ap[kst][2] = h2_as_u32(h10);
            ap[kst][3] = h2_as_u32(h11);
            float2 f;
            f = __half22float2(h00); sum0 += f.x + f.y;
            f = __half22float2(h10); sum0 += f.x + f.y;
            f = __half22float2(h01); sum1 += f.x + f.y;
            f = __half22float2(h11); sum1 += f.x + f.y;
        }
        sum0 += __shfl_xor_sync(0xffffffffu, sum0, 1);
        sum0 += __shfl_xor_sync(0xffffffffu, sum0, 2);
        sum1 += __shfl_xor_sync(0xffffffffu, sum1, 1);
        sum1 += __shfl_xor_sync(0xffffffffu, sum1, 2);
        l0 = l0 * a0 + sum0;
        l1 = l1 * a1 + sum1;

#pragma unroll
        for (int na = 0; na < 16; na++) {
            oacc[na][0] *= a0; oacc[na][1] *= a0;
            oacc[na][2] *= a1; oacc[na][3] *= a1;
        }

        // PV: warp tile 16x128, V fragments via LDSM
#pragma unroll
        for (int kst = 0; kst < 4; kst++) {
#pragma unroll
            for (int np = 0; np < 8; np++) {
                uint32_t vf[4];
                ldsm_x4(vf, stage_b + vfb +
                        (uint32_t)(np * 16 * VTSTR * 4) + kst * 32);
                mma_f16_16n8k16(oacc[2 * np], ap[kst], vf);
                mma_f16_16n8k16(oacc[2 * np + 1], ap[kst], vf + 2);
            }
        }
    }

    // Epilogue
    float li0 = 1.0f / l0;
    float li1 = 1.0f / l1;
    int srow0 = rbase + r0;
    float* Og0 = Olin + ((size_t)b * S_ + srow0) * D_ + h * DK_;
    float* Og1 = Olin + ((size_t)b * S_ + srow0 + 8) * D_ + h * DK_;
#pragma unroll
    for (int na = 0; na < 16; na++) {
        int col = na * 8 + 2 * gc;
        float2 o0, o1;
        o0.x = tf32_round(oacc[na][0] * li0);
        o0.y = tf32_round(oacc[na][1] * li0);
        o1.x = tf32_round(oacc[na][2] * li1);
        o1.y = tf32_round(oacc[na][3] * li1);
        *(float2*)(Og0 + col) = o0;
        *(float2*)(Og1 + col) = o1;
    }
}

// ---------------------------------------------------------------------------
extern "C" void kernel_launch(void* const* d_in, const int* in_sizes, int n_in,
                              void* d_out, int out_size)
{
    const float* x  = (const float*)d_in[0];
    const float* Wq = (const float*)d_in[2];
    const float* bq = (const float*)d_in[3];
    const float* Wk = (const float*)d_in[4];
    const float* bk = (const float*)d_in[5];
    const float* Wv = (const float*)d_in[6];
    const float* bv = (const float*)d_in[7];
    const float* Wo = (const float*)d_in[8];
    const float* bo = (const float*)d_in[9];
    float* out = (float*)d_out;

    float* base = nullptr;
    cudaGetSymbolAddress((void**)&base, g_scratch);
    __half* hbase = nullptr;
    cudaGetSymbolAddress((void**)&hbase, g_h16);
    uint32_t* vp = nullptr;
    cudaGetSymbolAddress((void**)&vp, g_vp);
    float* xt = nullptr;
    cudaGetSymbolAddress((void**)&xt, g_xt);
    float* wt = nullptr;
    cudaGetSymbolAddress((void**)&wt, g_wt);
    float* biasqkv = nullptr;
    cudaGetSymbolAddress((void**)&biasqkv, g_bias);

    float* Qlin = base;
    float* Klin = base + NBSD;
    float* Vlin = base + 2 * NBSD;
    __half* Qh16 = hbase;
    __half* Kh16 = hbase + NBSD;
    __half* Kl16 = hbase + 2 * NBSD;
    float* Olin = Qlin;
    float* Wot = wt + 3 * (size_t)D_ * D_;

    const int M = B_ * S_, K = D_;

    cudaMemcpyAsync(biasqkv,          bq, D_ * 4, cudaMemcpyDeviceToDevice);
    cudaMemcpyAsync(biasqkv + D_,     bk, D_ * 4, cudaMemcpyDeviceToDevice);
    cudaMemcpyAsync(biasqkv + 2 * D_, bv, D_ * 4, cudaMemcpyDeviceToDevice);

    {
        int nx4 = (int)(NBSD / 4);
        tf32_round_kernel<<<(nx4 + 255) / 256, 256>>>(x, xt, nx4);
        w4_round_kernel<<<16384, 256>>>(Wq, Wk, Wv, Wo, wt);
    }

    cudaFuncSetAttribute(tf32_gemm_nt_bias,
                         cudaFuncAttributeMaxDynamicSharedMemorySize, GEMM_SMEM);

    tf32_gemm_nt_bias<<<dim3(3 * D_ / 256, M / 128), 256, GEMM_SMEM>>>(
        xt, wt, biasqkv, Qlin, M, K, NBSD);

    int rope_total = B_ * H_ * S_ * 64;
    rope_relayout_kernel<<<rope_total / 256, 256>>>(Qlin, Klin,
                                                    Qh16, Kh16, Kl16);
    v_pack_kernel<<<B_ * H_ * 4 * 32, 256>>>(Vlin, vp);

    cudaFuncSetAttribute(attn_mma_kernel,
                         cudaFuncAttributeMaxDynamicSharedMemorySize, ATT_SMEM);
    attn_mma_kernel<<<dim3(S_ / 128, H_, B_), 256, ATT_SMEM>>>(
        Qh16, Kh16, Kl16, vp, Olin);

    tf32_gemm_nt_bias<<<dim3(D_ / 256, M / 128), 256, GEMM_SMEM>>>(
        Olin, Wot, bo, out, M, K, 0);
}

// round 14
// speedup vs baseline: 6.9018x; 1.6173x over previous
#include <cuda_runtime.h>
#include <cuda_fp16.h>
#include <math.h>
#include <cstdint>
#include <cstring>

// Problem constants
#define B_ 2
#define S_ 2048
#define D_ 2048
#define H_ 16
#define DK_ 128

static const size_t NBSD = (size_t)B_ * S_ * D_;
// fp32 planes: Qlin, Klin, Vlin (QKV GEMM output, consumed by rope/vpack)
__device__ float g_scratch[3 * (size_t)B_ * S_ * D_];
// fp16 planes: Qh, Kh, Kl, O16
__device__ __half g_h16[4 * (size_t)B_ * S_ * D_];
// packed+transposed V: u32 half2(V[2s2][d],V[2s2+1][d]) at [b,h][d][s2]
__device__ uint32_t g_vp[(size_t)B_ * S_ * D_ / 2];
__device__ __half g_x16[(size_t)B_ * S_ * D_];        // fp16 x
__device__ __half g_w16[4 * (size_t)D_ * D_];         // fp16 Wq,Wk,Wv,Wo
__device__ float g_bias[3 * D_];                      // concat bq,bk,bv

// ============================================================================
// Helpers
// ============================================================================
__device__ __forceinline__ uint32_t smem_to_u32(const void* smem_ptr) {
    uint32_t addr;
    asm("{ .reg .u64 tmp; cvta.to.shared.u64 tmp, %1; cvt.u32.u64 %0, tmp; }"
        : "=r"(addr) : "l"(smem_ptr));
    return addr;
}

__device__ __forceinline__ uint32_t h2_as_u32(__half2 h) {
    uint32_t u;
    memcpy(&u, &h, 4);
    return u;
}

__device__ __forceinline__ void cp_async16(uint32_t smem_addr, const void* gptr) {
    asm volatile("cp.async.cg.shared.global [%0], [%1], 16;"
                 :: "r"(smem_addr), "l"(gptr));
}
#define CP_ASYNC_COMMIT() asm volatile("cp.async.commit_group;" ::: "memory")
#define CP_ASYNC_WAIT(n)  asm volatile("cp.async.wait_group %0;" :: "n"(n) : "memory")

__device__ __forceinline__ void ldsm_x4(uint32_t* r, uint32_t addr) {
    asm volatile("ldmatrix.sync.aligned.m8n8.x4.shared.b16 {%0,%1,%2,%3}, [%4];"
                 : "=r"(r[0]), "=r"(r[1]), "=r"(r[2]), "=r"(r[3]) : "r"(addr));
}

__device__ __forceinline__ void mma_f16_16n8k16(float* d, const uint32_t* a,
                                                const uint32_t* b) {
    asm volatile(
        "mma.sync.aligned.m16n8k16.row.col.f32.f16.f16.f32 "
        "{%0,%1,%2,%3}, {%4,%5,%6,%7}, {%8,%9}, {%0,%1,%2,%3};"
        : "+f"(d[0]), "+f"(d[1]), "+f"(d[2]), "+f"(d[3])
        : "r"(a[0]), "r"(a[1]), "r"(a[2]), "r"(a[3]), "r"(b[0]), "r"(b[1]));
}

// ============================================================================
// fp16 conversion pre-passes
// ============================================================================
__global__ __launch_bounds__(256) void f32_to_f16_kernel(
    const float* __restrict__ in, __half* __restrict__ out, int n4)
{
    int i = blockIdx.x * 256 + threadIdx.x;
    if (i >= n4) return;
    float4 v = ((const float4*)in)[i];
    uint2 w;
    w.x = h2_as_u32(__floats2half2_rn(v.x, v.y));
    w.y = h2_as_u32(__floats2half2_rn(v.z, v.w));
    ((uint2*)out)[i] = w;
}

__global__ __launch_bounds__(256) void w4_to_f16_kernel(
    const float* __restrict__ W0, const float* __restrict__ W1,
    const float* __restrict__ W2, const float* __restrict__ W3,
    __half* __restrict__ out)
{
    int i = blockIdx.x * 256 + threadIdx.x;     // 0 .. 4*2^20-1
    const int per = (D_ * D_) / 4;
    int p = i >> 20, j = i & (per - 1);
    const float* W = (p == 0) ? W0 : (p == 1) ? W1 : (p == 2) ? W2 : W3;
    float4 v = ((const float4*)W)[j];
    uint2 w;
    w.x = h2_as_u32(__floats2half2_rn(v.x, v.y));
    w.y = h2_as_u32(__floats2half2_rn(v.z, v.w));
    ((uint2*)out)[i] = w;
}

// ============================================================================
// fp16 GEMM: C(fp32) = A(fp16)[M,K] @ W(fp16)[N,K]^T + bias.
// BM=128, BN=256, BK=64, 8 warps (2 M x 4 N), warp tile 64x64, m16n8k16.
// All fragments via ldmatrix.x4; 144B row stride (conflict-free LDSM).
// Output columns routed to planes of stride plane_stride (fused QKV).
// ============================================================================
#define HSTR 72                                  // halves per row (64 + 8 pad)
#define GA_BYTES (128 * HSTR * 2)                // 18432
#define GEMM_STAGE_BYTES ((128 + 256) * HSTR * 2)  // 55296
#define GEMM_SMEM (3 * GEMM_STAGE_BYTES + 16)

__device__ __forceinline__ void gemm16_load_stage(
    const __half* __restrict__ A, const __half* __restrict__ W,
    int row0, int col0, int K, int kc, uint32_t sbase, int tid)
{
#pragma unroll
    for (int i = 0; i < 4; i++) {
        int q = i * 256 + tid;           // 0..1023
        int r = q >> 3, c = q & 7;
        cp_async16(sbase + (uint32_t)(r * 144 + c * 16),
                   A + (size_t)(row0 + r) * K + kc * 64 + c * 8);
    }
#pragma unroll
    for (int i = 0; i < 8; i++) {
        int q = i * 256 + tid;           // 0..2047
        int r = q >> 3, c = q & 7;
        cp_async16(sbase + (uint32_t)GA_BYTES + (uint32_t)(r * 144 + c * 16),
                   W + (size_t)(col0 + r) * K + kc * 64 + c * 8);
    }
    CP_ASYNC_COMMIT();
}

__global__ __launch_bounds__(256) void f16_gemm_nt_bias(
    const __half* __restrict__ A, const __half* __restrict__ W,
    const float* __restrict__ bias, float* __restrict__ C,
    int M, int K, size_t plane_stride)
{
    extern __shared__ __align__(16) char dsm[];

    int tid = threadIdx.x;
    int wid = tid >> 5;
    int lane = tid & 31;
    int gr = lane >> 2;
    int gc = lane & 3;
    int wm = wid & 1;
    int wn = wid >> 1;
    int lrow = lane & 7, lsel = lane >> 3;

    int bx = blockIdx.x, by = blockIdx.y;
    int row0 = by * 128, col0 = bx * 256;

    uint32_t sb = smem_to_u32(dsm);
    // A-frag x4: m0=(r,k0) m1=(r+8,k0) m2=(r,k0+8h) m3=(r+8,k0+8h)
    uint32_t afb = (uint32_t)((wm * 64 + (lsel & 1) * 8 + lrow) * 144 +
                              (lsel >> 1) * 16);
    // W-frag x4: m0=(n,k0) m1=(n,k0+8h) m2=(n+8,k0) m3=(n+8,k0+8h)
    uint32_t wfb = (uint32_t)GA_BYTES +
                   (uint32_t)((wn * 64 + (lsel >> 1) * 8 + lrow) * 144 +
                              (lsel & 1) * 16);

    float acc[4][8][4];
#pragma unroll
    for (int i = 0; i < 4; i++)
#pragma unroll
        for (int j = 0; j < 8; j++)
#pragma unroll
            for (int k = 0; k < 4; k++) acc[i][j][k] = 0.f;

    const int NC = K >> 6;   // 32

    gemm16_load_stage(A, W, row0, col0, K, 0, sb + 0 * GEMM_STAGE_BYTES, tid);
    gemm16_load_stage(A, W, row0, col0, K, 1, sb + 1 * GEMM_STAGE_BYTES, tid);

    for (int j = 0; j < NC; j++) {
        if (j + 2 < NC) { CP_ASYNC_WAIT(1); } else { CP_ASYNC_WAIT(0); }
        __syncthreads();

        int jn = j + 2;
        if (jn < NC) {
            gemm16_load_stage(A, W, row0, col0, K, jn,
                              sb + (jn % 3) * GEMM_STAGE_BYTES, tid);
        }

        uint32_t stage_b = sb + (uint32_t)((j % 3) * GEMM_STAGE_BYTES);

#pragma unroll
        for (int kst = 0; kst < 4; kst++) {
            uint32_t af[4][4];
#pragma unroll
            for (int ma = 0; ma < 4; ma++)
                ldsm_x4(af[ma], stage_b + afb +
                        (uint32_t)(ma * 16 * 144) + kst * 32);
            uint32_t wf[4][4];
#pragma unroll
            for (int np = 0; np < 4; np++)
                ldsm_x4(wf[np], stage_b + wfb +
                        (uint32_t)(np * 16 * 144) + kst * 32);
#pragma unroll
            for (int ma = 0; ma < 4; ma++)
#pragma unroll
                for (int np = 0; np < 4; np++) {
                    mma_f16_16n8k16(acc[ma][2 * np], af[ma], &wf[np][0]);
                    mma_f16_16n8k16(acc[ma][2 * np + 1], af[ma], &wf[np][2]);
                }
        }
        __syncthreads();
    }

    // Epilogue: plane routing (col>>11), row stride 2048, fp32 out
    float* Cp = C + (size_t)(col0 >> 11) * plane_stride;
    int colp0 = col0 & 2047;
#pragma unroll
    for (int ma = 0; ma < 4; ma++) {
        int row = row0 + wm * 64 + ma * 16 + gr;
#pragma unroll
        for (int na = 0; na < 8; na++) {
            int colf = col0 + wn * 64 + na * 8 + gc * 2;
            int colp = colp0 + wn * 64 + na * 8 + gc * 2;
            float2 bb = *(const float2*)(bias + colf);
            float2 o0, o1;
            o0.x = acc[ma][na][0] + bb.x;
            o0.y = acc[ma][na][1] + bb.y;
            o1.x = acc[ma][na][2] + bb.x;
            o1.y = acc[ma][na][3] + bb.y;
            *(float2*)(Cp + (size_t)row * D_ + colp) = o0;
            *(float2*)(Cp + (size_t)(row + 8) * D_ + colp) = o1;
        }
    }
}

// ---------------------------------------------------------------------------
// RoPE + relayout. Q: fp16 hi only. K: fp16 hi/lo split.
// ---------------------------------------------------------------------------
__global__ __launch_bounds__(256) void rope_relayout_kernel(
    const float* __restrict__ Qlin, const float* __restrict__ Klin,
    __half* __restrict__ Qh,
    __half* __restrict__ Kh, __half* __restrict__ Kl)
{
    int idx = blockIdx.x * 256 + threadIdx.x;          // B*H*S*64
    if (idx >= B_ * H_ * S_ * 64) return;
    int i  = idx & 63;
    int s  = (idx >> 6) & (S_ - 1);
    int hb = idx >> 17;
    int h  = hb & (H_ - 1);
    int b  = hb >> 4;

    size_t lin = ((size_t)(b * S_ + s)) * D_ + h * DK_ + i;
    size_t out = ((size_t)hb * S_ + s) * DK_ + i;

    float inv = 1.0f / powf(10000.0f, (float)(2 * i) / 128.0f);
    float ang = (float)s * inv;
    float sn, cs;
    sincosf(ang, &sn, &cs);

    float q0 = Qlin[lin], q1 = Qlin[lin + 64];
    Qh[out]      = __float2half_rn(q0 * cs - q1 * sn);
    Qh[out + 64] = __float2half_rn(q1 * cs + q0 * sn);

    float k0 = Klin[lin], k1 = Klin[lin + 64];
    float kr0 = k0 * cs - k1 * sn;
    float kr1 = k1 * cs + k0 * sn;
    __half hh;
    hh = __float2half_rn(kr0);
    Kh[out] = hh;      Kl[out]      = __float2half_rn(kr0 - __half2float(hh));
    hh = __float2half_rn(kr1);
    Kh[out + 64] = hh; Kl[out + 64] = __float2half_rn(kr1 - __half2float(hh));
}

// ---------------------------------------------------------------------------
// V pack + transpose: [B,S,D] fp32 -> Vt[b,h][d][s2] u32 half2 pairs.
// ---------------------------------------------------------------------------
__global__ __launch_bounds__(256) void v_pack_kernel(
    const float* __restrict__ Vlin, uint32_t* __restrict__ Vp)
{
    __shared__ uint32_t tile[32][33];
    int blk = blockIdx.x;                // B*H * 4 * 32 = 4096
    int s2b = (blk & 31) * 32;
    int db  = ((blk >> 5) & 3) * 32;
    int hb  = blk >> 7;
    int h = hb & (H_ - 1), b = hb >> 4;
    int t = threadIdx.x;

#pragma unroll
    for (int it = 0; it < 4; it++) {
        int idx = it * 256 + t;
        int s2l = idx >> 5, dl = idx & 31;
        const float* src = Vlin +
            ((size_t)(b * S_ + 2 * (s2b + s2l))) * D_ + h * DK_ + db + dl;
        tile[s2l][dl] = h2_as_u32(__floats2half2_rn(src[0], src[D_]));
    }
    __syncthreads();
#pragma unroll
    for (int it = 0; it < 4; it++) {
        int idx = it * 256 + t;
        int dl = idx >> 5, s2l = idx & 31;
        Vp[((size_t)hb * DK_ + db + dl) * (S_ / 2) + s2b + s2l] = tile[s2l][dl];
    }
}

// ---------------------------------------------------------------------------
// Tensor-core flash attention (causal), FA2 + LDSM, 2-pass fp16 scores.
// BM=128, BN=64, 8 warps. Output written fp16 to O16 [B,S,D].
// ---------------------------------------------------------------------------
#define AHSTR 136                        // fp16 K/Q row stride (halves)
#define VTSTR 36                         // Vt row stride (u32)
#define KL_OFF (4352 * 4)                // bytes: KL plane within stage
#define VT_OFF (8704 * 4)                // bytes: Vt tile within stage
#define STG_F 13312                      // stage floats
#define ATT_FLOATS (3 * STG_F)           // 39936
#define ATT_SMEM (ATT_FLOATS * 4)        // 159744 bytes

__global__ __launch_bounds__(256, 1) void attn_mma_kernel(
    const __half* __restrict__ Qh_g,
    const __half* __restrict__ Kh_g, const __half* __restrict__ Kl_g,
    const uint32_t* __restrict__ Vp_g, __half* __restrict__ O16)
{
    extern __shared__ __align__(16) float sm[];
    uint32_t sb = smem_to_u32(sm);

    int qt = (int)gridDim.x - 1 - (int)blockIdx.x;
    int h = blockIdx.y, b = blockIdx.z;
    int hb = b * H_ + h;
    size_t base = (size_t)hb * S_ * DK_;
    size_t qoff = base + (size_t)qt * 128 * DK_;
    size_t vbase = (size_t)hb * DK_ * (S_ / 2);

    int tid = threadIdx.x;
    int wid = tid >> 5;
    int lane = tid & 31;
    int gr = lane >> 2, gc = lane & 3;

    int r0 = wid * 16 + gr;
    int rbase = qt * 128;

#pragma unroll
    for (int i = 0; i < 8; i++) {
        int q = i * 256 + tid;
        int r = q >> 4, c = q & 15;
        cp_async16(sb + (uint32_t)(r * AHSTR * 2 + c * 16),
                   Qh_g + qoff + (size_t)r * DK_ + c * 8);
    }
    CP_ASYNC_COMMIT();
    CP_ASYNC_WAIT(0);
    __syncthreads();

    uint32_t qh[8][4];
    {
        const __half* Qhp = (const __half*)sm;
#pragma unroll
        for (int kst = 0; kst < 8; kst++) {
            int k0 = kst * 16;
            qh[kst][0] = *(const uint32_t*)&Qhp[r0 * AHSTR + k0 + 2 * gc];
            qh[kst][1] = *(const uint32_t*)&Qhp[(r0 + 8) * AHSTR + k0 + 2 * gc];
            qh[kst][2] = *(const uint32_t*)&Qhp[r0 * AHSTR + k0 + 2 * gc + 8];
            qh[kst][3] = *(const uint32_t*)&Qhp[(r0 + 8) * AHSTR + k0 + 2 * gc + 8];
        }
    }
    __syncthreads();

    int lrow = lane & 7, lsel = lane >> 3;
    uint32_t kfb = (lsel >= 2 ? (uint32_t)KL_OFF : 0u) +
                   (uint32_t)lrow * (AHSTR * 2) + (uint32_t)(lsel & 1) * 16u;
    uint32_t vfb = (uint32_t)VT_OFF +
                   (uint32_t)(((lsel >> 1) * 8 + lrow) * (VTSTR * 4)) +
                   (uint32_t)(lsel & 1) * 16u;

    int nkt = 2 * qt + 2;

    auto load_group = [&](int j, int s) {
        size_t kb = base + (size_t)j * 64 * DK_;
        size_t vt = vbase + (size_t)j * 32;
        uint32_t st = sb + (uint32_t)(s * STG_F) * 4;
#pragma unroll
        for (int i = 0; i < 4; i++) {
            int q = i * 256 + tid;
            int r = q >> 4, c = q & 15;
            size_t g = kb + (size_t)r * DK_ + c * 8;
            uint32_t so = (uint32_t)(r * AHSTR * 2 + c * 16);
            cp_async16(st + so, Kh_g + g);
            cp_async16(st + KL_OFF + so, Kl_g + g);
        }
#pragma unroll
        for (int i = 0; i < 4; i++) {
            int q = i * 256 + tid;
            int r = q >> 3, c = q & 7;
            cp_async16(st + VT_OFF + (uint32_t)(r * VTSTR * 4 + c * 16),
                       Vp_g + vt + (size_t)r * (S_ / 2) + c * 4);
        }
        CP_ASYNC_COMMIT();
    };

    load_group(0, 0);
    if (nkt > 1) load_group(1, 1);

    float oacc[16][4];
#pragma unroll
    for (int i = 0; i < 16; i++)
#pragma unroll
        for (int j = 0; j < 4; j++) oacc[i][j] = 0.f;

    float m0 = -1e30f, m1 = -1e30f, l0 = 0.f, l1 = 0.f;
    const float scale = 0.088388347648318440f;

    for (int j = 0; j < nkt; j++) {
        if (j + 1 < nkt) { CP_ASYNC_WAIT(1); } else { CP_ASYNC_WAIT(0); }
        __syncthreads();

        if (j + 2 < nkt) load_group(j + 2, (j + 2) % 3);

        uint32_t stage_b = sb + (uint32_t)((j % 3) * STG_F) * 4;

        float sacc[8][4];
#pragma unroll
        for (int i = 0; i < 8; i++)
#pragma unroll
            for (int k = 0; k < 4; k++) sacc[i][k] = 0.f;

#pragma unroll
        for (int kst = 0; kst < 8; kst++) {
#pragma unroll
            for (int na = 0; na < 8; na++) {
                uint32_t kf[4];
                ldsm_x4(kf, stage_b + kfb +
                        (uint32_t)(na * 8 * AHSTR * 2) + kst * 32);
                mma_f16_16n8k16(sacc[na], qh[kst], kf + 2);
                mma_f16_16n8k16(sacc[na], qh[kst], kf);
            }
        }

        bool diag = (j >= 2 * qt);
        int rg0 = rbase + r0, rg1 = rg0 + 8;
#pragma unroll
        for (int na = 0; na < 8; na++) {
            float s0 = sacc[na][0] * scale;
            float s1 = sacc[na][1] * scale;
            float s2 = sacc[na][2] * scale;
            float s3 = sacc[na][3] * scale;
            if (diag) {
                int cg = j * 64 + na * 8 + 2 * gc;
                if (cg > rg0) s0 = -1e30f;
                if (cg + 1 > rg0) s1 = -1e30f;
                if (cg > rg1) s2 = -1e30f;
                if (cg + 1 > rg1) s3 = -1e30f;
            }
            sacc[na][0] = s0; sacc[na][1] = s1;
            sacc[na][2] = s2; sacc[na][3] = s3;
        }

        float rm0 = -1e30f, rm1 = -1e30f;
#pragma unroll
        for (int na = 0; na < 8; na++) {
            rm0 = fmaxf(rm0, fmaxf(sacc[na][0], sacc[na][1]));
            rm1 = fmaxf(rm1, fmaxf(sacc[na][2], sacc[na][3]));
        }
        rm0 = fmaxf(rm0, __shfl_xor_sync(0xffffffffu, rm0, 1));
        rm0 = fmaxf(rm0, __shfl_xor_sync(0xffffffffu, rm0, 2));
        rm1 = fmaxf(rm1, __shfl_xor_sync(0xffffffffu, rm1, 1));
        rm1 = fmaxf(rm1, __shfl_xor_sync(0xffffffffu, rm1, 2));

        float mn0 = fmaxf(m0, rm0), mn1 = fmaxf(m1, rm1);
        float a0 = __expf(m0 - mn0), a1 = __expf(m1 - mn1);
        m0 = mn0; m1 = mn1;

        uint32_t ap[4][4];
        float sum0 = 0.f, sum1 = 0.f;
#pragma unroll
        for (int kst = 0; kst < 4; kst++) {
            int e = 2 * kst, o = 2 * kst + 1;
            __half2 h00 = __floats2half2_rn(__expf(sacc[e][0] - mn0),
                                            __expf(sacc[e][1] - mn0));
            __half2 h01 = __floats2half2_rn(__expf(sacc[e][2] - mn1),
                                            __expf(sacc[e][3] - mn1));
            __half2 h10 = __floats2half2_rn(__expf(sacc[o][0] - mn0),
                                            __expf(sacc[o][1] - mn0));
            __half2 h11 = __floats2half2_rn(__expf(sacc[o][2] - mn1),
                                            __expf(sacc[o][3] - mn1));
            ap[kst][0] = h2_as_u32(h00);
            ap[kst][1] = h2_as_u32(h01);
            ap[kst][2] = h2_as_u32(h10);
            ap[kst][3] = h2_as_u32(h11);
            float2 f;
            f = __half22float2(h00); sum0 += f.x + f.y;
            f = __half22float2(h10); sum0 += f.x + f.y;
            f = __half22float2(h01); sum1 += f.x + f.y;
            f = __half22float2(h11); sum1 += f.x + f.y;
        }
        sum0 += __shfl_xor_sync(0xffffffffu, sum0, 1);
        sum0 += __shfl_xor_sync(0xffffffffu, sum0, 2);
        sum1 += __shfl_xor_sync(0xffffffffu, sum1, 1);
        sum1 += __shfl_xor_sync(0xffffffffu, sum1, 2);
        l0 = l0 * a0 + sum0;
        l1 = l1 * a1 + sum1;

#pragma unroll
        for (int na = 0; na < 16; na++) {
            oacc[na][0] *= a0; oacc[na][1] *= a0;
            oacc[na][2] *= a1; oacc[na][3] *= a1;
        }

#pragma unroll
        for (int kst = 0; kst < 4; kst++) {
#pragma unroll
            for (int np = 0; np < 8; np++) {
                uint32_t vf[4];
                ldsm_x4(vf, stage_b + vfb +
                        (uint32_t)(np * 16 * VTSTR * 4) + kst * 32);
                mma_f16_16n8k16(oacc[2 * np], ap[kst], vf);
                mma_f16_16n8k16(oacc[2 * np + 1], ap[kst], vf + 2);
            }
        }
    }

    // Epilogue: normalize, write fp16 directly into O16 [B,S,D]
    float li0 = 1.0f / l0;
    float li1 = 1.0f / l1;
    int srow0 = rbase + r0;
    __half* Og0 = O16 + ((size_t)b * S_ + srow0) * D_ + h * DK_;
    __half* Og1 = O16 + ((size_t)b * S_ + srow0 + 8) * D_ + h * DK_;
#pragma unroll
    for (int na = 0; na < 16; na++) {
        int col = na * 8 + 2 * gc;
        *(uint32_t*)(Og0 + col) =
            h2_as_u32(__floats2half2_rn(oacc[na][0] * li0, oacc[na][1] * li0));
        *(uint32_t*)(Og1 + col) =
            h2_as_u32(__floats2half2_rn(oacc[na][2] * li1, oacc[na][3] * li1));
    }
}

// ---------------------------------------------------------------------------
extern "C" void kernel_launch(void* const* d_in, const int* in_sizes, int n_in,
                              void* d_out, int out_size)
{
    const float* x  = (const float*)d_in[0];
    const float* Wq = (const float*)d_in[2];
    const float* bq = (const float*)d_in[3];
    const float* Wk = (const float*)d_in[4];
    const float* bk = (const float*)d_in[5];
    const float* Wv = (const float*)d_in[6];
    const float* bv = (const float*)d_in[7];
    const float* Wo = (const float*)d_in[8];
    const float* bo = (const float*)d_in[9];
    float* out = (float*)d_out;

    float* base = nullptr;
    cudaGetSymbolAddress((void**)&base, g_scratch);
    __half* hbase = nullptr;
    cudaGetSymbolAddress((void**)&hbase, g_h16);
    uint32_t* vp = nullptr;
    cudaGetSymbolAddress((void**)&vp, g_vp);
    __half* x16 = nullptr;
    cudaGetSymbolAddress((void**)&x16, g_x16);
    __half* w16 = nullptr;
    cudaGetSymbolAddress((void**)&w16, g_w16);
    float* biasqkv = nullptr;
    cudaGetSymbolAddress((void**)&biasqkv, g_bias);

    float* Qlin = base;
    float* Klin = base + NBSD;
    float* Vlin = base + 2 * NBSD;
    __half* Qh16 = hbase;
    __half* Kh16 = hbase + NBSD;
    __half* Kl16 = hbase + 2 * NBSD;
    __half* O16  = hbase + 3 * NBSD;
    __half* Wot16 = w16 + 3 * (size_t)D_ * D_;

    const int M = B_ * S_, K = D_;

    cudaMemcpyAsync(biasqkv,          bq, D_ * 4, cudaMemcpyDeviceToDevice);
    cudaMemcpyAsync(biasqkv + D_,     bk, D_ * 4, cudaMemcpyDeviceToDevice);
    cudaMemcpyAsync(biasqkv + 2 * D_, bv, D_ * 4, cudaMemcpyDeviceToDevice);

    {
        int nx4 = (int)(NBSD / 4);
        f32_to_f16_kernel<<<(nx4 + 255) / 256, 256>>>(x, x16, nx4);
        w4_to_f16_kernel<<<16384, 256>>>(Wq, Wk, Wv, Wo, w16);
    }

    cudaFuncSetAttribute(f16_gemm_nt_bias,
                         cudaFuncAttributeMaxDynamicSharedMemorySize, GEMM_SMEM);

    // Fused QKV projection: N=6144, columns routed to Qlin/Klin/Vlin planes
    f16_gemm_nt_bias<<<dim3(3 * D_ / 256, M / 128), 256, GEMM_SMEM>>>(
        x16, w16, biasqkv, Qlin, M, K, NBSD);

    int rope_total = B_ * H_ * S_ * 64;
    rope_relayout_kernel<<<rope_total / 256, 256>>>(Qlin, Klin,
                                                    Qh16, Kh16, Kl16);
    v_pack_kernel<<<B_ * H_ * 4 * 32, 256>>>(Vlin, vp);

    cudaFuncSetAttribute(attn_mma_kernel,
                         cudaFuncAttributeMaxDynamicSharedMemorySize, ATT_SMEM);
    attn_mma_kernel<<<dim3(S_ / 128, H_, B_), 256, ATT_SMEM>>>(
        Qh16, Kh16, Kl16, vp, O16);

    // Output projection (fp16 A from attention, fp32 C)
    f16_gemm_nt_bias<<<dim3(D_ / 256, M / 128), 256, GEMM_SMEM>>>(
        O16, Wot16, bo, out, M, K, 0);
}

// round 15
// speedup vs baseline: 7.4657x; 1.0817x over previous
#include <cuda_runtime.h>
#include <cuda_fp16.h>
#include <math.h>
#include <cstdint>
#include <cstring>

// Problem constants
#define B_ 2
#define S_ 2048
#define D_ 2048
#define H_ 16
#define DK_ 128

static const size_t NBSD = (size_t)B_ * S_ * D_;
// fp32 planes: Qlin, Klin, Vlin (QKV GEMM output)
__device__ float g_scratch[3 * (size_t)B_ * S_ * D_];
// fp16 planes: Qh, Kh, O16
__device__ __half g_h16[3 * (size_t)B_ * S_ * D_];
// packed+transposed V: u32 half2(V[2s2][d],V[2s2+1][d]) at [b,h][d][s2]
__device__ uint32_t g_vp[(size_t)B_ * S_ * D_ / 2];
__device__ __half g_x16[(size_t)B_ * S_ * D_];        // fp16 x
__device__ __half g_w16[4 * (size_t)D_ * D_];         // fp16 Wq,Wk,Wv,Wo
__device__ float g_bias[3 * D_];                      // concat bq,bk,bv

// ============================================================================
// Helpers
// ============================================================================
__device__ __forceinline__ uint32_t smem_to_u32(const void* smem_ptr) {
    uint32_t addr;
    asm("{ .reg .u64 tmp; cvta.to.shared.u64 tmp, %1; cvt.u32.u64 %0, tmp; }"
        : "=r"(addr) : "l"(smem_ptr));
    return addr;
}

__device__ __forceinline__ uint32_t h2_as_u32(__half2 h) {
    uint32_t u;
    memcpy(&u, &h, 4);
    return u;
}

__device__ __forceinline__ void cp_async16(uint32_t smem_addr, const void* gptr) {
    asm volatile("cp.async.cg.shared.global [%0], [%1], 16;"
                 :: "r"(smem_addr), "l"(gptr));
}
#define CP_ASYNC_COMMIT() asm volatile("cp.async.commit_group;" ::: "memory")
#define CP_ASYNC_WAIT(n)  asm volatile("cp.async.wait_group %0;" :: "n"(n) : "memory")

__device__ __forceinline__ void ldsm_x4(uint32_t* r, uint32_t addr) {
    asm volatile("ldmatrix.sync.aligned.m8n8.x4.shared.b16 {%0,%1,%2,%3}, [%4];"
                 : "=r"(r[0]), "=r"(r[1]), "=r"(r[2]), "=r"(r[3]) : "r"(addr));
}

__device__ __forceinline__ void mma_f16_16n8k16(float* d, const uint32_t* a,
                                                const uint32_t* b) {
    asm volatile(
        "mma.sync.aligned.m16n8k16.row.col.f32.f16.f16.f32 "
        "{%0,%1,%2,%3}, {%4,%5,%6,%7}, {%8,%9}, {%0,%1,%2,%3};"
        : "+f"(d[0]), "+f"(d[1]), "+f"(d[2]), "+f"(d[3])
        : "r"(a[0]), "r"(a[1]), "r"(a[2]), "r"(a[3]), "r"(b[0]), "r"(b[1]));
}

// ============================================================================
// fp16 conversion pre-passes
// ============================================================================
__global__ __launch_bounds__(256) void f32_to_f16_kernel(
    const float* __restrict__ in, __half* __restrict__ out, int n4)
{
    int i = blockIdx.x * 256 + threadIdx.x;
    if (i >= n4) return;
    float4 v = ((const float4*)in)[i];
    uint2 w;
    w.x = h2_as_u32(__floats2half2_rn(v.x, v.y));
    w.y = h2_as_u32(__floats2half2_rn(v.z, v.w));
    ((uint2*)out)[i] = w;
}

__global__ __launch_bounds__(256) void w4_to_f16_kernel(
    const float* __restrict__ W0, const float* __restrict__ W1,
    const float* __restrict__ W2, const float* __restrict__ W3,
    __half* __restrict__ out)
{
    int i = blockIdx.x * 256 + threadIdx.x;     // 0 .. 4*2^20-1
    const int per = (D_ * D_) / 4;
    int p = i >> 20, j = i & (per - 1);
    const float* W = (p == 0) ? W0 : (p == 1) ? W1 : (p == 2) ? W2 : W3;
    float4 v = ((const float4*)W)[j];
    uint2 w;
    w.x = h2_as_u32(__floats2half2_rn(v.x, v.y));
    w.y = h2_as_u32(__floats2half2_rn(v.z, v.w));
    ((uint2*)out)[i] = w;
}

// ============================================================================
// fp16 GEMM: C(fp32) = A(fp16)[M,K] @ W(fp16)[N,K]^T + bias.
// BM=128, BN=256, BK=64, 8 warps (2 M x 4 N), warp tile 64x64, m16n8k16.
// All fragments via ldmatrix.x4; 144B row stride (conflict-free LDSM).
// ============================================================================
#define HSTR 72                                  // halves per row (64 + 8 pad)
#define GA_BYTES (128 * HSTR * 2)                // 18432
#define GEMM_STAGE_BYTES ((128 + 256) * HSTR * 2)  // 55296
#define GEMM_SMEM (3 * GEMM_STAGE_BYTES + 16)

__device__ __forceinline__ void gemm16_load_stage(
    const __half* __restrict__ A, const __half* __restrict__ W,
    int row0, int col0, int K, int kc, uint32_t sbase, int tid)
{
#pragma unroll
    for (int i = 0; i < 4; i++) {
        int q = i * 256 + tid;           // 0..1023
        int r = q >> 3, c = q & 7;
        cp_async16(sbase + (uint32_t)(r * 144 + c * 16),
                   A + (size_t)(row0 + r) * K + kc * 64 + c * 8);
    }
#pragma unroll
    for (int i = 0; i < 8; i++) {
        int q = i * 256 + tid;           // 0..2047
        int r = q >> 3, c = q & 7;
        cp_async16(sbase + (uint32_t)GA_BYTES + (uint32_t)(r * 144 + c * 16),
                   W + (size_t)(col0 + r) * K + kc * 64 + c * 8);
    }
    CP_ASYNC_COMMIT();
}

__global__ __launch_bounds__(256) void f16_gemm_nt_bias(
    const __half* __restrict__ A, const __half* __restrict__ W,
    const float* __restrict__ bias, float* __restrict__ C,
    int M, int K, size_t plane_stride)
{
    extern __shared__ __align__(16) char dsm[];

    int tid = threadIdx.x;
    int wid = tid >> 5;
    int lane = tid & 31;
    int gr = lane >> 2;
    int gc = lane & 3;
    int wm = wid & 1;
    int wn = wid >> 1;
    int lrow = lane & 7, lsel = lane >> 3;

    int bx = blockIdx.x, by = blockIdx.y;
    int row0 = by * 128, col0 = bx * 256;

    uint32_t sb = smem_to_u32(dsm);
    uint32_t afb = (uint32_t)((wm * 64 + (lsel & 1) * 8 + lrow) * 144 +
                              (lsel >> 1) * 16);
    uint32_t wfb = (uint32_t)GA_BYTES +
                   (uint32_t)((wn * 64 + (lsel >> 1) * 8 + lrow) * 144 +
                              (lsel & 1) * 16);

    float acc[4][8][4];
#pragma unroll
    for (int i = 0; i < 4; i++)
#pragma unroll
        for (int j = 0; j < 8; j++)
#pragma unroll
            for (int k = 0; k < 4; k++) acc[i][j][k] = 0.f;

    const int NC = K >> 6;   // 32

    gemm16_load_stage(A, W, row0, col0, K, 0, sb + 0 * GEMM_STAGE_BYTES, tid);
    gemm16_load_stage(A, W, row0, col0, K, 1, sb + 1 * GEMM_STAGE_BYTES, tid);

    for (int j = 0; j < NC; j++) {
        if (j + 2 < NC) { CP_ASYNC_WAIT(1); } else { CP_ASYNC_WAIT(0); }
        __syncthreads();

        int jn = j + 2;
        if (jn < NC) {
            gemm16_load_stage(A, W, row0, col0, K, jn,
                              sb + (jn % 3) * GEMM_STAGE_BYTES, tid);
        }

        uint32_t stage_b = sb + (uint32_t)((j % 3) * GEMM_STAGE_BYTES);

#pragma unroll
        for (int kst = 0; kst < 4; kst++) {
            uint32_t af[4][4];
#pragma unroll
            for (int ma = 0; ma < 4; ma++)
                ldsm_x4(af[ma], stage_b + afb +
                        (uint32_t)(ma * 16 * 144) + kst * 32);
            uint32_t wf[4][4];
#pragma unroll
            for (int np = 0; np < 4; np++)
                ldsm_x4(wf[np], stage_b + wfb +
                        (uint32_t)(np * 16 * 144) + kst * 32);
#pragma unroll
            for (int ma = 0; ma < 4; ma++)
#pragma unroll
                for (int np = 0; np < 4; np++) {
                    mma_f16_16n8k16(acc[ma][2 * np], af[ma], &wf[np][0]);
                    mma_f16_16n8k16(acc[ma][2 * np + 1], af[ma], &wf[np][2]);
                }
        }
        __syncthreads();
    }

    float* Cp = C + (size_t)(col0 >> 11) * plane_stride;
    int colp0 = col0 & 2047;
#pragma unroll
    for (int ma = 0; ma < 4; ma++) {
        int row = row0 + wm * 64 + ma * 16 + gr;
#pragma unroll
        for (int na = 0; na < 8; na++) {
            int colf = col0 + wn * 64 + na * 8 + gc * 2;
            int colp = colp0 + wn * 64 + na * 8 + gc * 2;
            float2 bb = *(const float2*)(bias + colf);
            float2 o0, o1;
            o0.x = acc[ma][na][0] + bb.x;
            o0.y = acc[ma][na][1] + bb.y;
            o1.x = acc[ma][na][2] + bb.x;
            o1.y = acc[ma][na][3] + bb.y;
            *(float2*)(Cp + (size_t)row * D_ + colp) = o0;
            *(float2*)(Cp + (size_t)(row + 8) * D_ + colp) = o1;
        }
    }
}

// ---------------------------------------------------------------------------
// RoPE + relayout. Q, K: fp16 (single plane each).
// ---------------------------------------------------------------------------
__global__ __launch_bounds__(256) void rope_relayout_kernel(
    const float* __restrict__ Qlin, const float* __restrict__ Klin,
    __half* __restrict__ Qh, __half* __restrict__ Kh)
{
    int idx = blockIdx.x * 256 + threadIdx.x;          // B*H*S*64
    if (idx >= B_ * H_ * S_ * 64) return;
    int i  = idx & 63;
    int s  = (idx >> 6) & (S_ - 1);
    int hb = idx >> 17;
    int h  = hb & (H_ - 1);
    int b  = hb >> 4;

    size_t lin = ((size_t)(b * S_ + s)) * D_ + h * DK_ + i;
    size_t out = ((size_t)hb * S_ + s) * DK_ + i;

    float inv = 1.0f / powf(10000.0f, (float)(2 * i) / 128.0f);
    float ang = (float)s * inv;
    float sn, cs;
    sincosf(ang, &sn, &cs);

    float q0 = Qlin[lin], q1 = Qlin[lin + 64];
    Qh[out]      = __float2half_rn(q0 * cs - q1 * sn);
    Qh[out + 64] = __float2half_rn(q1 * cs + q0 * sn);

    float k0 = Klin[lin], k1 = Klin[lin + 64];
    Kh[out]      = __float2half_rn(k0 * cs - k1 * sn);
    Kh[out + 64] = __float2half_rn(k1 * cs + k0 * sn);
}

// ---------------------------------------------------------------------------
// V pack + transpose: [B,S,D] fp32 -> Vt[b,h][d][s2] u32 half2 pairs.
// ---------------------------------------------------------------------------
__global__ __launch_bounds__(256) void v_pack_kernel(
    const float* __restrict__ Vlin, uint32_t* __restrict__ Vp)
{
    __shared__ uint32_t tile[32][33];
    int blk = blockIdx.x;                // B*H * 4 * 32 = 4096
    int s2b = (blk & 31) * 32;
    int db  = ((blk >> 5) & 3) * 32;
    int hb  = blk >> 7;
    int h = hb & (H_ - 1), b = hb >> 4;
    int t = threadIdx.x;

#pragma unroll
    for (int it = 0; it < 4; it++) {
        int idx = it * 256 + t;
        int s2l = idx >> 5, dl = idx & 31;
        const float* src = Vlin +
            ((size_t)(b * S_ + 2 * (s2b + s2l))) * D_ + h * DK_ + db + dl;
        tile[s2l][dl] = h2_as_u32(__floats2half2_rn(src[0], src[D_]));
    }
    __syncthreads();
#pragma unroll
    for (int it = 0; it < 4; it++) {
        int idx = it * 256 + t;
        int dl = idx >> 5, s2l = idx & 31;
        Vp[((size_t)hb * DK_ + db + dl) * (S_ / 2) + s2b + s2l] = tile[s2l][dl];
    }
}

// ---------------------------------------------------------------------------
// Tensor-core flash attention (causal), FA2 + LDSM, single-pass fp16 scores.
// BM=128, BN=64, 8 warps; warp owns 16 q-rows. One barrier per kv-group.
// ---------------------------------------------------------------------------
#define AHSTR 136                        // fp16 K/Q row stride (halves)
#define VTSTR 36                         // Vt row stride (u32)
#define VT_OFF (4352 * 4)                // bytes: Vt tile within stage
#define STG_F 8960                       // stage floats: KH 4352 + VT 4608
#define ATT_FLOATS (3 * STG_F)           // 26880
#define ATT_SMEM (ATT_FLOATS * 4)        // 107520 bytes

__global__ __launch_bounds__(256, 1) void attn_mma_kernel(
    const __half* __restrict__ Qh_g, const __half* __restrict__ Kh_g,
    const uint32_t* __restrict__ Vp_g, __half* __restrict__ O16)
{
    extern __shared__ __align__(16) float sm[];
    uint32_t sb = smem_to_u32(sm);

    int qt = (int)gridDim.x - 1 - (int)blockIdx.x;
    int h = blockIdx.y, b = blockIdx.z;
    int hb = b * H_ + h;
    size_t base = (size_t)hb * S_ * DK_;
    size_t qoff = base + (size_t)qt * 128 * DK_;
    size_t vbase = (size_t)hb * DK_ * (S_ / 2);

    int tid = threadIdx.x;
    int wid = tid >> 5;
    int lane = tid & 31;
    int gr = lane >> 2, gc = lane & 3;

    int r0 = wid * 16 + gr;
    int rbase = qt * 128;

    // ---- Stage Q into stage-0 area, hoist fragments
#pragma unroll
    for (int i = 0; i < 8; i++) {
        int q = i * 256 + tid;
        int r = q >> 4, c = q & 15;
        cp_async16(sb + (uint32_t)(r * AHSTR * 2 + c * 16),
                   Qh_g + qoff + (size_t)r * DK_ + c * 8);
    }
    CP_ASYNC_COMMIT();
    CP_ASYNC_WAIT(0);
    __syncthreads();

    uint32_t qh[8][4];
    {
        const __half* Qhp = (const __half*)sm;
#pragma unroll
        for (int kst = 0; kst < 8; kst++) {
            int k0 = kst * 16;
            qh[kst][0] = *(const uint32_t*)&Qhp[r0 * AHSTR + k0 + 2 * gc];
            qh[kst][1] = *(const uint32_t*)&Qhp[(r0 + 8) * AHSTR + k0 + 2 * gc];
            qh[kst][2] = *(const uint32_t*)&Qhp[r0 * AHSTR + k0 + 2 * gc + 8];
            qh[kst][3] = *(const uint32_t*)&Qhp[(r0 + 8) * AHSTR + k0 + 2 * gc + 8];
        }
    }
    __syncthreads();   // stage-0 area free for K/V ring

    int lrow = lane & 7, lsel = lane >> 3;
    // K frag x4 (2 n-atoms): m0=(n,k0) m1=(n,k0+8h) m2=(n+8,k0) m3=(n+8,k0+8h)
    uint32_t kfb = (uint32_t)(((lsel >> 1) * 8 + lrow) * (AHSTR * 2) +
                              (lsel & 1) * 16);
    // V frag x4: m0=(n0,c0) m1=(n0,c0+8h) m2=(n0+8,c0) m3=(n0+8,c0+8h)
    uint32_t vfb = (uint32_t)VT_OFF +
                   (uint32_t)(((lsel >> 1) * 8 + lrow) * (VTSTR * 4)) +
                   (uint32_t)(lsel & 1) * 16u;

    int nkt = 2 * qt + 2;

    auto load_group = [&](int j, int s) {
        size_t kb = base + (size_t)j * 64 * DK_;
        size_t vt = vbase + (size_t)j * 32;
        uint32_t st = sb + (uint32_t)(s * STG_F) * 4;
#pragma unroll
        for (int i = 0; i < 4; i++) {
            int q = i * 256 + tid;   // 0..1023 (64 rows x 16 chunks)
            int r = q >> 4, c = q & 15;
            cp_async16(st + (uint32_t)(r * AHSTR * 2 + c * 16),
                       Kh_g + kb + (size_t)r * DK_ + c * 8);
        }
#pragma unroll
        for (int i = 0; i < 4; i++) {
            int q = i * 256 + tid;   // 0..1023 (128 d-rows x 8 chunks)
            int r = q >> 3, c = q & 7;
            cp_async16(st + VT_OFF + (uint32_t)(r * VTSTR * 4 + c * 16),
                       Vp_g + vt + (size_t)r * (S_ / 2) + c * 4);
        }
        CP_ASYNC_COMMIT();
    };

    load_group(0, 0);
    if (nkt > 1) load_group(1, 1);

    float oacc[16][4];
#pragma unroll
    for (int i = 0; i < 16; i++)
#pragma unroll
        for (int j = 0; j < 4; j++) oacc[i][j] = 0.f;

    float m0 = -1e30f, m1 = -1e30f, l0 = 0.f, l1 = 0.f;
    const float scale = 0.088388347648318440f;

    for (int j = 0; j < nkt; j++) {
        if (j + 1 < nkt) { CP_ASYNC_WAIT(1); } else { CP_ASYNC_WAIT(0); }
        __syncthreads();

        if (j + 2 < nkt) load_group(j + 2, (j + 2) % 3);

        uint32_t stage_b = sb + (uint32_t)((j % 3) * STG_F) * 4;

        // Scores: warp tile 16x64, single-pass fp16 (Qh x Kh)
        float sacc[8][4];
#pragma unroll
        for (int i = 0; i < 8; i++)
#pragma unroll
            for (int k = 0; k < 4; k++) sacc[i][k] = 0.f;

#pragma unroll
        for (int kst = 0; kst < 8; kst++) {
#pragma unroll
            for (int np = 0; np < 4; np++) {
                uint32_t kf[4];
                ldsm_x4(kf, stage_b + kfb +
                        (uint32_t)(np * 16 * AHSTR * 2) + kst * 32);
                mma_f16_16n8k16(sacc[2 * np], qh[kst], &kf[0]);
                mma_f16_16n8k16(sacc[2 * np + 1], qh[kst], &kf[2]);
            }
        }

        // Scale + causal mask (registers only)
        bool diag = (j >= 2 * qt);
        int rg0 = rbase + r0, rg1 = rg0 + 8;
#pragma unroll
        for (int na = 0; na < 8; na++) {
            float s0 = sacc[na][0] * scale;
            float s1 = sacc[na][1] * scale;
            float s2 = sacc[na][2] * scale;
            float s3 = sacc[na][3] * scale;
            if (diag) {
                int cg = j * 64 + na * 8 + 2 * gc;
                if (cg > rg0) s0 = -1e30f;
                if (cg + 1 > rg0) s1 = -1e30f;
                if (cg > rg1) s2 = -1e30f;
                if (cg + 1 > rg1) s3 = -1e30f;
            }
            sacc[na][0] = s0; sacc[na][1] = s1;
            sacc[na][2] = s2; sacc[na][3] = s3;
        }

        // Warp-local online softmax
        float rm0 = -1e30f, rm1 = -1e30f;
#pragma unroll
        for (int na = 0; na < 8; na++) {
            rm0 = fmaxf(rm0, fmaxf(sacc[na][0], sacc[na][1]));
            rm1 = fmaxf(rm1, fmaxf(sacc[na][2], sacc[na][3]));
        }
        rm0 = fmaxf(rm0, __shfl_xor_sync(0xffffffffu, rm0, 1));
        rm0 = fmaxf(rm0, __shfl_xor_sync(0xffffffffu, rm0, 2));
        rm1 = fmaxf(rm1, __shfl_xor_sync(0xffffffffu, rm1, 1));
        rm1 = fmaxf(rm1, __shfl_xor_sync(0xffffffffu, rm1, 2));

        float mn0 = fmaxf(m0, rm0), mn1 = fmaxf(m1, rm1);
        float a0 = __expf(m0 - mn0), a1 = __expf(m1 - mn1);
        m0 = mn0; m1 = mn1;

        uint32_t ap[4][4];
        float sum0 = 0.f, sum1 = 0.f;
#pragma unroll
        for (int kst = 0; kst < 4; kst++) {
            int e = 2 * kst, o = 2 * kst + 1;
            __half2 h00 = __floats2half2_rn(__expf(sacc[e][0] - mn0),
                                            __expf(sacc[e][1] - mn0));
            __half2 h01 = __floats2half2_rn(__expf(sacc[e][2] - mn1),
                                            __expf(sacc[e][3] - mn1));
            __half2 h10 = __floats2half2_rn(__expf(sacc[o][0] - mn0),
                                            __expf(sacc[o][1] - mn0));
            __half2 h11 = __floats2half2_rn(__expf(sacc[o][2] - mn1),
                                            __expf(sacc[o][3] - mn1));
            ap[kst][0] = h2_as_u32(h00);
            ap[kst][1] = h2_as_u32(h01);
            ap[kst][2] = h2_as_u32(h10);
            ap[kst][3] = h2_as_u32(h11);
            float2 f;
            f = __half22float2(h00); sum0 += f.x + f.y;
            f = __half22float2(h10); sum0 += f.x + f.y;
            f = __half22float2(h01); sum1 += f.x + f.y;
            f = __half22float2(h11); sum1 += f.x + f.y;
        }
        sum0 += __shfl_xor_sync(0xffffffffu, sum0, 1);
        sum0 += __shfl_xor_sync(0xffffffffu, sum0, 2);
        sum1 += __shfl_xor_sync(0xffffffffu, sum1, 1);
        sum1 += __shfl_xor_sync(0xffffffffu, sum1, 2);
        l0 = l0 * a0 + sum0;
        l1 = l1 * a1 + sum1;

#pragma unroll
        for (int na = 0; na < 16; na++) {
            oacc[na][0] *= a0; oacc[na][1] *= a0;
            oacc[na][2] *= a1; oacc[na][3] *= a1;
        }

        // PV: warp tile 16x128, V fragments via LDSM
#pragma unroll
        for (int kst = 0; kst < 4; kst++) {
#pragma unroll
            for (int np = 0; np < 8; np++) {
                uint32_t vf[4];
                ldsm_x4(vf, stage_b + vfb +
                        (uint32_t)(np * 16 * VTSTR * 4) + kst * 32);
                mma_f16_16n8k16(oacc[2 * np], ap[kst], vf);
                mma_f16_16n8k16(oacc[2 * np + 1], ap[kst], vf + 2);
            }
        }
    }

    // Epilogue: normalize, write fp16 directly into O16 [B,S,D]
    float li0 = 1.0f / l0;
    float li1 = 1.0f / l1;
    int srow0 = rbase + r0;
    __half* Og0 = O16 + ((size_t)b * S_ + srow0) * D_ + h * DK_;
    __half* Og1 = O16 + ((size_t)b * S_ + srow0 + 8) * D_ + h * DK_;
#pragma unroll
    for (int na = 0; na < 16; na++) {
        int col = na * 8 + 2 * gc;
        *(uint32_t*)(Og0 + col) =
            h2_as_u32(__floats2half2_rn(oacc[na][0] * li0, oacc[na][1] * li0));
        *(uint32_t*)(Og1 + col) =
            h2_as_u32(__floats2half2_rn(oacc[na][2] * li1, oacc[na][3] * li1));
    }
}

// ---------------------------------------------------------------------------
extern "C" void kernel_launch(void* const* d_in, const int* in_sizes, int n_in,
                              void* d_out, int out_size)
{
    const float* x  = (const float*)d_in[0];
    const float* Wq = (const float*)d_in[2];
    const float* bq = (const float*)d_in[3];
    const float* Wk = (const float*)d_in[4];
    const float* bk = (const float*)d_in[5];
    const float* Wv = (const float*)d_in[6];
    const float* bv = (const float*)d_in[7];
    const float* Wo = (const float*)d_in[8];
    const float* bo = (const float*)d_in[9];
    float* out = (float*)d_out;

    float* base = nullptr;
    cudaGetSymbolAddress((void**)&base, g_scratch);
    __half* hbase = nullptr;
    cudaGetSymbolAddress((void**)&hbase, g_h16);
    uint32_t* vp = nullptr;
    cudaGetSymbolAddress((void**)&vp, g_vp);
    __half* x16 = nullptr;
    cudaGetSymbolAddress((void**)&x16, g_x16);
    __half* w16 = nullptr;
    cudaGetSymbolAddress((void**)&w16, g_w16);
    float* biasqkv = nullptr;
    cudaGetSymbolAddress((void**)&biasqkv, g_bias);

    float* Qlin = base;
    float* Klin = base + NBSD;
    float* Vlin = base + 2 * NBSD;
    __half* Qh16 = hbase;
    __half* Kh16 = hbase + NBSD;
    __half* O16  = hbase + 2 * NBSD;
    __half* Wot16 = w16 + 3 * (size_t)D_ * D_;

    const int M = B_ * S_, K = D_;

    cudaMemcpyAsync(biasqkv,          bq, D_ * 4, cudaMemcpyDeviceToDevice);
    cudaMemcpyAsync(biasqkv + D_,     bk, D_ * 4, cudaMemcpyDeviceToDevice);
    cudaMemcpyAsync(biasqkv + 2 * D_, bv, D_ * 4, cudaMemcpyDeviceToDevice);

    {
        int nx4 = (int)(NBSD / 4);
        f32_to_f16_kernel<<<(nx4 + 255) / 256, 256>>>(x, x16, nx4);
        w4_to_f16_kernel<<<16384, 256>>>(Wq, Wk, Wv, Wo, w16);
    }

    cudaFuncSetAttribute(f16_gemm_nt_bias,
                         cudaFuncAttributeMaxDynamicSharedMemorySize, GEMM_SMEM);

    // Fused QKV projection: N=6144, columns routed to Qlin/Klin/Vlin planes
    f16_gemm_nt_bias<<<dim3(3 * D_ / 256, M / 128), 256, GEMM_SMEM>>>(
        x16, w16, biasqkv, Qlin, M, K, NBSD);

    int rope_total = B_ * H_ * S_ * 64;
    rope_relayout_kernel<<<rope_total / 256, 256>>>(Qlin, Klin, Qh16, Kh16);
    v_pack_kernel<<<B_ * H_ * 4 * 32, 256>>>(Vlin, vp);

    cudaFuncSetAttribute(attn_mma_kernel,
                         cudaFuncAttributeMaxDynamicSharedMemorySize, ATT_SMEM);
    attn_mma_kernel<<<dim3(S_ / 128, H_, B_), 256, ATT_SMEM>>>(
        Qh16, Kh16, vp, O16);

    // Output projection (fp16 A from attention, fp32 C)
    f16_gemm_nt_bias<<<dim3(D_ / 256, M / 128), 256, GEMM_SMEM>>>(
        O16, Wot16, bo, out, M, K, 0);
}